// round 6
// baseline (speedup 1.0000x reference)
#include <cuda_runtime.h>
#include <math_constants.h>
#include <cstdint>

typedef long long ll;

// Problem constants
constexpr int Lc   = 2;
constexpr int Bc   = 4;
constexpr int Tc   = 2048;
constexpr int Fc   = 1024;
constexpr int Cc   = 200;
constexpr int Hc   = 8;
constexpr int DFFc = 128;
constexpr int Sc   = Tc + Cc;   // 2248
constexpr int BSc  = Bc * Sc;   // 8992
constexpr int DHc  = Fc / Hc;   // 128
constexpr int SP   = 2304;      // padded S (72*32) for PV K-dim

// ---------------------------------------------------------------------------
// Scratch (device globals; no allocations allowed)
// ---------------------------------------------------------------------------
__device__ float d_src [(size_t)BSc * Fc];
__device__ float d_srcR[(size_t)BSc * Fc];                 // tf32-rounded src
__device__ float d_qb  [(size_t)BSc * Fc];
__device__ float d_kb  [(size_t)BSc * Fc];
__device__ float d_vb  [(size_t)BSc * Fc];
__device__ float d_att [(size_t)BSc * Fc];
__device__ float d_tmp [(size_t)BSc * Fc];
__device__ float d_ffh [(size_t)BSc * DFFc];
__device__ float d_probs[(size_t)Bc * Hc * Sc * SP];       // ~663 MB
__device__ float d_vt  [(size_t)Bc * Fc * SP];             // V transposed, padded
__device__ float d_wt  [Fc * Fc];                          // transposed small weight
__device__ float d_wfq [Fc * Fc];
__device__ float d_wfk [Fc * Fc];
__device__ float d_bfq [Fc];
__device__ float d_bfk [Fc];
__device__ float d_icol[(size_t)Bc * Tc * 3 * Fc];
__device__ float d_ct  [(size_t)Bc * Tc * Fc];
// tf32-rounded weight copies
__device__ float d_wiR [3 * Fc * Fc];
__device__ float d_owR [Fc * Fc];
__device__ float d_l1R [DFFc * Fc];
__device__ float d_l2R [Fc * DFFc];
__device__ float d_embR[3 * Fc * Fc];

// ---------------------------------------------------------------------------
// PTX helpers (sm_80-compatible only — harness compiles for plain sm_100)
// ---------------------------------------------------------------------------
__device__ __forceinline__ uint32_t smem_u32(const void* p) {
    uint32_t a;
    asm("{ .reg .u64 t; cvta.to.shared.u64 t, %1; cvt.u32.u64 %0, t; }" : "=r"(a) : "l"(p));
    return a;
}

__device__ __forceinline__ void cp_async16(uint32_t dst, const float* src, int pred_bytes) {
    asm volatile("cp.async.cg.shared.global [%0], [%1], 16, %2;"
                 :: "r"(dst), "l"(src), "r"(pred_bytes) : "memory");
}
#define CP_COMMIT() asm volatile("cp.async.commit_group;" ::: "memory")
#define CP_WAIT2()  asm volatile("cp.async.wait_group 2;" ::: "memory")

__device__ __forceinline__ uint32_t cvt_tf32(float f) {
    uint32_t u;
    asm("cvt.rna.tf32.f32 %0, %1;" : "=r"(u) : "f"(f));
    return u;
}
__device__ __forceinline__ float round_tf32(float f) {
    return __uint_as_float(cvt_tf32(f));
}

__device__ __forceinline__ void mma_tf32(float* c, const uint32_t* a,
                                         uint32_t b0, uint32_t b1) {
    asm volatile(
        "mma.sync.aligned.m16n8k8.row.col.f32.tf32.tf32.f32 "
        "{%0,%1,%2,%3}, {%4,%5,%6,%7}, {%8,%9}, {%0,%1,%2,%3};"
        : "+f"(c[0]), "+f"(c[1]), "+f"(c[2]), "+f"(c[3])
        : "r"(a[0]), "r"(a[1]), "r"(a[2]), "r"(a[3]), "r"(b0), "r"(b1));
}

// ---------------------------------------------------------------------------
// Tensor-core tf32 GEMM:  C[m,n] = alpha*sum_k A[m,k]*B[n,k] (+bias[n]) (+relu)
// Operands MUST already be tf32-RNA-rounded in gmem (no cvt in mainloop).
// A: [M,K] row-major, B: [N,K] row-major. K % 32 == 0.
// Block tile 128x128x32, 256 threads (warp grid 4(M) x 2(N), warp tile 32x64),
// mma.sync m16n8k8 tf32 with k-slot permutation (slots {l,l+4} hold actual
// k = {2l, 2l+1}) so all fragment loads are contiguous ld.shared.v2.
// KPAD=40 floats -> bank = 8*(row%4)+kb, conflict-free per 16-lane phase.
// 4-stage cp.async pipeline. Batched via blockIdx.z = zb*batchH + zh.
// ---------------------------------------------------------------------------
constexpr int NSTG = 4;
constexpr int KPAD = 40;
constexpr int STAGE_FLOATS = 2 * 128 * KPAD;           // 10240 floats = 40960 B
constexpr size_t TMMA_SMEM = (size_t)NSTG * STAGE_FLOATS * 4;   // 163840 B

template<bool HASBIAS, bool DORELU, bool ROUND>
__global__ void __launch_bounds__(256, 1)
tmma_kernel(int M, int N, int K,
            const float* __restrict__ A, int lda,
            const float* __restrict__ B, int ldb,
            float* __restrict__ C, int ldc,
            const float* __restrict__ bias, float alpha,
            int batchH,
            ll sAb, ll sAh, ll sBb, ll sBh, ll sCb, ll sCh)
{
    extern __shared__ float sm[];

    const int t = threadIdx.x;
    const int wid = t >> 5, lane = t & 31;
    const int warp_m = wid & 3, warp_n = wid >> 2;

    {
        int z = blockIdx.z;
        int zb = z / batchH, zh = z - zb * batchH;
        A += zb * sAb + zh * sAh;
        B += zb * sBb + zh * sBh;
        C += zb * sCb + zh * sCh;
    }
    const int m0 = blockIdx.y * 128, n0 = blockIdx.x * 128;

    const uint32_t smb = smem_u32(sm);

    // ---- async tile loader: thread t loads 4 float4 of A and 4 of B ----
    const int lrow = t >> 1;          // 0..127
    const int lhalf = (t & 1) * 16;   // float offset within 32-float span
    const int KT = K >> 5;

    auto load_stage = [&](int stage, int kc) {
        const int k0 = kc << 5;
        uint32_t aB = smb + (uint32_t)(stage * STAGE_FLOATS) * 4;
        uint32_t bB = aB + 128 * KPAD * 4;
        const int gm = m0 + lrow, gn = n0 + lrow;
        const float* ap = A + (ll)gm * lda + k0 + lhalf;
        const float* bp = B + (ll)gn * ldb + k0 + lhalf;
        uint32_t ad = aB + (lrow * KPAD + lhalf) * 4;
        uint32_t bd = bB + (lrow * KPAD + lhalf) * 4;
        int pa = (gm < M) ? 16 : 0;
        int pb = (gn < N) ? 16 : 0;
        #pragma unroll
        for (int i = 0; i < 4; i++) {
            cp_async16(ad + i * 16, ap + i * 4, pa);
            cp_async16(bd + i * 16, bp + i * 4, pb);
        }
    };

    float c[2][8][4] = {};
    const int aRowBase = warp_m * 32 + (lane >> 2);
    const int bRowBase = warp_n * 64 + (lane >> 2);
    const int kLane2 = (lane & 3) << 1;   // actual k pair base for this lane

    // prologue: stages 0..NSTG-2
    #pragma unroll
    for (int s = 0; s < NSTG - 1; s++) { load_stage(s, s); CP_COMMIT(); }

    for (int kt = 0; kt < KT; kt++) {
        const int s = kt & (NSTG - 1);
        CP_WAIT2();
        __syncthreads();

        const float* As = sm + s * STAGE_FLOATS;
        const float* Bs = As + 128 * KPAD;

        #pragma unroll
        for (int kk = 0; kk < 4; kk++) {
            const int kb = kk * 8 + kLane2;
            uint32_t a[2][4];
            #pragma unroll
            for (int mt = 0; mt < 2; mt++) {
                int r = aRowBase + mt * 16;
                uint2 lo = *(const uint2*)&As[r * KPAD + kb];        // k, k+1 @ row r
                uint2 hi = *(const uint2*)&As[(r + 8) * KPAD + kb];  // k, k+1 @ row r+8
                a[mt][0] = lo.x; a[mt][1] = hi.x;
                a[mt][2] = lo.y; a[mt][3] = hi.y;
            }
            #pragma unroll
            for (int nt = 0; nt < 8; nt++) {
                uint2 b = *(const uint2*)&Bs[(bRowBase + nt * 8) * KPAD + kb];
                mma_tf32(c[0][nt], a[0], b.x, b.y);
                mma_tf32(c[1][nt], a[1], b.x, b.y);
            }
        }
        __syncthreads();

        int nc = kt + NSTG - 1;
        if (nc < KT) load_stage(nc & (NSTG - 1), nc);
        CP_COMMIT();
    }

    // ---- epilogue: registers -> gmem ----
    #pragma unroll
    for (int mt = 0; mt < 2; mt++) {
        const int r0 = m0 + warp_m * 32 + mt * 16 + (lane >> 2);
        const int r1 = r0 + 8;
        #pragma unroll
        for (int nt = 0; nt < 8; nt++) {
            const int cb = n0 + warp_n * 64 + nt * 8;
            if (cb < N) {
                const int col = cb + 2 * (lane & 3);
                float2 v0 = make_float2(c[mt][nt][0] * alpha, c[mt][nt][1] * alpha);
                float2 v1 = make_float2(c[mt][nt][2] * alpha, c[mt][nt][3] * alpha);
                if (HASBIAS) {
                    float bx = bias[col], by = bias[col + 1];
                    v0.x += bx; v0.y += by; v1.x += bx; v1.y += by;
                }
                if (DORELU) {
                    v0.x = fmaxf(v0.x, 0.f); v0.y = fmaxf(v0.y, 0.f);
                    v1.x = fmaxf(v1.x, 0.f); v1.y = fmaxf(v1.y, 0.f);
                }
                if (ROUND) {
                    v0.x = round_tf32(v0.x); v0.y = round_tf32(v0.y);
                    v1.x = round_tf32(v1.x); v1.y = round_tf32(v1.y);
                }
                if (r0 < M) *(float2*)(C + (ll)r0 * ldc + col) = v0;
                if (r1 < M) *(float2*)(C + (ll)r1 * ldc + col) = v1;
            }
        }
    }
}

// ---------------------------------------------------------------------------
// Block reductions
// ---------------------------------------------------------------------------
__device__ __forceinline__ float blkReduceSum(float v) {
    __shared__ float sh[32];
    int lane = threadIdx.x & 31, w = threadIdx.x >> 5;
    #pragma unroll
    for (int o = 16; o; o >>= 1) v += __shfl_xor_sync(0xffffffffu, v, o);
    if (lane == 0) sh[w] = v;
    __syncthreads();
    int nw = blockDim.x >> 5;
    float r = (lane < nw) ? sh[lane] : 0.f;
    #pragma unroll
    for (int o = 16; o; o >>= 1) r += __shfl_xor_sync(0xffffffffu, r, o);
    __syncthreads();
    return r;
}

__device__ __forceinline__ float blkReduceMax(float v) {
    __shared__ float sh[32];
    int lane = threadIdx.x & 31, w = threadIdx.x >> 5;
    #pragma unroll
    for (int o = 16; o; o >>= 1) v = fmaxf(v, __shfl_xor_sync(0xffffffffu, v, o));
    if (lane == 0) sh[w] = v;
    __syncthreads();
    int nw = blockDim.x >> 5;
    float r = (lane < nw) ? sh[lane] : -CUDART_INF_F;
    #pragma unroll
    for (int o = 16; o; o >>= 1) r = fmaxf(r, __shfl_xor_sync(0xffffffffu, r, o));
    __syncthreads();
    return r;
}

// ---------------------------------------------------------------------------
// Small kernels
// ---------------------------------------------------------------------------
__global__ void round_copy_kernel(const float* __restrict__ in, float* __restrict__ out, int n) {
    int i = blockIdx.x * 256 + threadIdx.x;
    if (i < n) out[i] = round_tf32(in[i]);
}

__global__ void copy_x_kernel(const float* __restrict__ x, float* __restrict__ src,
                              float* __restrict__ srcR) {
    int idx = blockIdx.x * 256 + threadIdx.x;
    if (idx >= Bc * Tc * Fc) return;
    int b = idx / (Tc * Fc);
    int r = idx - b * (Tc * Fc);
    float v = x[idx];
    size_t o = (size_t)b * Sc * Fc + r;
    src[o] = v;
    srcR[o] = round_tf32(v);
}

__global__ void fill_proto_kernel(const float* __restrict__ proto, float* __restrict__ src,
                                  float* __restrict__ srcR) {
    int idx = blockIdx.x * 256 + threadIdx.x;
    if (idx >= Bc * Cc * Fc) return;
    int b   = idx / (Cc * Fc);
    int rem = idx - b * (Cc * Fc);
    int c   = rem / Fc;
    int f   = rem - c * Fc;
    float v = proto[(size_t)f * Cc + c];
    size_t o = (size_t)b * Sc * Fc + (size_t)(Tc + c) * Fc + f;
    src[o] = v;
    srcR[o] = round_tf32(v);
}

__global__ void fuse_bias_kernel(const float* __restrict__ Wi,
                                 const float* __restrict__ bsmall,
                                 const float* __restrict__ badd,
                                 float* __restrict__ outb) {
    int n = blockIdx.x;
    float s = 0.f;
    for (int t = threadIdx.x; t < Fc; t += 256) s += Wi[(size_t)n * Fc + t] * bsmall[t];
    s = blkReduceSum(s);
    if (threadIdx.x == 0) outb[n] = s + badd[n];
}

// softmax over first Sc cols of a SP-wide row; zeros pad cols [Sc,SP); rounds output
__global__ void softmax_kernel(float* __restrict__ p) {
    size_t row = blockIdx.x;
    float* r = p + row * (size_t)SP;
    float vals[9];
    float m = -CUDART_INF_F;
    int cnt = 0;
    for (int i = threadIdx.x; i < Sc; i += 256) {
        float v = r[i];
        vals[cnt++] = v;
        m = fmaxf(m, v);
    }
    m = blkReduceMax(m);
    float s = 0.f;
    for (int j = 0; j < cnt; j++) { vals[j] = __expf(vals[j] - m); s += vals[j]; }
    s = blkReduceSum(s);
    float inv = 1.f / s;
    cnt = 0;
    for (int i = threadIdx.x; i < Sc; i += 256) r[i] = round_tf32(vals[cnt++] * inv);
    for (int i = Sc + threadIdx.x; i < SP; i += 256) r[i] = 0.f;
}

// src = LN(src + delta); also writes tf32-rounded copy to srcR
__global__ void ln_add_kernel(float* __restrict__ src, float* __restrict__ srcR,
                              const float* __restrict__ delta,
                              const float* __restrict__ g, const float* __restrict__ b) {
    size_t row = blockIdx.x;
    float* sp = src + row * Fc;
    float* rp = srcR + row * Fc;
    const float* dp = delta + row * Fc;
    float x[4];
    float s = 0.f;
    #pragma unroll
    for (int j = 0; j < 4; j++) {
        int i = threadIdx.x + j * 256;
        x[j] = sp[i] + dp[i];
        s += x[j];
    }
    float mean = blkReduceSum(s) * (1.f / Fc);
    float s2 = 0.f;
    #pragma unroll
    for (int j = 0; j < 4; j++) { float d = x[j] - mean; s2 += d * d; }
    float var = blkReduceSum(s2) * (1.f / Fc);
    float rstd = rsqrtf(var + 1e-5f);
    #pragma unroll
    for (int j = 0; j < 4; j++) {
        int i = threadIdx.x + j * 256;
        float o = (x[j] - mean) * rstd * g[i] + b[i];
        sp[i] = o;
        rp[i] = round_tf32(o);
    }
}

// im2col from rounded src: col[b, t, fi*3+kk] = srcR[b, t+kk-1, fi]
__global__ void im2col_kernel(const float* __restrict__ srcR, float* __restrict__ col) {
    int idx = blockIdx.x * 256 + threadIdx.x;
    if (idx >= Bc * Tc * 3 * Fc) return;
    int c3 = idx % (3 * Fc);
    int bt = idx / (3 * Fc);
    int t = bt % Tc, b = bt / Tc;
    int fi = c3 / 3, kk = c3 - fi * 3;
    int tt = t + kk - 1;
    float v = 0.f;
    if (tt >= 0 && tt < Tc) v = srcR[(size_t)b * Sc * Fc + (size_t)tt * Fc + fi];
    col[idx] = v;
}

// generic transpose with tf32 rounding of outputs (all uses feed GEMM operands)
__global__ void transpose_kernel(const float* __restrict__ in, float* __restrict__ outp,
                                 int R, int ldin, int ldout, ll sIn, ll sOut) {
    __shared__ float tile[32][33];
    int b = blockIdx.z;
    in += b * sIn; outp += b * sOut;
    int r0 = blockIdx.x * 32, c0 = blockIdx.y * 32;
    int tx = threadIdx.x, ty = threadIdx.y;
    #pragma unroll
    for (int i = 0; i < 4; i++) {
        int r = r0 + ty + i * 8;
        if (r < R) tile[ty + i * 8][tx] = in[(ll)r * ldin + c0 + tx];
    }
    __syncthreads();
    int r = r0 + tx;
    if (r < R) {
        #pragma unroll
        for (int i = 0; i < 4; i++) {
            int c = c0 + ty + i * 8;
            outp[(ll)c * ldout + r] = round_tf32(tile[tx][ty + i * 8]);
        }
    }
}

__global__ void transpose_relu_kernel(const float* __restrict__ in, float* __restrict__ outp) {
    __shared__ float tile[32][33];
    int b = blockIdx.z;
    int t0 = blockIdx.x * 32, f0 = blockIdx.y * 32;
    int tx = threadIdx.x, ty = threadIdx.y;
    #pragma unroll
    for (int i = 0; i < 4; i++) {
        int tt = t0 + ty + i * 8;
        tile[ty + i * 8][tx] = in[(size_t)b * Tc * Fc + (size_t)tt * Fc + f0 + tx];
    }
    __syncthreads();
    #pragma unroll
    for (int i = 0; i < 4; i++) {
        int f = f0 + ty + i * 8;
        float v = tile[tx][ty + i * 8];
        outp[(size_t)b * Fc * Tc + (size_t)f * Tc + t0 + tx] = fmaxf(v, 0.f);
    }
}

// ---------------------------------------------------------------------------
// Host dispatch
// ---------------------------------------------------------------------------
static void launch_tmma(bool hasbias, bool dorelu, bool doround,
                        int M, int N, int K,
                        const float* A, int lda, const float* B, int ldb,
                        float* C, int ldc, const float* bias, float alpha,
                        int nz = 1, int batchH = 1,
                        ll sAb = 0, ll sAh = 0, ll sBb = 0, ll sBh = 0,
                        ll sCb = 0, ll sCh = 0)
{
    dim3 grid((N + 127) / 128, (M + 127) / 128, nz);
    #define TM_ARGS M, N, K, A, lda, B, ldb, C, ldc, bias, alpha, batchH, sAb, sAh, sBb, sBh, sCb, sCh
    if (!hasbias && !dorelu && doround)
        tmma_kernel<false, false, true ><<<grid, 256, TMMA_SMEM>>>(TM_ARGS);
    else if (!hasbias && !dorelu && !doround)
        tmma_kernel<false, false, false><<<grid, 256, TMMA_SMEM>>>(TM_ARGS);
    else if (hasbias && !dorelu && doround)
        tmma_kernel<true,  false, true ><<<grid, 256, TMMA_SMEM>>>(TM_ARGS);
    else if (hasbias && !dorelu && !doround)
        tmma_kernel<true,  false, false><<<grid, 256, TMMA_SMEM>>>(TM_ARGS);
    else
        tmma_kernel<true,  true,  true ><<<grid, 256, TMMA_SMEM>>>(TM_ARGS);
    #undef TM_ARGS
}

extern "C" void kernel_launch(void* const* d_in, const int* in_sizes, int n_in,
                              void* d_out, int out_size)
{
    const float* x      = (const float*)d_in[0];
    const float* proto  = (const float*)d_in[1];
    const float* wq     = (const float*)d_in[2];
    const float* bq     = (const float*)d_in[3];
    const float* wk     = (const float*)d_in[4];
    const float* bk     = (const float*)d_in[5];
    const float* in_w   = (const float*)d_in[6];
    const float* in_b   = (const float*)d_in[7];
    const float* out_w  = (const float*)d_in[8];
    const float* out_b  = (const float*)d_in[9];
    const float* l1w    = (const float*)d_in[10];
    const float* l1b    = (const float*)d_in[11];
    const float* l2w    = (const float*)d_in[12];
    const float* l2b    = (const float*)d_in[13];
    const float* ln1g   = (const float*)d_in[14];
    const float* ln1b   = (const float*)d_in[15];
    const float* ln2g   = (const float*)d_in[16];
    const float* ln2b   = (const float*)d_in[17];
    const float* embw   = (const float*)d_in[18];
    const float* embb   = (const float*)d_in[19];
    float* out = (float*)d_out;

    cudaFuncSetAttribute(tmma_kernel<false, false, true >,
                         cudaFuncAttributeMaxDynamicSharedMemorySize, (int)TMMA_SMEM);
    cudaFuncSetAttribute(tmma_kernel<false, false, false>,
                         cudaFuncAttributeMaxDynamicSharedMemorySize, (int)TMMA_SMEM);
    cudaFuncSetAttribute(tmma_kernel<true,  false, true >,
                         cudaFuncAttributeMaxDynamicSharedMemorySize, (int)TMMA_SMEM);
    cudaFuncSetAttribute(tmma_kernel<true,  false, false>,
                         cudaFuncAttributeMaxDynamicSharedMemorySize, (int)TMMA_SMEM);
    cudaFuncSetAttribute(tmma_kernel<true,  true,  true >,
                         cudaFuncAttributeMaxDynamicSharedMemorySize, (int)TMMA_SMEM);

    float *src, *srcR, *q, *k, *v, *att, *tmp, *ffh, *probs, *vt, *wt;
    float *wfq, *wfk, *bfq, *bfk, *icol, *ct, *wiR, *owR, *l1R, *l2R, *embR;
    cudaGetSymbolAddress((void**)&src,  d_src);
    cudaGetSymbolAddress((void**)&srcR, d_srcR);
    cudaGetSymbolAddress((void**)&q,    d_qb);
    cudaGetSymbolAddress((void**)&k,    d_kb);
    cudaGetSymbolAddress((void**)&v,    d_vb);
    cudaGetSymbolAddress((void**)&att,  d_att);
    cudaGetSymbolAddress((void**)&tmp,  d_tmp);
    cudaGetSymbolAddress((void**)&ffh,  d_ffh);
    cudaGetSymbolAddress((void**)&probs, d_probs);
    cudaGetSymbolAddress((void**)&vt,   d_vt);
    cudaGetSymbolAddress((void**)&wt,   d_wt);
    cudaGetSymbolAddress((void**)&wfq,  d_wfq);
    cudaGetSymbolAddress((void**)&wfk,  d_wfk);
    cudaGetSymbolAddress((void**)&bfq,  d_bfq);
    cudaGetSymbolAddress((void**)&bfk,  d_bfk);
    cudaGetSymbolAddress((void**)&icol, d_icol);
    cudaGetSymbolAddress((void**)&ct,   d_ct);
    cudaGetSymbolAddress((void**)&wiR,  d_wiR);
    cudaGetSymbolAddress((void**)&owR,  d_owR);
    cudaGetSymbolAddress((void**)&l1R,  d_l1R);
    cudaGetSymbolAddress((void**)&l2R,  d_l2R);
    cudaGetSymbolAddress((void**)&embR, d_embR);

    const float scale = 0.08838834764831845f;  // 1/sqrt(128)

    copy_x_kernel<<<(Bc * Tc * Fc + 255) / 256, 256>>>(x, src, srcR);
    fill_proto_kernel<<<(Bc * Cc * Fc + 255) / 256, 256>>>(proto, src, srcR);
    round_copy_kernel<<<(3 * Fc * Fc + 255) / 256, 256>>>(embw, embR, 3 * Fc * Fc);

    for (int l = 0; l < Lc; l++) {
        const float* Wi   = in_w + (ll)l * 3 * Fc * Fc;   // [3F, F]
        const float* Wiq  = Wi;
        const float* Wik  = Wi + (ll)Fc * Fc;
        const float* bin  = in_b + (ll)l * 3 * Fc;

        // rounded weight copies for this layer
        round_copy_kernel<<<(3 * Fc * Fc + 255) / 256, 256>>>(Wi, wiR, 3 * Fc * Fc);
        round_copy_kernel<<<(Fc * Fc + 255) / 256, 256>>>(out_w + (ll)l * Fc * Fc, owR, Fc * Fc);
        round_copy_kernel<<<(DFFc * Fc + 255) / 256, 256>>>(l1w + (ll)l * DFFc * Fc, l1R, DFFc * Fc);
        round_copy_kernel<<<(Fc * DFFc + 255) / 256, 256>>>(l2w + (ll)l * Fc * DFFc, l2R, Fc * DFFc);

        // Wfq = Wiq @ wq[l]  (transpose wq -> K-major, rounded)
        transpose_kernel<<<dim3(32, 32, 1), dim3(32, 8)>>>(
            wq + (ll)l * Fc * Fc, wt, Fc, Fc, Fc, 0, 0);
        launch_tmma(false, false, true, Fc, Fc, Fc, wiR, Fc, wt, Fc, wfq, Fc, nullptr, 1.f);
        transpose_kernel<<<dim3(32, 32, 1), dim3(32, 8)>>>(
            wk + (ll)l * Fc * Fc, wt, Fc, Fc, Fc, 0, 0);
        launch_tmma(false, false, true, Fc, Fc, Fc, wiR + (ll)Fc * Fc, Fc, wt, Fc, wfk, Fc, nullptr, 1.f);
        fuse_bias_kernel<<<Fc, 256>>>(Wiq, bq + (ll)l * Fc, bin,      bfq);
        fuse_bias_kernel<<<Fc, 256>>>(Wik, bk + (ll)l * Fc, bin + Fc, bfk);

        // Q, K, V : (BS, F) — outputs rounded (all feed later GEMMs)
        launch_tmma(true, false, true, BSc, Fc, Fc, srcR, Fc, wfq, Fc, q, Fc, bfq, 1.f);
        launch_tmma(true, false, true, BSc, Fc, Fc, srcR, Fc, wfk, Fc, k, Fc, bfk, 1.f);
        launch_tmma(true, false, true, BSc, Fc, Fc, srcR, Fc, wiR + (ll)2 * Fc * Fc, Fc,
                    v, Fc, bin + 2 * Fc, 1.f);

        // V^T per batch: (Sc,F) -> (F, SP)
        transpose_kernel<<<dim3((Sc + 31) / 32, Fc / 32, Bc), dim3(32, 8)>>>(
            v, vt, Sc, Fc, SP, (ll)Sc * Fc, (ll)Fc * SP);

        // scores = scale * Q_h K_h^T  -> probs [b,h][Sc, SP] (softmax rounds)
        launch_tmma(false, false, false, Sc, Sc, DHc,
                    q, Fc, k, Fc, probs, SP, nullptr, scale,
                    Bc * Hc, Hc,
                    (ll)Sc * Fc, DHc, (ll)Sc * Fc, DHc,
                    (ll)Hc * Sc * SP, (ll)Sc * SP);
        softmax_kernel<<<Bc * Hc * Sc, 256>>>(probs);

        // att = P V : A=probs (K=SP, zero-padded), B=vt K-major; round output
        launch_tmma(false, false, true, Sc, DHc, SP,
                    probs, SP, vt, SP, att, Fc, nullptr, 1.f,
                    Bc * Hc, Hc,
                    (ll)Hc * Sc * SP, (ll)Sc * SP,
                    (ll)Fc * SP, (ll)DHc * SP,
                    (ll)Sc * Fc, (ll)DHc);

        // out-proj (residual delta: NOT rounded) + residual LN
        launch_tmma(true, false, false, BSc, Fc, Fc,
                    att, Fc, owR, Fc, tmp, Fc, out_b + (ll)l * Fc, 1.f);
        ln_add_kernel<<<BSc, 256>>>(src, srcR, tmp, ln1g + (ll)l * Fc, ln1b + (ll)l * Fc);

        // FFN + residual LN
        launch_tmma(true, true, true, BSc, DFFc, Fc,
                    srcR, Fc, l1R, Fc, ffh, DFFc, l1b + (ll)l * DFFc, 1.f);
        launch_tmma(true, false, false, BSc, Fc, DFFc,
                    ffh, DFFc, l2R, DFFc, tmp, Fc, l2b + (ll)l * Fc, 1.f);
        ln_add_kernel<<<BSc, 256>>>(src, srcR, tmp, ln2g + (ll)l * Fc, ln2b + (ll)l * Fc);
    }

    // Conv1d(F->F, k=3, pad=1) as im2col GEMM (operands pre-rounded)
    im2col_kernel<<<(Bc * Tc * 3 * Fc + 255) / 256, 256>>>(srcR, icol);
    launch_tmma(true, false, false, Bc * Tc, Fc, 3 * Fc,
                icol, 3 * Fc, embR, 3 * Fc, ct, Fc, embb, 1.f);

    transpose_relu_kernel<<<dim3(Tc / 32, Fc / 32, Bc), dim3(32, 8)>>>(ct, out);
}

// round 7
// speedup vs baseline: 1.2917x; 1.2917x over previous
#include <cuda_runtime.h>
#include <math_constants.h>
#include <cstdint>

typedef long long ll;

// Problem constants
constexpr int Lc   = 2;
constexpr int Bc   = 4;
constexpr int Tc   = 2048;
constexpr int Fc   = 1024;
constexpr int Cc   = 200;
constexpr int Hc   = 8;
constexpr int DFFc = 128;
constexpr int Sc   = Tc + Cc;   // 2248
constexpr int BSc  = Bc * Sc;   // 8992
constexpr int DHc  = Fc / Hc;   // 128
constexpr int SP   = 2304;      // padded S (36*64) for KV iteration

// ---------------------------------------------------------------------------
// Scratch (device globals; no allocations allowed)
// ---------------------------------------------------------------------------
__device__ float d_src [(size_t)BSc * Fc];
__device__ float d_srcR[(size_t)BSc * Fc];                 // tf32-rounded src
__device__ float d_qb  [(size_t)BSc * Fc];
__device__ float d_kb  [(size_t)BSc * Fc];
__device__ float d_vb  [(size_t)BSc * Fc];
__device__ float d_att [(size_t)BSc * Fc];
__device__ float d_tmp [(size_t)BSc * Fc];
__device__ float d_ffh [(size_t)BSc * DFFc];
__device__ float d_vt  [(size_t)Bc * Fc * SP];             // V transposed, padded
__device__ float d_wt  [Fc * Fc];                          // transposed small weight
__device__ float d_wfq [Fc * Fc];
__device__ float d_wfk [Fc * Fc];
__device__ float d_bfq [Fc];
__device__ float d_bfk [Fc];
__device__ float d_icol[(size_t)Bc * Tc * 3 * Fc];
__device__ float d_ct  [(size_t)Bc * Tc * Fc];
// tf32-rounded weight copies
__device__ float d_wiR [3 * Fc * Fc];
__device__ float d_owR [Fc * Fc];
__device__ float d_l1R [DFFc * Fc];
__device__ float d_l2R [Fc * DFFc];
__device__ float d_embR[3 * Fc * Fc];

// ---------------------------------------------------------------------------
// PTX helpers (sm_80-compatible only — harness compiles for plain sm_100)
// ---------------------------------------------------------------------------
__device__ __forceinline__ uint32_t smem_u32(const void* p) {
    uint32_t a;
    asm("{ .reg .u64 t; cvta.to.shared.u64 t, %1; cvt.u32.u64 %0, t; }" : "=r"(a) : "l"(p));
    return a;
}

__device__ __forceinline__ void cp_async16(uint32_t dst, const float* src, int pred_bytes) {
    asm volatile("cp.async.cg.shared.global [%0], [%1], 16, %2;"
                 :: "r"(dst), "l"(src), "r"(pred_bytes) : "memory");
}
#define CP_COMMIT() asm volatile("cp.async.commit_group;" ::: "memory")
#define CP_WAIT2()  asm volatile("cp.async.wait_group 2;" ::: "memory")
#define CP_WAIT1()  asm volatile("cp.async.wait_group 1;" ::: "memory")

__device__ __forceinline__ uint32_t cvt_tf32(float f) {
    uint32_t u;
    asm("cvt.rna.tf32.f32 %0, %1;" : "=r"(u) : "f"(f));
    return u;
}
__device__ __forceinline__ float round_tf32(float f) {
    return __uint_as_float(cvt_tf32(f));
}

__device__ __forceinline__ void mma_tf32(float* c, const uint32_t* a,
                                         uint32_t b0, uint32_t b1) {
    asm volatile(
        "mma.sync.aligned.m16n8k8.row.col.f32.tf32.tf32.f32 "
        "{%0,%1,%2,%3}, {%4,%5,%6,%7}, {%8,%9}, {%0,%1,%2,%3};"
        : "+f"(c[0]), "+f"(c[1]), "+f"(c[2]), "+f"(c[3])
        : "r"(a[0]), "r"(a[1]), "r"(a[2]), "r"(a[3]), "r"(b0), "r"(b1));
}

// ---------------------------------------------------------------------------
// Tensor-core tf32 GEMM (as in R6):  C = alpha*A*B^T (+bias) (+relu)
// Operands pre-rounded to tf32 (RNA). k-slot permutation -> ld.shared.v2 frags.
// ---------------------------------------------------------------------------
constexpr int NSTG = 4;
constexpr int KPAD = 40;
constexpr int STAGE_FLOATS = 2 * 128 * KPAD;
constexpr size_t TMMA_SMEM = (size_t)NSTG * STAGE_FLOATS * 4;   // 163840 B

template<bool HASBIAS, bool DORELU, bool ROUND>
__global__ void __launch_bounds__(256, 1)
tmma_kernel(int M, int N, int K,
            const float* __restrict__ A, int lda,
            const float* __restrict__ B, int ldb,
            float* __restrict__ C, int ldc,
            const float* __restrict__ bias, float alpha,
            int batchH,
            ll sAb, ll sAh, ll sBb, ll sBh, ll sCb, ll sCh)
{
    extern __shared__ float sm[];

    const int t = threadIdx.x;
    const int wid = t >> 5, lane = t & 31;
    const int warp_m = wid & 3, warp_n = wid >> 2;

    {
        int z = blockIdx.z;
        int zb = z / batchH, zh = z - zb * batchH;
        A += zb * sAb + zh * sAh;
        B += zb * sBb + zh * sBh;
        C += zb * sCb + zh * sCh;
    }
    const int m0 = blockIdx.y * 128, n0 = blockIdx.x * 128;

    const uint32_t smb = smem_u32(sm);

    const int lrow = t >> 1;
    const int lhalf = (t & 1) * 16;
    const int KT = K >> 5;

    auto load_stage = [&](int stage, int kc) {
        const int k0 = kc << 5;
        uint32_t aB = smb + (uint32_t)(stage * STAGE_FLOATS) * 4;
        uint32_t bB = aB + 128 * KPAD * 4;
        const int gm = m0 + lrow, gn = n0 + lrow;
        const float* ap = A + (ll)gm * lda + k0 + lhalf;
        const float* bp = B + (ll)gn * ldb + k0 + lhalf;
        uint32_t ad = aB + (lrow * KPAD + lhalf) * 4;
        uint32_t bd = bB + (lrow * KPAD + lhalf) * 4;
        int pa = (gm < M) ? 16 : 0;
        int pb = (gn < N) ? 16 : 0;
        #pragma unroll
        for (int i = 0; i < 4; i++) {
            cp_async16(ad + i * 16, ap + i * 4, pa);
            cp_async16(bd + i * 16, bp + i * 4, pb);
        }
    };

    float c[2][8][4] = {};
    const int aRowBase = warp_m * 32 + (lane >> 2);
    const int bRowBase = warp_n * 64 + (lane >> 2);
    const int kLane2 = (lane & 3) << 1;

    #pragma unroll
    for (int s = 0; s < NSTG - 1; s++) { load_stage(s, s); CP_COMMIT(); }

    for (int kt = 0; kt < KT; kt++) {
        const int s = kt & (NSTG - 1);
        CP_WAIT2();
        __syncthreads();

        const float* As = sm + s * STAGE_FLOATS;
        const float* Bs = As + 128 * KPAD;

        #pragma unroll
        for (int kk = 0; kk < 4; kk++) {
            const int kb = kk * 8 + kLane2;
            uint32_t a[2][4];
            #pragma unroll
            for (int mt = 0; mt < 2; mt++) {
                int r = aRowBase + mt * 16;
                uint2 lo = *(const uint2*)&As[r * KPAD + kb];
                uint2 hi = *(const uint2*)&As[(r + 8) * KPAD + kb];
                a[mt][0] = lo.x; a[mt][1] = hi.x;
                a[mt][2] = lo.y; a[mt][3] = hi.y;
            }
            #pragma unroll
            for (int nt = 0; nt < 8; nt++) {
                uint2 b = *(const uint2*)&Bs[(bRowBase + nt * 8) * KPAD + kb];
                mma_tf32(c[0][nt], a[0], b.x, b.y);
                mma_tf32(c[1][nt], a[1], b.x, b.y);
            }
        }
        __syncthreads();

        int nc = kt + NSTG - 1;
        if (nc < KT) load_stage(nc & (NSTG - 1), nc);
        CP_COMMIT();
    }

    #pragma unroll
    for (int mt = 0; mt < 2; mt++) {
        const int r0 = m0 + warp_m * 32 + mt * 16 + (lane >> 2);
        const int r1 = r0 + 8;
        #pragma unroll
        for (int nt = 0; nt < 8; nt++) {
            const int cb = n0 + warp_n * 64 + nt * 8;
            if (cb < N) {
                const int col = cb + 2 * (lane & 3);
                float2 v0 = make_float2(c[mt][nt][0] * alpha, c[mt][nt][1] * alpha);
                float2 v1 = make_float2(c[mt][nt][2] * alpha, c[mt][nt][3] * alpha);
                if (HASBIAS) {
                    float bx = bias[col], by = bias[col + 1];
                    v0.x += bx; v0.y += by; v1.x += bx; v1.y += by;
                }
                if (DORELU) {
                    v0.x = fmaxf(v0.x, 0.f); v0.y = fmaxf(v0.y, 0.f);
                    v1.x = fmaxf(v1.x, 0.f); v1.y = fmaxf(v1.y, 0.f);
                }
                if (ROUND) {
                    v0.x = round_tf32(v0.x); v0.y = round_tf32(v0.y);
                    v1.x = round_tf32(v1.x); v1.y = round_tf32(v1.y);
                }
                if (r0 < M) *(float2*)(C + (ll)r0 * ldc + col) = v0;
                if (r1 < M) *(float2*)(C + (ll)r1 * ldc + col) = v1;
            }
        }
    }
}

// ---------------------------------------------------------------------------
// Flash attention: att = softmax(Q K^T) V, per (b,h), no probs materialization.
// Q pre-scaled by 1/sqrt(dh). Q,K: [BSc, Fc] head slices (tf32-rounded).
// vt: [Bc][Fc][SP] (V^T per batch, tf32-rounded, cols >= Sc are zero-init).
// Grid (18 q-tiles, 32 b*h), 256 thr. Warp tile 16x64; m16n8k8 tf32 with the
// k-slot permutation {l,l+4}={2l,2l+1}; the S accumulator (c0,c2,c1,c3) is then
// EXACTLY the slot-permuted A fragment for PV -> P stays in registers.
// ---------------------------------------------------------------------------
constexpr int FBN   = 64;
constexpr int NITER = SP / FBN;        // 36
constexpr int QLD = 132, KLD = 132, VLD = 72;
constexpr int KVSTG = 64 * KLD + 128 * VLD;   // floats per stage
constexpr size_t FLASH_SMEM = (size_t)(128 * QLD + 2 * KVSTG) * 4;  // 208896 B

__global__ void __launch_bounds__(256, 1)
flash_kernel(const float* __restrict__ q, const float* __restrict__ k,
             const float* __restrict__ vt, float* __restrict__ att)
{
    extern __shared__ float sm[];
    const int t = threadIdx.x, wid = t >> 5, lane = t & 31;
    const int b = blockIdx.y >> 3, h = blockIdx.y & 7;
    const int q0 = blockIdx.x * 128;

    const float* qg = q  + ((ll)b * Sc) * Fc + (ll)h * DHc;
    const float* kg = k  + ((ll)b * Sc) * Fc + (ll)h * DHc;
    const float* vg = vt + (ll)b * Fc * SP + (ll)h * DHc * SP;

    const uint32_t smb = smem_u32(sm);

    // Q tile: 128 x 128 -> Qs[128][QLD] (scale already folded into q)
    #pragma unroll
    for (int i = 0; i < 16; i++) {
        int idx = t + i * 256;
        int row = idx >> 5, c4 = idx & 31;
        int gr = q0 + row;
        cp_async16(smb + (uint32_t)(row * QLD + c4 * 4) * 4,
                   qg + (ll)gr * Fc + c4 * 4, gr < Sc ? 16 : 0);
    }
    CP_COMMIT();

    auto load_kv = [&](int stage, int it) {
        uint32_t ks = smb + (uint32_t)(128 * QLD + stage * KVSTG) * 4;
        uint32_t vs = ks + (uint32_t)(64 * KLD) * 4;
        int kv0 = it * FBN;
        #pragma unroll
        for (int i = 0; i < 8; i++) {          // K: 64 rows x 128
            int idx = t + i * 256;
            int row = idx >> 5, c4 = idx & 31;
            int gr = kv0 + row;
            cp_async16(ks + (uint32_t)(row * KLD + c4 * 4) * 4,
                       kg + (ll)gr * Fc + c4 * 4, gr < Sc ? 16 : 0);
        }
        #pragma unroll
        for (int i = 0; i < 8; i++) {          // Vt: 128 rows x 64
            int idx = t + i * 256;
            int row = idx >> 4, c4 = idx & 15;
            cp_async16(vs + (uint32_t)(row * VLD + c4 * 4) * 4,
                       vg + (ll)row * SP + kv0 + c4 * 4, 16);
        }
        CP_COMMIT();
    };

    load_kv(0, 0);
    load_kv(1, 1);

    const int aRow = wid * 16 + (lane >> 2);   // warp owns rows wid*16..+15
    const int cb = 2 * (lane & 3);

    float o[16][4];
    #pragma unroll
    for (int i = 0; i < 16; i++) { o[i][0] = o[i][1] = o[i][2] = o[i][3] = 0.f; }
    float m_a = -CUDART_INF_F, m_b = -CUDART_INF_F;
    float l_a = 0.f, l_b = 0.f;

    for (int it = 0; it < NITER; it++) {
        CP_WAIT1();
        __syncthreads();
        const float* Ks  = sm + 128 * QLD + (it & 1) * KVSTG;
        const float* Vts = Ks + 64 * KLD;

        // ---- S = Q K^T (warp: 16 x 64) ----
        float s[8][4];
        #pragma unroll
        for (int i = 0; i < 8; i++) { s[i][0] = s[i][1] = s[i][2] = s[i][3] = 0.f; }
        #pragma unroll
        for (int kk = 0; kk < 16; kk++) {
            const int kb = kk * 8 + cb;
            uint2 lo = *(const uint2*)&sm[aRow * QLD + kb];
            uint2 hi = *(const uint2*)&sm[(aRow + 8) * QLD + kb];
            uint32_t a[4] = {lo.x, hi.x, lo.y, hi.y};
            #pragma unroll
            for (int nt = 0; nt < 8; nt++) {
                uint2 bf = *(const uint2*)&Ks[(nt * 8 + (lane >> 2)) * KLD + kb];
                mma_tf32(s[nt], a, bf.x, bf.y);
            }
        }

        // mask invalid kv columns (only last tile)
        const int kv0 = it * FBN;
        if (kv0 + FBN > Sc) {
            #pragma unroll
            for (int nt = 0; nt < 8; nt++) {
                int c0 = kv0 + nt * 8 + cb;
                if (c0 >= Sc)     { s[nt][0] = -CUDART_INF_F; s[nt][2] = -CUDART_INF_F; }
                if (c0 + 1 >= Sc) { s[nt][1] = -CUDART_INF_F; s[nt][3] = -CUDART_INF_F; }
            }
        }

        // ---- online softmax (rows a = aRow, b = aRow+8) ----
        float mx_a = -CUDART_INF_F, mx_b = -CUDART_INF_F;
        #pragma unroll
        for (int nt = 0; nt < 8; nt++) {
            mx_a = fmaxf(mx_a, fmaxf(s[nt][0], s[nt][1]));
            mx_b = fmaxf(mx_b, fmaxf(s[nt][2], s[nt][3]));
        }
        mx_a = fmaxf(mx_a, __shfl_xor_sync(0xffffffffu, mx_a, 1));
        mx_a = fmaxf(mx_a, __shfl_xor_sync(0xffffffffu, mx_a, 2));
        mx_b = fmaxf(mx_b, __shfl_xor_sync(0xffffffffu, mx_b, 1));
        mx_b = fmaxf(mx_b, __shfl_xor_sync(0xffffffffu, mx_b, 2));
        float mn_a = fmaxf(m_a, mx_a), mn_b = fmaxf(m_b, mx_b);
        float ca = __expf(m_a - mn_a), cbv = __expf(m_b - mn_b);
        m_a = mn_a; m_b = mn_b;

        float ra = 0.f, rb = 0.f;
        #pragma unroll
        for (int nt = 0; nt < 8; nt++) {
            s[nt][0] = round_tf32(__expf(s[nt][0] - mn_a));
            s[nt][1] = round_tf32(__expf(s[nt][1] - mn_a));
            s[nt][2] = round_tf32(__expf(s[nt][2] - mn_b));
            s[nt][3] = round_tf32(__expf(s[nt][3] - mn_b));
            ra += s[nt][0] + s[nt][1];
            rb += s[nt][2] + s[nt][3];
        }
        ra += __shfl_xor_sync(0xffffffffu, ra, 1);
        ra += __shfl_xor_sync(0xffffffffu, ra, 2);
        rb += __shfl_xor_sync(0xffffffffu, rb, 1);
        rb += __shfl_xor_sync(0xffffffffu, rb, 2);
        l_a = l_a * ca + ra;
        l_b = l_b * cbv + rb;

        #pragma unroll
        for (int dt = 0; dt < 16; dt++) {
            o[dt][0] *= ca;  o[dt][1] *= ca;
            o[dt][2] *= cbv; o[dt][3] *= cbv;
        }

        // ---- O += P V  (A fragment straight from S accumulator) ----
        #pragma unroll
        for (int nt = 0; nt < 8; nt++) {
            uint32_t a[4] = { __float_as_uint(s[nt][0]), __float_as_uint(s[nt][2]),
                              __float_as_uint(s[nt][1]), __float_as_uint(s[nt][3]) };
            #pragma unroll
            for (int dt = 0; dt < 16; dt++) {
                uint2 bf = *(const uint2*)&Vts[(dt * 8 + (lane >> 2)) * VLD + nt * 8 + cb];
                mma_tf32(o[dt], a, bf.x, bf.y);
            }
        }

        __syncthreads();
        if (it + 2 < NITER) load_kv(it & 1, it + 2);
    }

    // ---- write O / l (rounded: att feeds out-proj GEMM) ----
    float inva = 1.f / l_a, invb = 1.f / l_b;
    int r0 = q0 + aRow, r1 = r0 + 8;
    float* og0 = att + ((ll)b * Sc + r0) * Fc + h * DHc;
    float* og1 = att + ((ll)b * Sc + r1) * Fc + h * DHc;
    #pragma unroll
    for (int dt = 0; dt < 16; dt++) {
        int col = dt * 8 + cb;
        if (r0 < Sc) {
            float2 v = make_float2(round_tf32(o[dt][0] * inva), round_tf32(o[dt][1] * inva));
            *(float2*)(og0 + col) = v;
        }
        if (r1 < Sc) {
            float2 v = make_float2(round_tf32(o[dt][2] * invb), round_tf32(o[dt][3] * invb));
            *(float2*)(og1 + col) = v;
        }
    }
}

// ---------------------------------------------------------------------------
// Block reductions
// ---------------------------------------------------------------------------
__device__ __forceinline__ float blkReduceSum(float v) {
    __shared__ float sh[32];
    int lane = threadIdx.x & 31, w = threadIdx.x >> 5;
    #pragma unroll
    for (int o = 16; o; o >>= 1) v += __shfl_xor_sync(0xffffffffu, v, o);
    if (lane == 0) sh[w] = v;
    __syncthreads();
    int nw = blockDim.x >> 5;
    float r = (lane < nw) ? sh[lane] : 0.f;
    #pragma unroll
    for (int o = 16; o; o >>= 1) r += __shfl_xor_sync(0xffffffffu, r, o);
    __syncthreads();
    return r;
}

// ---------------------------------------------------------------------------
// Small kernels
// ---------------------------------------------------------------------------
__global__ void round_copy_kernel(const float* __restrict__ in, float* __restrict__ out, int n) {
    int i = blockIdx.x * 256 + threadIdx.x;
    if (i < n) out[i] = round_tf32(in[i]);
}

__global__ void copy_x_kernel(const float* __restrict__ x, float* __restrict__ src,
                              float* __restrict__ srcR) {
    int idx = blockIdx.x * 256 + threadIdx.x;
    if (idx >= Bc * Tc * Fc) return;
    int b = idx / (Tc * Fc);
    int r = idx - b * (Tc * Fc);
    float v = x[idx];
    size_t o = (size_t)b * Sc * Fc + r;
    src[o] = v;
    srcR[o] = round_tf32(v);
}

__global__ void fill_proto_kernel(const float* __restrict__ proto, float* __restrict__ src,
                                  float* __restrict__ srcR) {
    int idx = blockIdx.x * 256 + threadIdx.x;
    if (idx >= Bc * Cc * Fc) return;
    int b   = idx / (Cc * Fc);
    int rem = idx - b * (Cc * Fc);
    int c   = rem / Fc;
    int f   = rem - c * Fc;
    float v = proto[(size_t)f * Cc + c];
    size_t o = (size_t)b * Sc * Fc + (size_t)(Tc + c) * Fc + f;
    src[o] = v;
    srcR[o] = round_tf32(v);
}

// outb[n] = scl * (badd[n] + sum_t Wi[n,t]*bsmall[t])
__global__ void fuse_bias_kernel(const float* __restrict__ Wi,
                                 const float* __restrict__ bsmall,
                                 const float* __restrict__ badd,
                                 float* __restrict__ outb, float scl) {
    int n = blockIdx.x;
    float s = 0.f;
    for (int t = threadIdx.x; t < Fc; t += 256) s += Wi[(size_t)n * Fc + t] * bsmall[t];
    s = blkReduceSum(s);
    if (threadIdx.x == 0) outb[n] = (s + badd[n]) * scl;
}

// src = LN(src + delta); also writes tf32-rounded copy to srcR
__global__ void ln_add_kernel(float* __restrict__ src, float* __restrict__ srcR,
                              const float* __restrict__ delta,
                              const float* __restrict__ g, const float* __restrict__ b) {
    size_t row = blockIdx.x;
    float* sp = src + row * Fc;
    float* rp = srcR + row * Fc;
    const float* dp = delta + row * Fc;
    float x[4];
    float s = 0.f;
    #pragma unroll
    for (int j = 0; j < 4; j++) {
        int i = threadIdx.x + j * 256;
        x[j] = sp[i] + dp[i];
        s += x[j];
    }
    float mean = blkReduceSum(s) * (1.f / Fc);
    float s2 = 0.f;
    #pragma unroll
    for (int j = 0; j < 4; j++) { float d = x[j] - mean; s2 += d * d; }
    float var = blkReduceSum(s2) * (1.f / Fc);
    float rstd = rsqrtf(var + 1e-5f);
    #pragma unroll
    for (int j = 0; j < 4; j++) {
        int i = threadIdx.x + j * 256;
        float o = (x[j] - mean) * rstd * g[i] + b[i];
        sp[i] = o;
        rp[i] = round_tf32(o);
    }
}

__global__ void im2col_kernel(const float* __restrict__ srcR, float* __restrict__ col) {
    int idx = blockIdx.x * 256 + threadIdx.x;
    if (idx >= Bc * Tc * 3 * Fc) return;
    int c3 = idx % (3 * Fc);
    int bt = idx / (3 * Fc);
    int t = bt % Tc, b = bt / Tc;
    int fi = c3 / 3, kk = c3 - fi * 3;
    int tt = t + kk - 1;
    float v = 0.f;
    if (tt >= 0 && tt < Tc) v = srcR[(size_t)b * Sc * Fc + (size_t)tt * Fc + fi];
    col[idx] = v;
}

// generic transpose with tf32 rounding of outputs
__global__ void transpose_kernel(const float* __restrict__ in, float* __restrict__ outp,
                                 int R, int ldin, int ldout, ll sIn, ll sOut) {
    __shared__ float tile[32][33];
    int b = blockIdx.z;
    in += b * sIn; outp += b * sOut;
    int r0 = blockIdx.x * 32, c0 = blockIdx.y * 32;
    int tx = threadIdx.x, ty = threadIdx.y;
    #pragma unroll
    for (int i = 0; i < 4; i++) {
        int r = r0 + ty + i * 8;
        if (r < R) tile[ty + i * 8][tx] = in[(ll)r * ldin + c0 + tx];
    }
    __syncthreads();
    int r = r0 + tx;
    if (r < R) {
        #pragma unroll
        for (int i = 0; i < 4; i++) {
            int c = c0 + ty + i * 8;
            outp[(ll)c * ldout + r] = round_tf32(tile[tx][ty + i * 8]);
        }
    }
}

__global__ void transpose_relu_kernel(const float* __restrict__ in, float* __restrict__ outp) {
    __shared__ float tile[32][33];
    int b = blockIdx.z;
    int t0 = blockIdx.x * 32, f0 = blockIdx.y * 32;
    int tx = threadIdx.x, ty = threadIdx.y;
    #pragma unroll
    for (int i = 0; i < 4; i++) {
        int tt = t0 + ty + i * 8;
        tile[ty + i * 8][tx] = in[(size_t)b * Tc * Fc + (size_t)tt * Fc + f0 + tx];
    }
    __syncthreads();
    #pragma unroll
    for (int i = 0; i < 4; i++) {
        int f = f0 + ty + i * 8;
        float v = tile[tx][ty + i * 8];
        outp[(size_t)b * Fc * Tc + (size_t)f * Tc + t0 + tx] = fmaxf(v, 0.f);
    }
}

// ---------------------------------------------------------------------------
// Host dispatch
// ---------------------------------------------------------------------------
static void launch_tmma(bool hasbias, bool dorelu, bool doround,
                        int M, int N, int K,
                        const float* A, int lda, const float* B, int ldb,
                        float* C, int ldc, const float* bias, float alpha,
                        int nz = 1, int batchH = 1,
                        ll sAb = 0, ll sAh = 0, ll sBb = 0, ll sBh = 0,
                        ll sCb = 0, ll sCh = 0)
{
    dim3 grid((N + 127) / 128, (M + 127) / 128, nz);
    #define TM_ARGS M, N, K, A, lda, B, ldb, C, ldc, bias, alpha, batchH, sAb, sAh, sBb, sBh, sCb, sCh
    if (!hasbias && !dorelu && doround)
        tmma_kernel<false, false, true ><<<grid, 256, TMMA_SMEM>>>(TM_ARGS);
    else if (!hasbias && !dorelu && !doround)
        tmma_kernel<false, false, false><<<grid, 256, TMMA_SMEM>>>(TM_ARGS);
    else if (hasbias && !dorelu && doround)
        tmma_kernel<true,  false, true ><<<grid, 256, TMMA_SMEM>>>(TM_ARGS);
    else if (hasbias && !dorelu && !doround)
        tmma_kernel<true,  false, false><<<grid, 256, TMMA_SMEM>>>(TM_ARGS);
    else
        tmma_kernel<true,  true,  true ><<<grid, 256, TMMA_SMEM>>>(TM_ARGS);
    #undef TM_ARGS
}

extern "C" void kernel_launch(void* const* d_in, const int* in_sizes, int n_in,
                              void* d_out, int out_size)
{
    const float* x      = (const float*)d_in[0];
    const float* proto  = (const float*)d_in[1];
    const float* wq     = (const float*)d_in[2];
    const float* bq     = (const float*)d_in[3];
    const float* wk     = (const float*)d_in[4];
    const float* bk     = (const float*)d_in[5];
    const float* in_w   = (const float*)d_in[6];
    const float* in_b   = (const float*)d_in[7];
    const float* out_w  = (const float*)d_in[8];
    const float* out_b  = (const float*)d_in[9];
    const float* l1w    = (const float*)d_in[10];
    const float* l1b    = (const float*)d_in[11];
    const float* l2w    = (const float*)d_in[12];
    const float* l2b    = (const float*)d_in[13];
    const float* ln1g   = (const float*)d_in[14];
    const float* ln1b   = (const float*)d_in[15];
    const float* ln2g   = (const float*)d_in[16];
    const float* ln2b   = (const float*)d_in[17];
    const float* embw   = (const float*)d_in[18];
    const float* embb   = (const float*)d_in[19];
    float* out = (float*)d_out;

    cudaFuncSetAttribute(tmma_kernel<false, false, true >,
                         cudaFuncAttributeMaxDynamicSharedMemorySize, (int)TMMA_SMEM);
    cudaFuncSetAttribute(tmma_kernel<false, false, false>,
                         cudaFuncAttributeMaxDynamicSharedMemorySize, (int)TMMA_SMEM);
    cudaFuncSetAttribute(tmma_kernel<true,  false, true >,
                         cudaFuncAttributeMaxDynamicSharedMemorySize, (int)TMMA_SMEM);
    cudaFuncSetAttribute(tmma_kernel<true,  false, false>,
                         cudaFuncAttributeMaxDynamicSharedMemorySize, (int)TMMA_SMEM);
    cudaFuncSetAttribute(tmma_kernel<true,  true,  true >,
                         cudaFuncAttributeMaxDynamicSharedMemorySize, (int)TMMA_SMEM);
    cudaFuncSetAttribute(flash_kernel,
                         cudaFuncAttributeMaxDynamicSharedMemorySize, (int)FLASH_SMEM);

    float *src, *srcR, *q, *k, *v, *att, *tmp, *ffh, *vt, *wt;
    float *wfq, *wfk, *bfq, *bfk, *icol, *ct, *wiR, *owR, *l1R, *l2R, *embR;
    cudaGetSymbolAddress((void**)&src,  d_src);
    cudaGetSymbolAddress((void**)&srcR, d_srcR);
    cudaGetSymbolAddress((void**)&q,    d_qb);
    cudaGetSymbolAddress((void**)&k,    d_kb);
    cudaGetSymbolAddress((void**)&v,    d_vb);
    cudaGetSymbolAddress((void**)&att,  d_att);
    cudaGetSymbolAddress((void**)&tmp,  d_tmp);
    cudaGetSymbolAddress((void**)&ffh,  d_ffh);
    cudaGetSymbolAddress((void**)&vt,   d_vt);
    cudaGetSymbolAddress((void**)&wt,   d_wt);
    cudaGetSymbolAddress((void**)&wfq,  d_wfq);
    cudaGetSymbolAddress((void**)&wfk,  d_wfk);
    cudaGetSymbolAddress((void**)&bfq,  d_bfq);
    cudaGetSymbolAddress((void**)&bfk,  d_bfk);
    cudaGetSymbolAddress((void**)&icol, d_icol);
    cudaGetSymbolAddress((void**)&ct,   d_ct);
    cudaGetSymbolAddress((void**)&wiR,  d_wiR);
    cudaGetSymbolAddress((void**)&owR,  d_owR);
    cudaGetSymbolAddress((void**)&l1R,  d_l1R);
    cudaGetSymbolAddress((void**)&l2R,  d_l2R);
    cudaGetSymbolAddress((void**)&embR, d_embR);

    const float scale = 0.08838834764831845f;  // 1/sqrt(128)

    copy_x_kernel<<<(Bc * Tc * Fc + 255) / 256, 256>>>(x, src, srcR);
    fill_proto_kernel<<<(Bc * Cc * Fc + 255) / 256, 256>>>(proto, src, srcR);
    round_copy_kernel<<<(3 * Fc * Fc + 255) / 256, 256>>>(embw, embR, 3 * Fc * Fc);

    for (int l = 0; l < Lc; l++) {
        const float* Wi   = in_w + (ll)l * 3 * Fc * Fc;   // [3F, F]
        const float* Wiq  = Wi;
        const float* Wik  = Wi + (ll)Fc * Fc;
        const float* bin  = in_b + (ll)l * 3 * Fc;

        // rounded weight copies for this layer
        round_copy_kernel<<<(3 * Fc * Fc + 255) / 256, 256>>>(Wi, wiR, 3 * Fc * Fc);
        round_copy_kernel<<<(Fc * Fc + 255) / 256, 256>>>(out_w + (ll)l * Fc * Fc, owR, Fc * Fc);
        round_copy_kernel<<<(DFFc * Fc + 255) / 256, 256>>>(l1w + (ll)l * DFFc * Fc, l1R, DFFc * Fc);
        round_copy_kernel<<<(Fc * DFFc + 255) / 256, 256>>>(l2w + (ll)l * Fc * DFFc, l2R, Fc * DFFc);

        // Wfq = Wiq @ wq[l]  (transpose wq -> K-major, rounded)
        transpose_kernel<<<dim3(32, 32, 1), dim3(32, 8)>>>(
            wq + (ll)l * Fc * Fc, wt, Fc, Fc, Fc, 0, 0);
        launch_tmma(false, false, true, Fc, Fc, Fc, wiR, Fc, wt, Fc, wfq, Fc, nullptr, 1.f);
        transpose_kernel<<<dim3(32, 32, 1), dim3(32, 8)>>>(
            wk + (ll)l * Fc * Fc, wt, Fc, Fc, Fc, 0, 0);
        launch_tmma(false, false, true, Fc, Fc, Fc, wiR + (ll)Fc * Fc, Fc, wt, Fc, wfk, Fc, nullptr, 1.f);
        fuse_bias_kernel<<<Fc, 256>>>(Wiq, bq + (ll)l * Fc, bin,      bfq, scale);
        fuse_bias_kernel<<<Fc, 256>>>(Wik, bk + (ll)l * Fc, bin + Fc, bfk, 1.f);

        // Q (pre-scaled by 1/sqrt(dh)), K, V : (BS, F) — rounded outputs
        launch_tmma(true, false, true, BSc, Fc, Fc, srcR, Fc, wfq, Fc, q, Fc, bfq, scale);
        launch_tmma(true, false, true, BSc, Fc, Fc, srcR, Fc, wfk, Fc, k, Fc, bfk, 1.f);
        launch_tmma(true, false, true, BSc, Fc, Fc, srcR, Fc, wiR + (ll)2 * Fc * Fc, Fc,
                    v, Fc, bin + 2 * Fc, 1.f);

        // V^T per batch: (Sc,F) -> (F, SP); cols >= Sc stay zero (zero-init globals)
        transpose_kernel<<<dim3((Sc + 31) / 32, Fc / 32, Bc), dim3(32, 8)>>>(
            v, vt, Sc, Fc, SP, (ll)Sc * Fc, (ll)Fc * SP);

        // fused attention: att = softmax(Q K^T) V
        flash_kernel<<<dim3((Sc + 127) / 128, Bc * Hc), 256, FLASH_SMEM>>>(q, k, vt, att);

        // out-proj (residual delta: NOT rounded) + residual LN
        launch_tmma(true, false, false, BSc, Fc, Fc,
                    att, Fc, owR, Fc, tmp, Fc, out_b + (ll)l * Fc, 1.f);
        ln_add_kernel<<<BSc, 256>>>(src, srcR, tmp, ln1g + (ll)l * Fc, ln1b + (ll)l * Fc);

        // FFN + residual LN
        launch_tmma(true, true, true, BSc, DFFc, Fc,
                    srcR, Fc, l1R, Fc, ffh, DFFc, l1b + (ll)l * DFFc, 1.f);
        launch_tmma(true, false, false, BSc, Fc, DFFc,
                    ffh, DFFc, l2R, DFFc, tmp, Fc, l2b + (ll)l * Fc, 1.f);
        ln_add_kernel<<<BSc, 256>>>(src, srcR, tmp, ln2g + (ll)l * Fc, ln2b + (ll)l * Fc);
    }

    // Conv1d(F->F, k=3, pad=1) as im2col GEMM (operands pre-rounded)
    im2col_kernel<<<(Bc * Tc * 3 * Fc + 255) / 256, 256>>>(srcR, icol);
    launch_tmma(true, false, false, Bc * Tc, Fc, 3 * Fc,
                icol, 3 * Fc, embR, 3 * Fc, ct, Fc, embb, 1.f);

    transpose_relu_kernel<<<dim3(Tc / 32, Fc / 32, Bc), dim3(32, 8)>>>(ct, out);
}

// round 8
// speedup vs baseline: 1.3702x; 1.0607x over previous
#include <cuda_runtime.h>
#include <math_constants.h>
#include <cstdint>

typedef long long ll;

// Problem constants
constexpr int Lc   = 2;
constexpr int Bc   = 4;
constexpr int Tc   = 2048;
constexpr int Fc   = 1024;
constexpr int Cc   = 200;
constexpr int Hc   = 8;
constexpr int DFFc = 128;
constexpr int Sc   = Tc + Cc;   // 2248
constexpr int BSc  = Bc * Sc;   // 8992
constexpr int DHc  = Fc / Hc;   // 128
constexpr int SP   = 2304;      // padded S (36*64) for KV iteration
constexpr int F3   = 3 * Fc;    // packed QKV width

// ---------------------------------------------------------------------------
// Scratch (device globals; no allocations allowed)
// ---------------------------------------------------------------------------
__device__ float d_src [(size_t)BSc * Fc];
__device__ float d_srcR[(size_t)BSc * Fc];                 // tf32-rounded src
__device__ float d_qkv [(size_t)BSc * F3];                 // packed Q|K|V
__device__ float d_att [(size_t)BSc * Fc];
__device__ float d_tmp [(size_t)BSc * Fc];
__device__ float d_ffh [(size_t)BSc * DFFc];
__device__ float d_vt  [(size_t)Bc * Fc * SP];             // V transposed, padded
__device__ float d_wt  [Fc * Fc];                          // transposed small weight
__device__ float d_wfqkv[(size_t)F3 * Fc];                 // fused+rounded QKV weights
__device__ float d_bfqkv[F3];
__device__ float d_icol[(size_t)Bc * Tc * 3 * Fc];
__device__ float d_ct  [(size_t)Bc * Tc * Fc];
// tf32-rounded weight copies
__device__ float d_wiR [2 * Fc * Fc];                      // rounded Wiq|Wik (fusion A)
__device__ float d_owR [Fc * Fc];
__device__ float d_l1R [DFFc * Fc];
__device__ float d_l2R [Fc * DFFc];
__device__ float d_embR[3 * Fc * Fc];

// ---------------------------------------------------------------------------
// PTX helpers (sm_80-compatible only — harness compiles for plain sm_100)
// ---------------------------------------------------------------------------
__device__ __forceinline__ uint32_t smem_u32(const void* p) {
    uint32_t a;
    asm("{ .reg .u64 t; cvta.to.shared.u64 t, %1; cvt.u32.u64 %0, t; }" : "=r"(a) : "l"(p));
    return a;
}

__device__ __forceinline__ void cp_async16(uint32_t dst, const float* src, int pred_bytes) {
    asm volatile("cp.async.cg.shared.global [%0], [%1], 16, %2;"
                 :: "r"(dst), "l"(src), "r"(pred_bytes) : "memory");
}
#define CP_COMMIT() asm volatile("cp.async.commit_group;" ::: "memory")
#define CP_WAIT1()  asm volatile("cp.async.wait_group 1;" ::: "memory")

__device__ __forceinline__ uint32_t cvt_tf32(float f) {
    uint32_t u;
    asm("cvt.rna.tf32.f32 %0, %1;" : "=r"(u) : "f"(f));
    return u;
}
__device__ __forceinline__ float round_tf32(float f) {
    return __uint_as_float(cvt_tf32(f));
}

__device__ __forceinline__ void mma_tf32(float* c, const uint32_t* a,
                                         uint32_t b0, uint32_t b1) {
    asm volatile(
        "mma.sync.aligned.m16n8k8.row.col.f32.tf32.tf32.f32 "
        "{%0,%1,%2,%3}, {%4,%5,%6,%7}, {%8,%9}, {%0,%1,%2,%3};"
        : "+f"(c[0]), "+f"(c[1]), "+f"(c[2]), "+f"(c[3])
        : "r"(a[0]), "r"(a[1]), "r"(a[2]), "r"(a[3]), "r"(b0), "r"(b1));
}

// ---------------------------------------------------------------------------
// Tensor-core tf32 GEMM:  C = alpha*A*B^T (+bias) (+relu) (+round)
// Operands pre-rounded to tf32 (RNA). k-slot permutation -> ld.shared.v2 frags.
// 2-stage double buffer, 80KB smem -> 2 CTAs/SM (4 warps/SMSP latency hiding).
// ---------------------------------------------------------------------------
constexpr int NSTG = 2;
constexpr int KPAD = 40;
constexpr int STAGE_FLOATS = 2 * 128 * KPAD;
constexpr size_t TMMA_SMEM = (size_t)NSTG * STAGE_FLOATS * 4;   // 81920 B

template<bool HASBIAS, bool DORELU, bool ROUND>
__global__ void __launch_bounds__(256, 2)
tmma_kernel(int M, int N, int K,
            const float* __restrict__ A, int lda,
            const float* __restrict__ B, int ldb,
            float* __restrict__ C, int ldc,
            const float* __restrict__ bias, float alpha,
            int batchH,
            ll sAb, ll sAh, ll sBb, ll sBh, ll sCb, ll sCh)
{
    extern __shared__ float sm[];

    const int t = threadIdx.x;
    const int wid = t >> 5, lane = t & 31;
    const int warp_m = wid & 3, warp_n = wid >> 2;

    {
        int z = blockIdx.z;
        int zb = z / batchH, zh = z - zb * batchH;
        A += zb * sAb + zh * sAh;
        B += zb * sBb + zh * sBh;
        C += zb * sCb + zh * sCh;
    }
    const int m0 = blockIdx.y * 128, n0 = blockIdx.x * 128;

    const uint32_t smb = smem_u32(sm);

    const int lrow = t >> 1;
    const int lhalf = (t & 1) * 16;
    const int KT = K >> 5;

    auto load_stage = [&](int stage, int kc) {
        const int k0 = kc << 5;
        uint32_t aB = smb + (uint32_t)(stage * STAGE_FLOATS) * 4;
        uint32_t bB = aB + 128 * KPAD * 4;
        const int gm = m0 + lrow, gn = n0 + lrow;
        const float* ap = A + (ll)gm * lda + k0 + lhalf;
        const float* bp = B + (ll)gn * ldb + k0 + lhalf;
        uint32_t ad = aB + (lrow * KPAD + lhalf) * 4;
        uint32_t bd = bB + (lrow * KPAD + lhalf) * 4;
        int pa = (gm < M) ? 16 : 0;
        int pb = (gn < N) ? 16 : 0;
        #pragma unroll
        for (int i = 0; i < 4; i++) {
            cp_async16(ad + i * 16, ap + i * 4, pa);
            cp_async16(bd + i * 16, bp + i * 4, pb);
        }
    };

    float c[2][8][4] = {};
    const int aRowBase = warp_m * 32 + (lane >> 2);
    const int bRowBase = warp_n * 64 + (lane >> 2);
    const int kLane2 = (lane & 3) << 1;

    load_stage(0, 0); CP_COMMIT();
    if (KT > 1) load_stage(1, 1);
    CP_COMMIT();

    for (int kt = 0; kt < KT; kt++) {
        const int s = kt & 1;
        CP_WAIT1();
        __syncthreads();

        const float* As = sm + s * STAGE_FLOATS;
        const float* Bs = As + 128 * KPAD;

        #pragma unroll
        for (int kk = 0; kk < 4; kk++) {
            const int kb = kk * 8 + kLane2;
            uint32_t a[2][4];
            #pragma unroll
            for (int mt = 0; mt < 2; mt++) {
                int r = aRowBase + mt * 16;
                uint2 lo = *(const uint2*)&As[r * KPAD + kb];
                uint2 hi = *(const uint2*)&As[(r + 8) * KPAD + kb];
                a[mt][0] = lo.x; a[mt][1] = hi.x;
                a[mt][2] = lo.y; a[mt][3] = hi.y;
            }
            #pragma unroll
            for (int nt = 0; nt < 8; nt++) {
                uint2 b = *(const uint2*)&Bs[(bRowBase + nt * 8) * KPAD + kb];
                mma_tf32(c[0][nt], a[0], b.x, b.y);
                mma_tf32(c[1][nt], a[1], b.x, b.y);
            }
        }
        __syncthreads();

        if (kt + 2 < KT) load_stage(s, kt + 2);
        CP_COMMIT();
    }

    #pragma unroll
    for (int mt = 0; mt < 2; mt++) {
        const int r0 = m0 + warp_m * 32 + mt * 16 + (lane >> 2);
        const int r1 = r0 + 8;
        #pragma unroll
        for (int nt = 0; nt < 8; nt++) {
            const int cb = n0 + warp_n * 64 + nt * 8;
            if (cb < N) {
                const int col = cb + 2 * (lane & 3);
                float2 v0 = make_float2(c[mt][nt][0] * alpha, c[mt][nt][1] * alpha);
                float2 v1 = make_float2(c[mt][nt][2] * alpha, c[mt][nt][3] * alpha);
                if (HASBIAS) {
                    float bx = bias[col], by = bias[col + 1];
                    v0.x += bx; v0.y += by; v1.x += bx; v1.y += by;
                }
                if (DORELU) {
                    v0.x = fmaxf(v0.x, 0.f); v0.y = fmaxf(v0.y, 0.f);
                    v1.x = fmaxf(v1.x, 0.f); v1.y = fmaxf(v1.y, 0.f);
                }
                if (ROUND) {
                    v0.x = round_tf32(v0.x); v0.y = round_tf32(v0.y);
                    v1.x = round_tf32(v1.x); v1.y = round_tf32(v1.y);
                }
                if (r0 < M) *(float2*)(C + (ll)r0 * ldc + col) = v0;
                if (r1 < M) *(float2*)(C + (ll)r1 * ldc + col) = v1;
            }
        }
    }
}

// ---------------------------------------------------------------------------
// Flash attention (as R7): att = softmax(Q K^T) V, per (b,h).
// Q pre-scaled; q/k rows have stride qld (packed QKV buffer).
// ---------------------------------------------------------------------------
constexpr int FBN   = 64;
constexpr int NITER = SP / FBN;        // 36
constexpr int QLD = 132, KLD = 132, VLD = 72;
constexpr int KVSTG = 64 * KLD + 128 * VLD;
constexpr size_t FLASH_SMEM = (size_t)(128 * QLD + 2 * KVSTG) * 4;  // 208896 B

__global__ void __launch_bounds__(256, 1)
flash_kernel(const float* __restrict__ q, const float* __restrict__ k,
             const float* __restrict__ vt, float* __restrict__ att, int qld)
{
    extern __shared__ float sm[];
    const int t = threadIdx.x, wid = t >> 5, lane = t & 31;
    const int b = blockIdx.y >> 3, h = blockIdx.y & 7;
    const int q0 = blockIdx.x * 128;

    const float* qg = q  + ((ll)b * Sc) * qld + (ll)h * DHc;
    const float* kg = k  + ((ll)b * Sc) * qld + (ll)h * DHc;
    const float* vg = vt + (ll)b * Fc * SP + (ll)h * DHc * SP;

    const uint32_t smb = smem_u32(sm);

    #pragma unroll
    for (int i = 0; i < 16; i++) {
        int idx = t + i * 256;
        int row = idx >> 5, c4 = idx & 31;
        int gr = q0 + row;
        cp_async16(smb + (uint32_t)(row * QLD + c4 * 4) * 4,
                   qg + (ll)gr * qld + c4 * 4, gr < Sc ? 16 : 0);
    }
    CP_COMMIT();

    auto load_kv = [&](int stage, int it) {
        uint32_t ks = smb + (uint32_t)(128 * QLD + stage * KVSTG) * 4;
        uint32_t vs = ks + (uint32_t)(64 * KLD) * 4;
        int kv0 = it * FBN;
        #pragma unroll
        for (int i = 0; i < 8; i++) {
            int idx = t + i * 256;
            int row = idx >> 5, c4 = idx & 31;
            int gr = kv0 + row;
            cp_async16(ks + (uint32_t)(row * KLD + c4 * 4) * 4,
                       kg + (ll)gr * qld + c4 * 4, gr < Sc ? 16 : 0);
        }
        #pragma unroll
        for (int i = 0; i < 8; i++) {
            int idx = t + i * 256;
            int row = idx >> 4, c4 = idx & 15;
            cp_async16(vs + (uint32_t)(row * VLD + c4 * 4) * 4,
                       vg + (ll)row * SP + kv0 + c4 * 4, 16);
        }
        CP_COMMIT();
    };

    load_kv(0, 0);
    load_kv(1, 1);

    const int aRow = wid * 16 + (lane >> 2);
    const int cb = 2 * (lane & 3);

    float o[16][4];
    #pragma unroll
    for (int i = 0; i < 16; i++) { o[i][0] = o[i][1] = o[i][2] = o[i][3] = 0.f; }
    float m_a = -CUDART_INF_F, m_b = -CUDART_INF_F;
    float l_a = 0.f, l_b = 0.f;

    for (int it = 0; it < NITER; it++) {
        CP_WAIT1();
        __syncthreads();
        const float* Ks  = sm + 128 * QLD + (it & 1) * KVSTG;
        const float* Vts = Ks + 64 * KLD;

        float s[8][4];
        #pragma unroll
        for (int i = 0; i < 8; i++) { s[i][0] = s[i][1] = s[i][2] = s[i][3] = 0.f; }
        #pragma unroll
        for (int kk = 0; kk < 16; kk++) {
            const int kb = kk * 8 + cb;
            uint2 lo = *(const uint2*)&sm[aRow * QLD + kb];
            uint2 hi = *(const uint2*)&sm[(aRow + 8) * QLD + kb];
            uint32_t a[4] = {lo.x, hi.x, lo.y, hi.y};
            #pragma unroll
            for (int nt = 0; nt < 8; nt++) {
                uint2 bf = *(const uint2*)&Ks[(nt * 8 + (lane >> 2)) * KLD + kb];
                mma_tf32(s[nt], a, bf.x, bf.y);
            }
        }

        const int kv0 = it * FBN;
        if (kv0 + FBN > Sc) {
            #pragma unroll
            for (int nt = 0; nt < 8; nt++) {
                int c0 = kv0 + nt * 8 + cb;
                if (c0 >= Sc)     { s[nt][0] = -CUDART_INF_F; s[nt][2] = -CUDART_INF_F; }
                if (c0 + 1 >= Sc) { s[nt][1] = -CUDART_INF_F; s[nt][3] = -CUDART_INF_F; }
            }
        }

        float mx_a = -CUDART_INF_F, mx_b = -CUDART_INF_F;
        #pragma unroll
        for (int nt = 0; nt < 8; nt++) {
            mx_a = fmaxf(mx_a, fmaxf(s[nt][0], s[nt][1]));
            mx_b = fmaxf(mx_b, fmaxf(s[nt][2], s[nt][3]));
        }
        mx_a = fmaxf(mx_a, __shfl_xor_sync(0xffffffffu, mx_a, 1));
        mx_a = fmaxf(mx_a, __shfl_xor_sync(0xffffffffu, mx_a, 2));
        mx_b = fmaxf(mx_b, __shfl_xor_sync(0xffffffffu, mx_b, 1));
        mx_b = fmaxf(mx_b, __shfl_xor_sync(0xffffffffu, mx_b, 2));
        float mn_a = fmaxf(m_a, mx_a), mn_b = fmaxf(m_b, mx_b);
        float ca = __expf(m_a - mn_a), cbv = __expf(m_b - mn_b);
        m_a = mn_a; m_b = mn_b;

        float ra = 0.f, rb = 0.f;
        #pragma unroll
        for (int nt = 0; nt < 8; nt++) {
            s[nt][0] = round_tf32(__expf(s[nt][0] - mn_a));
            s[nt][1] = round_tf32(__expf(s[nt][1] - mn_a));
            s[nt][2] = round_tf32(__expf(s[nt][2] - mn_b));
            s[nt][3] = round_tf32(__expf(s[nt][3] - mn_b));
            ra += s[nt][0] + s[nt][1];
            rb += s[nt][2] + s[nt][3];
        }
        ra += __shfl_xor_sync(0xffffffffu, ra, 1);
        ra += __shfl_xor_sync(0xffffffffu, ra, 2);
        rb += __shfl_xor_sync(0xffffffffu, rb, 1);
        rb += __shfl_xor_sync(0xffffffffu, rb, 2);
        l_a = l_a * ca + ra;
        l_b = l_b * cbv + rb;

        #pragma unroll
        for (int dt = 0; dt < 16; dt++) {
            o[dt][0] *= ca;  o[dt][1] *= ca;
            o[dt][2] *= cbv; o[dt][3] *= cbv;
        }

        #pragma unroll
        for (int nt = 0; nt < 8; nt++) {
            uint32_t a[4] = { __float_as_uint(s[nt][0]), __float_as_uint(s[nt][2]),
                              __float_as_uint(s[nt][1]), __float_as_uint(s[nt][3]) };
            #pragma unroll
            for (int dt = 0; dt < 16; dt++) {
                uint2 bf = *(const uint2*)&Vts[(dt * 8 + (lane >> 2)) * VLD + nt * 8 + cb];
                mma_tf32(o[dt], a, bf.x, bf.y);
            }
        }

        __syncthreads();
        if (it + 2 < NITER) load_kv(it & 1, it + 2);
    }

    float inva = 1.f / l_a, invb = 1.f / l_b;
    int r0 = q0 + aRow, r1 = r0 + 8;
    float* og0 = att + ((ll)b * Sc + r0) * Fc + h * DHc;
    float* og1 = att + ((ll)b * Sc + r1) * Fc + h * DHc;
    #pragma unroll
    for (int dt = 0; dt < 16; dt++) {
        int col = dt * 8 + cb;
        if (r0 < Sc) {
            float2 v = make_float2(round_tf32(o[dt][0] * inva), round_tf32(o[dt][1] * inva));
            *(float2*)(og0 + col) = v;
        }
        if (r1 < Sc) {
            float2 v = make_float2(round_tf32(o[dt][2] * invb), round_tf32(o[dt][3] * invb));
            *(float2*)(og1 + col) = v;
        }
    }
}

// ---------------------------------------------------------------------------
// Block reductions
// ---------------------------------------------------------------------------
__device__ __forceinline__ float blkReduceSum(float v) {
    __shared__ float sh[32];
    int lane = threadIdx.x & 31, w = threadIdx.x >> 5;
    #pragma unroll
    for (int o = 16; o; o >>= 1) v += __shfl_xor_sync(0xffffffffu, v, o);
    if (lane == 0) sh[w] = v;
    __syncthreads();
    int nw = blockDim.x >> 5;
    float r = (lane < nw) ? sh[lane] : 0.f;
    #pragma unroll
    for (int o = 16; o; o >>= 1) r += __shfl_xor_sync(0xffffffffu, r, o);
    __syncthreads();
    return r;
}

// ---------------------------------------------------------------------------
// Small kernels
// ---------------------------------------------------------------------------
__global__ void round_copy_kernel(const float* __restrict__ in, float* __restrict__ out, int n) {
    int i = blockIdx.x * 256 + threadIdx.x;
    if (i < n) out[i] = round_tf32(in[i]);
}

__global__ void copy_x_kernel(const float* __restrict__ x, float* __restrict__ src,
                              float* __restrict__ srcR) {
    int idx = blockIdx.x * 256 + threadIdx.x;
    if (idx >= Bc * Tc * Fc) return;
    int b = idx / (Tc * Fc);
    int r = idx - b * (Tc * Fc);
    float v = x[idx];
    size_t o = (size_t)b * Sc * Fc + r;
    src[o] = v;
    srcR[o] = round_tf32(v);
}

__global__ void fill_proto_kernel(const float* __restrict__ proto, float* __restrict__ src,
                                  float* __restrict__ srcR) {
    int idx = blockIdx.x * 256 + threadIdx.x;
    if (idx >= Bc * Cc * Fc) return;
    int b   = idx / (Cc * Fc);
    int rem = idx - b * (Cc * Fc);
    int c   = rem / Fc;
    int f   = rem - c * Fc;
    float v = proto[(size_t)f * Cc + c];
    size_t o = (size_t)b * Sc * Fc + (size_t)(Tc + c) * Fc + f;
    src[o] = v;
    srcR[o] = round_tf32(v);
}

// outb[n] = scl * (badd[n] + sum_t Wi[n,t]*bsmall[t])
__global__ void fuse_bias_kernel(const float* __restrict__ Wi,
                                 const float* __restrict__ bsmall,
                                 const float* __restrict__ badd,
                                 float* __restrict__ outb, float scl) {
    int n = blockIdx.x;
    float s = 0.f;
    for (int t = threadIdx.x; t < Fc; t += 256) s += Wi[(size_t)n * Fc + t] * bsmall[t];
    s = blkReduceSum(s);
    if (threadIdx.x == 0) outb[n] = (s + badd[n]) * scl;
}

// src = LN(src + delta); also writes tf32-rounded copy to srcR
__global__ void ln_add_kernel(float* __restrict__ src, float* __restrict__ srcR,
                              const float* __restrict__ delta,
                              const float* __restrict__ g, const float* __restrict__ b) {
    size_t row = blockIdx.x;
    float* sp = src + row * Fc;
    float* rp = srcR + row * Fc;
    const float* dp = delta + row * Fc;
    float x[4];
    float s = 0.f;
    #pragma unroll
    for (int j = 0; j < 4; j++) {
        int i = threadIdx.x + j * 256;
        x[j] = sp[i] + dp[i];
        s += x[j];
    }
    float mean = blkReduceSum(s) * (1.f / Fc);
    float s2 = 0.f;
    #pragma unroll
    for (int j = 0; j < 4; j++) { float d = x[j] - mean; s2 += d * d; }
    float var = blkReduceSum(s2) * (1.f / Fc);
    float rstd = rsqrtf(var + 1e-5f);
    #pragma unroll
    for (int j = 0; j < 4; j++) {
        int i = threadIdx.x + j * 256;
        float o = (x[j] - mean) * rstd * g[i] + b[i];
        sp[i] = o;
        rp[i] = round_tf32(o);
    }
}

__global__ void im2col_kernel(const float* __restrict__ srcR, float* __restrict__ col) {
    int idx = blockIdx.x * 256 + threadIdx.x;
    if (idx >= Bc * Tc * 3 * Fc) return;
    int c3 = idx % (3 * Fc);
    int bt = idx / (3 * Fc);
    int t = bt % Tc, b = bt / Tc;
    int fi = c3 / 3, kk = c3 - fi * 3;
    int tt = t + kk - 1;
    float v = 0.f;
    if (tt >= 0 && tt < Tc) v = srcR[(size_t)b * Sc * Fc + (size_t)tt * Fc + fi];
    col[idx] = v;
}

// generic transpose with tf32 rounding of outputs
__global__ void transpose_kernel(const float* __restrict__ in, float* __restrict__ outp,
                                 int R, int ldin, int ldout, ll sIn, ll sOut) {
    __shared__ float tile[32][33];
    int b = blockIdx.z;
    in += b * sIn; outp += b * sOut;
    int r0 = blockIdx.x * 32, c0 = blockIdx.y * 32;
    int tx = threadIdx.x, ty = threadIdx.y;
    #pragma unroll
    for (int i = 0; i < 4; i++) {
        int r = r0 + ty + i * 8;
        if (r < R) tile[ty + i * 8][tx] = in[(ll)r * ldin + c0 + tx];
    }
    __syncthreads();
    int r = r0 + tx;
    if (r < R) {
        #pragma unroll
        for (int i = 0; i < 4; i++) {
            int c = c0 + ty + i * 8;
            outp[(ll)c * ldout + r] = round_tf32(tile[tx][ty + i * 8]);
        }
    }
}

__global__ void transpose_relu_kernel(const float* __restrict__ in, float* __restrict__ outp) {
    __shared__ float tile[32][33];
    int b = blockIdx.z;
    int t0 = blockIdx.x * 32, f0 = blockIdx.y * 32;
    int tx = threadIdx.x, ty = threadIdx.y;
    #pragma unroll
    for (int i = 0; i < 4; i++) {
        int tt = t0 + ty + i * 8;
        tile[ty + i * 8][tx] = in[(size_t)b * Tc * Fc + (size_t)tt * Fc + f0 + tx];
    }
    __syncthreads();
    #pragma unroll
    for (int i = 0; i < 4; i++) {
        int f = f0 + ty + i * 8;
        float v = tile[tx][ty + i * 8];
        outp[(size_t)b * Fc * Tc + (size_t)f * Tc + t0 + tx] = fmaxf(v, 0.f);
    }
}

// ---------------------------------------------------------------------------
// Host dispatch
// ---------------------------------------------------------------------------
static void launch_tmma(bool hasbias, bool dorelu, bool doround,
                        int M, int N, int K,
                        const float* A, int lda, const float* B, int ldb,
                        float* C, int ldc, const float* bias, float alpha,
                        int nz = 1, int batchH = 1,
                        ll sAb = 0, ll sAh = 0, ll sBb = 0, ll sBh = 0,
                        ll sCb = 0, ll sCh = 0)
{
    dim3 grid((N + 127) / 128, (M + 127) / 128, nz);
    #define TM_ARGS M, N, K, A, lda, B, ldb, C, ldc, bias, alpha, batchH, sAb, sAh, sBb, sBh, sCb, sCh
    if (!hasbias && !dorelu && doround)
        tmma_kernel<false, false, true ><<<grid, 256, TMMA_SMEM>>>(TM_ARGS);
    else if (!hasbias && !dorelu && !doround)
        tmma_kernel<false, false, false><<<grid, 256, TMMA_SMEM>>>(TM_ARGS);
    else if (hasbias && !dorelu && doround)
        tmma_kernel<true,  false, true ><<<grid, 256, TMMA_SMEM>>>(TM_ARGS);
    else if (hasbias && !dorelu && !doround)
        tmma_kernel<true,  false, false><<<grid, 256, TMMA_SMEM>>>(TM_ARGS);
    else
        tmma_kernel<true,  true,  true ><<<grid, 256, TMMA_SMEM>>>(TM_ARGS);
    #undef TM_ARGS
}

extern "C" void kernel_launch(void* const* d_in, const int* in_sizes, int n_in,
                              void* d_out, int out_size)
{
    const float* x      = (const float*)d_in[0];
    const float* proto  = (const float*)d_in[1];
    const float* wq     = (const float*)d_in[2];
    const float* bq     = (const float*)d_in[3];
    const float* wk     = (const float*)d_in[4];
    const float* bk     = (const float*)d_in[5];
    const float* in_w   = (const float*)d_in[6];
    const float* in_b   = (const float*)d_in[7];
    const float* out_w  = (const float*)d_in[8];
    const float* out_b  = (const float*)d_in[9];
    const float* l1w    = (const float*)d_in[10];
    const float* l1b    = (const float*)d_in[11];
    const float* l2w    = (const float*)d_in[12];
    const float* l2b    = (const float*)d_in[13];
    const float* ln1g   = (const float*)d_in[14];
    const float* ln1b   = (const float*)d_in[15];
    const float* ln2g   = (const float*)d_in[16];
    const float* ln2b   = (const float*)d_in[17];
    const float* embw   = (const float*)d_in[18];
    const float* embb   = (const float*)d_in[19];
    float* out = (float*)d_out;

    cudaFuncSetAttribute(tmma_kernel<false, false, true >,
                         cudaFuncAttributeMaxDynamicSharedMemorySize, (int)TMMA_SMEM);
    cudaFuncSetAttribute(tmma_kernel<false, false, false>,
                         cudaFuncAttributeMaxDynamicSharedMemorySize, (int)TMMA_SMEM);
    cudaFuncSetAttribute(tmma_kernel<true,  false, true >,
                         cudaFuncAttributeMaxDynamicSharedMemorySize, (int)TMMA_SMEM);
    cudaFuncSetAttribute(tmma_kernel<true,  false, false>,
                         cudaFuncAttributeMaxDynamicSharedMemorySize, (int)TMMA_SMEM);
    cudaFuncSetAttribute(tmma_kernel<true,  true,  true >,
                         cudaFuncAttributeMaxDynamicSharedMemorySize, (int)TMMA_SMEM);
    cudaFuncSetAttribute(flash_kernel,
                         cudaFuncAttributeMaxDynamicSharedMemorySize, (int)FLASH_SMEM);

    float *src, *srcR, *qkv, *att, *tmp, *ffh, *vt, *wt;
    float *wfqkv, *bfqkv, *icol, *ct, *wiR, *owR, *l1R, *l2R, *embR;
    cudaGetSymbolAddress((void**)&src,  d_src);
    cudaGetSymbolAddress((void**)&srcR, d_srcR);
    cudaGetSymbolAddress((void**)&qkv,  d_qkv);
    cudaGetSymbolAddress((void**)&att,  d_att);
    cudaGetSymbolAddress((void**)&tmp,  d_tmp);
    cudaGetSymbolAddress((void**)&ffh,  d_ffh);
    cudaGetSymbolAddress((void**)&vt,   d_vt);
    cudaGetSymbolAddress((void**)&wt,   d_wt);
    cudaGetSymbolAddress((void**)&wfqkv, d_wfqkv);
    cudaGetSymbolAddress((void**)&bfqkv, d_bfqkv);
    cudaGetSymbolAddress((void**)&icol, d_icol);
    cudaGetSymbolAddress((void**)&ct,   d_ct);
    cudaGetSymbolAddress((void**)&wiR,  d_wiR);
    cudaGetSymbolAddress((void**)&owR,  d_owR);
    cudaGetSymbolAddress((void**)&l1R,  d_l1R);
    cudaGetSymbolAddress((void**)&l2R,  d_l2R);
    cudaGetSymbolAddress((void**)&embR, d_embR);

    const float scale = 0.08838834764831845f;  // 1/sqrt(128)

    copy_x_kernel<<<(Bc * Tc * Fc + 255) / 256, 256>>>(x, src, srcR);
    fill_proto_kernel<<<(Bc * Cc * Fc + 255) / 256, 256>>>(proto, src, srcR);
    round_copy_kernel<<<(3 * Fc * Fc + 255) / 256, 256>>>(embw, embR, 3 * Fc * Fc);

    for (int l = 0; l < Lc; l++) {
        const float* Wi   = in_w + (ll)l * 3 * Fc * Fc;   // [3F, F]
        const float* Wiq  = Wi;
        const float* Wik  = Wi + (ll)Fc * Fc;
        const float* bin  = in_b + (ll)l * 3 * Fc;

        // rounded weight copies for this layer
        round_copy_kernel<<<(2 * Fc * Fc + 255) / 256, 256>>>(Wi, wiR, 2 * Fc * Fc);
        round_copy_kernel<<<(Fc * Fc + 255) / 256, 256>>>(
            Wi + (ll)2 * Fc * Fc, wfqkv + (ll)2 * Fc * Fc, Fc * Fc);   // V weights
        round_copy_kernel<<<(Fc * Fc + 255) / 256, 256>>>(out_w + (ll)l * Fc * Fc, owR, Fc * Fc);
        round_copy_kernel<<<(DFFc * Fc + 255) / 256, 256>>>(l1w + (ll)l * DFFc * Fc, l1R, DFFc * Fc);
        round_copy_kernel<<<(Fc * DFFc + 255) / 256, 256>>>(l2w + (ll)l * Fc * DFFc, l2R, Fc * DFFc);

        // fused QKV weights: rows [0,F)=scale*Wiq@wq, [F,2F)=Wik@wk, [2F,3F)=Wiv
        transpose_kernel<<<dim3(32, 32, 1), dim3(32, 8)>>>(
            wq + (ll)l * Fc * Fc, wt, Fc, Fc, Fc, 0, 0);
        launch_tmma(false, false, true, Fc, Fc, Fc, wiR, Fc, wt, Fc, wfqkv, Fc, nullptr, scale);
        transpose_kernel<<<dim3(32, 32, 1), dim3(32, 8)>>>(
            wk + (ll)l * Fc * Fc, wt, Fc, Fc, Fc, 0, 0);
        launch_tmma(false, false, true, Fc, Fc, Fc, wiR + (ll)Fc * Fc, Fc, wt, Fc,
                    wfqkv + (ll)Fc * Fc, Fc, nullptr, 1.f);
        fuse_bias_kernel<<<Fc, 256>>>(Wiq, bq + (ll)l * Fc, bin,      bfqkv,      scale);
        fuse_bias_kernel<<<Fc, 256>>>(Wik, bk + (ll)l * Fc, bin + Fc, bfqkv + Fc, 1.f);
        cudaMemcpyAsync(bfqkv + 2 * Fc, bin + 2 * Fc, Fc * sizeof(float),
                        cudaMemcpyDeviceToDevice);

        // packed QKV: (BS, 3F), Q pre-scaled; rounded outputs
        launch_tmma(true, false, true, BSc, F3, Fc, srcR, Fc, wfqkv, Fc,
                    qkv, F3, bfqkv, 1.f);

        // V^T per batch: (Sc,F slice of qkv) -> (F, SP); pad cols stay zero
        transpose_kernel<<<dim3((Sc + 31) / 32, Fc / 32, Bc), dim3(32, 8)>>>(
            qkv + 2 * Fc, vt, Sc, F3, SP, (ll)Sc * F3, (ll)Fc * SP);

        // fused attention: att = softmax(Q K^T) V
        flash_kernel<<<dim3((Sc + 127) / 128, Bc * Hc), 256, FLASH_SMEM>>>(
            qkv, qkv + Fc, vt, att, F3);

        // out-proj (residual delta: NOT rounded) + residual LN
        launch_tmma(true, false, false, BSc, Fc, Fc,
                    att, Fc, owR, Fc, tmp, Fc, out_b + (ll)l * Fc, 1.f);
        ln_add_kernel<<<BSc, 256>>>(src, srcR, tmp, ln1g + (ll)l * Fc, ln1b + (ll)l * Fc);

        // FFN + residual LN
        launch_tmma(true, true, true, BSc, DFFc, Fc,
                    srcR, Fc, l1R, Fc, ffh, DFFc, l1b + (ll)l * DFFc, 1.f);
        launch_tmma(true, false, false, BSc, Fc, DFFc,
                    ffh, DFFc, l2R, DFFc, tmp, Fc, l2b + (ll)l * Fc, 1.f);
        ln_add_kernel<<<BSc, 256>>>(src, srcR, tmp, ln2g + (ll)l * Fc, ln2b + (ll)l * Fc);
    }

    // Conv1d(F->F, k=3, pad=1) as im2col GEMM (operands pre-rounded)
    im2col_kernel<<<(Bc * Tc * 3 * Fc + 255) / 256, 256>>>(srcR, icol);
    launch_tmma(true, false, false, Bc * Tc, Fc, 3 * Fc,
                icol, 3 * Fc, embR, 3 * Fc, ct, Fc, embb, 1.f);

    transpose_relu_kernel<<<dim3(Tc / 32, Fc / 32, Bc), dim3(32, 8)>>>(ct, out);
}

// round 11
// speedup vs baseline: 1.7010x; 1.2415x over previous
#include <cuda_runtime.h>
#include <math_constants.h>
#include <cstdint>

typedef long long ll;

// Problem constants
constexpr int Lc   = 2;
constexpr int Bc   = 4;
constexpr int Tc   = 2048;
constexpr int Fc   = 1024;
constexpr int Cc   = 200;
constexpr int Hc   = 8;
constexpr int DFFc = 128;
constexpr int Sc   = Tc + Cc;   // 2248
constexpr int BSc  = Bc * Sc;   // 8992
constexpr int DHc  = Fc / Hc;   // 128
constexpr int SP   = 2304;      // padded S (36*64) for KV iteration
constexpr int F3   = 3 * Fc;    // packed QKV width
constexpr int FF   = Fc * Fc;

// ---------------------------------------------------------------------------
// Scratch (device globals; no allocations allowed)
// ---------------------------------------------------------------------------
__device__ float d_src [(size_t)BSc * Fc];
__device__ float d_srcR[(size_t)BSc * Fc];                 // tf32-rounded src
__device__ float d_qkv [(size_t)BSc * F3];                 // packed Q|K|V
__device__ float d_att [(size_t)BSc * Fc];
__device__ float d_tmp [(size_t)BSc * Fc];
__device__ float d_ffh [(size_t)BSc * DFFc];
__device__ float d_vt  [(size_t)Bc * Fc * SP];             // V transposed, padded
__device__ float d_wt  [4 * FF];                           // transposed wq/wk (2 layers)
__device__ float d_wfqkv[(size_t)2 * F3 * Fc];             // fused+rounded QKV weights
__device__ float d_bfqkv[2 * F3];
__device__ float d_icol[(size_t)Bc * Tc * 3 * Fc];
__device__ float d_ct  [(size_t)Bc * Tc * Fc];
// tf32-rounded weight copies (both layers)
__device__ float d_wiR [2 * 2 * FF];                       // Wiq|Wik per layer
__device__ float d_owR [2 * FF];
__device__ float d_l1R [2 * DFFc * Fc];
__device__ float d_l2R [2 * Fc * DFFc];
__device__ float d_embR[3 * FF];

// ---------------------------------------------------------------------------
// PTX helpers (sm_80-compatible only — harness compiles for plain sm_100)
// ---------------------------------------------------------------------------
__device__ __forceinline__ uint32_t smem_u32(const void* p) {
    uint32_t a;
    asm("{ .reg .u64 t; cvta.to.shared.u64 t, %1; cvt.u32.u64 %0, t; }" : "=r"(a) : "l"(p));
    return a;
}

__device__ __forceinline__ void cp_async16(uint32_t dst, const float* src, int pred_bytes) {
    asm volatile("cp.async.cg.shared.global [%0], [%1], 16, %2;"
                 :: "r"(dst), "l"(src), "r"(pred_bytes) : "memory");
}
#define CP_COMMIT() asm volatile("cp.async.commit_group;" ::: "memory")
#define CP_WAIT2()  asm volatile("cp.async.wait_group 2;" ::: "memory")
#define CP_WAIT1()  asm volatile("cp.async.wait_group 1;" ::: "memory")

__device__ __forceinline__ uint32_t cvt_tf32(float f) {
    uint32_t u;
    asm("cvt.rna.tf32.f32 %0, %1;" : "=r"(u) : "f"(f));
    return u;
}
__device__ __forceinline__ float round_tf32(float f) {
    return __uint_as_float(cvt_tf32(f));
}

__device__ __forceinline__ void mma_tf32(float* c, const uint32_t* a,
                                         uint32_t b0, uint32_t b1) {
    asm volatile(
        "mma.sync.aligned.m16n8k8.row.col.f32.tf32.tf32.f32 "
        "{%0,%1,%2,%3}, {%4,%5,%6,%7}, {%8,%9}, {%0,%1,%2,%3};"
        : "+f"(c[0]), "+f"(c[1]), "+f"(c[2]), "+f"(c[3])
        : "r"(a[0]), "r"(a[1]), "r"(a[2]), "r"(a[3]), "r"(b0), "r"(b1));
}

// ---------------------------------------------------------------------------
// Tensor-core tf32 GEMM:  C = alpha*A*B^T (+bias) (+relu) (+round)
// Operands pre-rounded to tf32 (RNA). k-slot permutation -> ld.shared.v2 frags.
// 4-stage pipeline, K-chunk 16, ONE __syncthreads per chunk, 96KB smem ->
// 2 CTAs/SM. KPAD=24: per-16-lane-phase banks g*24%32 in {0,24,16,8} + 2q
// cover all 32 banks exactly once -> conflict-free v2 fragment loads.
// Requires K % 16 == 0 and K >= 48.
// ---------------------------------------------------------------------------
constexpr int KPAD = 24;
constexpr int STAGE_FLOATS = 2 * 128 * KPAD;                   // 6144
constexpr size_t TMMA_SMEM = (size_t)4 * STAGE_FLOATS * 4;     // 98304 B

template<bool HASBIAS, bool DORELU, bool ROUND>
__global__ void __launch_bounds__(256, 2)
tmma_kernel(int M, int N, int K,
            const float* __restrict__ A, int lda,
            const float* __restrict__ B, int ldb,
            float* __restrict__ C, int ldc,
            const float* __restrict__ bias, float alpha,
            int batchH,
            ll sAb, ll sAh, ll sBb, ll sBh, ll sCb, ll sCh)
{
    extern __shared__ float sm[];

    const int t = threadIdx.x;
    const int wid = t >> 5, lane = t & 31;
    const int warp_m = wid & 3, warp_n = wid >> 2;

    {
        int z = blockIdx.z;
        int zb = z / batchH, zh = z - zb * batchH;
        A += zb * sAb + zh * sAh;
        B += zb * sBb + zh * sBh;
        C += zb * sCb + zh * sCh;
    }
    const int m0 = blockIdx.y * 128, n0 = blockIdx.x * 128;

    const uint32_t smb = smem_u32(sm);
    const int KT = K >> 4;

    auto load_stage = [&](int stage, int kc) {
        const int k0 = kc << 4;
        uint32_t aB = smb + (uint32_t)(stage * STAGE_FLOATS) * 4;
        uint32_t bB = aB + 128 * KPAD * 4;
        #pragma unroll
        for (int i = 0; i < 2; i++) {
            int idx = t + i * 256;          // 0..511
            int row = idx >> 2, sub = idx & 3;
            int gm = m0 + row, gn = n0 + row;
            cp_async16(aB + (uint32_t)(row * KPAD + sub * 4) * 4,
                       A + (ll)gm * lda + k0 + sub * 4, (gm < M) ? 16 : 0);
            cp_async16(bB + (uint32_t)(row * KPAD + sub * 4) * 4,
                       B + (ll)gn * ldb + k0 + sub * 4, (gn < N) ? 16 : 0);
        }
    };

    float c[2][8][4] = {};
    const int aRowBase = warp_m * 32 + (lane >> 2);
    const int bRowBase = warp_n * 64 + (lane >> 2);
    const int kLane2 = (lane & 3) << 1;

    load_stage(0, 0); CP_COMMIT();
    load_stage(1, 1); CP_COMMIT();
    load_stage(2, 2); CP_COMMIT();

    for (int kt = 0; kt < KT; kt++) {
        CP_WAIT2();
        __syncthreads();
        // refill the stage retired last iteration (safe: sync above guarantees
        // every warp finished computing chunk kt-1 = stage (kt+3)&3)
        if (kt + 3 < KT) load_stage((kt + 3) & 3, kt + 3);
        CP_COMMIT();

        const float* As = sm + (kt & 3) * STAGE_FLOATS;
        const float* Bs = As + 128 * KPAD;

        #pragma unroll
        for (int kk = 0; kk < 2; kk++) {
            const int kb = kk * 8 + kLane2;
            uint32_t a[2][4];
            #pragma unroll
            for (int mt = 0; mt < 2; mt++) {
                int r = aRowBase + mt * 16;
                uint2 lo = *(const uint2*)&As[r * KPAD + kb];
                uint2 hi = *(const uint2*)&As[(r + 8) * KPAD + kb];
                a[mt][0] = lo.x; a[mt][1] = hi.x;
                a[mt][2] = lo.y; a[mt][3] = hi.y;
            }
            #pragma unroll
            for (int nt = 0; nt < 8; nt++) {
                uint2 b = *(const uint2*)&Bs[(bRowBase + nt * 8) * KPAD + kb];
                mma_tf32(c[0][nt], a[0], b.x, b.y);
                mma_tf32(c[1][nt], a[1], b.x, b.y);
            }
        }
    }

    #pragma unroll
    for (int mt = 0; mt < 2; mt++) {
        const int r0 = m0 + warp_m * 32 + mt * 16 + (lane >> 2);
        const int r1 = r0 + 8;
        #pragma unroll
        for (int nt = 0; nt < 8; nt++) {
            const int cb = n0 + warp_n * 64 + nt * 8;
            if (cb < N) {
                const int col = cb + 2 * (lane & 3);
                float2 v0 = make_float2(c[mt][nt][0] * alpha, c[mt][nt][1] * alpha);
                float2 v1 = make_float2(c[mt][nt][2] * alpha, c[mt][nt][3] * alpha);
                if (HASBIAS) {
                    float bx = bias[col], by = bias[col + 1];
                    v0.x += bx; v0.y += by; v1.x += bx; v1.y += by;
                }
                if (DORELU) {
                    v0.x = fmaxf(v0.x, 0.f); v0.y = fmaxf(v0.y, 0.f);
                    v1.x = fmaxf(v1.x, 0.f); v1.y = fmaxf(v1.y, 0.f);
                }
                if (ROUND) {
                    v0.x = round_tf32(v0.x); v0.y = round_tf32(v0.y);
                    v1.x = round_tf32(v1.x); v1.y = round_tf32(v1.y);
                }
                if (r0 < M) *(float2*)(C + (ll)r0 * ldc + col) = v0;
                if (r1 < M) *(float2*)(C + (ll)r1 * ldc + col) = v1;
            }
        }
    }
}

// ---------------------------------------------------------------------------
// Flash attention (as R8): att = softmax(Q K^T) V, per (b,h).
// ---------------------------------------------------------------------------
constexpr int FBN   = 64;
constexpr int NITER = SP / FBN;        // 36
constexpr int QLD = 132, KLD = 132, VLD = 72;
constexpr int KVSTG = 64 * KLD + 128 * VLD;
constexpr size_t FLASH_SMEM = (size_t)(128 * QLD + 2 * KVSTG) * 4;  // 208896 B

__global__ void __launch_bounds__(256, 1)
flash_kernel(const float* __restrict__ q, const float* __restrict__ k,
             const float* __restrict__ vt, float* __restrict__ att, int qld)
{
    extern __shared__ float sm[];
    const int t = threadIdx.x, wid = t >> 5, lane = t & 31;
    const int b = blockIdx.y >> 3, h = blockIdx.y & 7;
    const int q0 = blockIdx.x * 128;

    const float* qg = q  + ((ll)b * Sc) * qld + (ll)h * DHc;
    const float* kg = k  + ((ll)b * Sc) * qld + (ll)h * DHc;
    const float* vg = vt + (ll)b * Fc * SP + (ll)h * DHc * SP;

    const uint32_t smb = smem_u32(sm);

    #pragma unroll
    for (int i = 0; i < 16; i++) {
        int idx = t + i * 256;
        int row = idx >> 5, c4 = idx & 31;
        int gr = q0 + row;
        cp_async16(smb + (uint32_t)(row * QLD + c4 * 4) * 4,
                   qg + (ll)gr * qld + c4 * 4, gr < Sc ? 16 : 0);
    }
    CP_COMMIT();

    auto load_kv = [&](int stage, int it) {
        uint32_t ks = smb + (uint32_t)(128 * QLD + stage * KVSTG) * 4;
        uint32_t vs = ks + (uint32_t)(64 * KLD) * 4;
        int kv0 = it * FBN;
        #pragma unroll
        for (int i = 0; i < 8; i++) {
            int idx = t + i * 256;
            int row = idx >> 5, c4 = idx & 31;
            int gr = kv0 + row;
            cp_async16(ks + (uint32_t)(row * KLD + c4 * 4) * 4,
                       kg + (ll)gr * qld + c4 * 4, gr < Sc ? 16 : 0);
        }
        #pragma unroll
        for (int i = 0; i < 8; i++) {
            int idx = t + i * 256;
            int row = idx >> 4, c4 = idx & 15;
            cp_async16(vs + (uint32_t)(row * VLD + c4 * 4) * 4,
                       vg + (ll)row * SP + kv0 + c4 * 4, 16);
        }
        CP_COMMIT();
    };

    load_kv(0, 0);
    load_kv(1, 1);

    const int aRow = wid * 16 + (lane >> 2);
    const int cb = 2 * (lane & 3);

    float o[16][4];
    #pragma unroll
    for (int i = 0; i < 16; i++) { o[i][0] = o[i][1] = o[i][2] = o[i][3] = 0.f; }
    float m_a = -CUDART_INF_F, m_b = -CUDART_INF_F;
    float l_a = 0.f, l_b = 0.f;

    for (int it = 0; it < NITER; it++) {
        CP_WAIT1();
        __syncthreads();
        const float* Ks  = sm + 128 * QLD + (it & 1) * KVSTG;
        const float* Vts = Ks + 64 * KLD;

        float s[8][4];
        #pragma unroll
        for (int i = 0; i < 8; i++) { s[i][0] = s[i][1] = s[i][2] = s[i][3] = 0.f; }
        #pragma unroll
        for (int kk = 0; kk < 16; kk++) {
            const int kb = kk * 8 + cb;
            uint2 lo = *(const uint2*)&sm[aRow * QLD + kb];
            uint2 hi = *(const uint2*)&sm[(aRow + 8) * QLD + kb];
            uint32_t a[4] = {lo.x, hi.x, lo.y, hi.y};
            #pragma unroll
            for (int nt = 0; nt < 8; nt++) {
                uint2 bf = *(const uint2*)&Ks[(nt * 8 + (lane >> 2)) * KLD + kb];
                mma_tf32(s[nt], a, bf.x, bf.y);
            }
        }

        const int kv0 = it * FBN;
        if (kv0 + FBN > Sc) {
            #pragma unroll
            for (int nt = 0; nt < 8; nt++) {
                int c0 = kv0 + nt * 8 + cb;
                if (c0 >= Sc)     { s[nt][0] = -CUDART_INF_F; s[nt][2] = -CUDART_INF_F; }
                if (c0 + 1 >= Sc) { s[nt][1] = -CUDART_INF_F; s[nt][3] = -CUDART_INF_F; }
            }
        }

        float mx_a = -CUDART_INF_F, mx_b = -CUDART_INF_F;
        #pragma unroll
        for (int nt = 0; nt < 8; nt++) {
            mx_a = fmaxf(mx_a, fmaxf(s[nt][0], s[nt][1]));
            mx_b = fmaxf(mx_b, fmaxf(s[nt][2], s[nt][3]));
        }
        mx_a = fmaxf(mx_a, __shfl_xor_sync(0xffffffffu, mx_a, 1));
        mx_a = fmaxf(mx_a, __shfl_xor_sync(0xffffffffu, mx_a, 2));
        mx_b = fmaxf(mx_b, __shfl_xor_sync(0xffffffffu, mx_b, 1));
        mx_b = fmaxf(mx_b, __shfl_xor_sync(0xffffffffu, mx_b, 2));
        float mn_a = fmaxf(m_a, mx_a), mn_b = fmaxf(m_b, mx_b);
        float ca = __expf(m_a - mn_a), cbv = __expf(m_b - mn_b);
        m_a = mn_a; m_b = mn_b;

        float ra = 0.f, rb = 0.f;
        #pragma unroll
        for (int nt = 0; nt < 8; nt++) {
            s[nt][0] = round_tf32(__expf(s[nt][0] - mn_a));
            s[nt][1] = round_tf32(__expf(s[nt][1] - mn_a));
            s[nt][2] = round_tf32(__expf(s[nt][2] - mn_b));
            s[nt][3] = round_tf32(__expf(s[nt][3] - mn_b));
            ra += s[nt][0] + s[nt][1];
            rb += s[nt][2] + s[nt][3];
        }
        ra += __shfl_xor_sync(0xffffffffu, ra, 1);
        ra += __shfl_xor_sync(0xffffffffu, ra, 2);
        rb += __shfl_xor_sync(0xffffffffu, rb, 1);
        rb += __shfl_xor_sync(0xffffffffu, rb, 2);
        l_a = l_a * ca + ra;
        l_b = l_b * cbv + rb;

        #pragma unroll
        for (int dt = 0; dt < 16; dt++) {
            o[dt][0] *= ca;  o[dt][1] *= ca;
            o[dt][2] *= cbv; o[dt][3] *= cbv;
        }

        #pragma unroll
        for (int nt = 0; nt < 8; nt++) {
            uint32_t a[4] = { __float_as_uint(s[nt][0]), __float_as_uint(s[nt][2]),
                              __float_as_uint(s[nt][1]), __float_as_uint(s[nt][3]) };
            #pragma unroll
            for (int dt = 0; dt < 16; dt++) {
                uint2 bf = *(const uint2*)&Vts[(dt * 8 + (lane >> 2)) * VLD + nt * 8 + cb];
                mma_tf32(o[dt], a, bf.x, bf.y);
            }
        }

        __syncthreads();
        if (it + 2 < NITER) load_kv(it & 1, it + 2);
    }

    float inva = 1.f / l_a, invb = 1.f / l_b;
    int r0 = q0 + aRow, r1 = r0 + 8;
    float* og0 = att + ((ll)b * Sc + r0) * Fc + h * DHc;
    float* og1 = att + ((ll)b * Sc + r1) * Fc + h * DHc;
    #pragma unroll
    for (int dt = 0; dt < 16; dt++) {
        int col = dt * 8 + cb;
        if (r0 < Sc) {
            float2 v = make_float2(round_tf32(o[dt][0] * inva), round_tf32(o[dt][1] * inva));
            *(float2*)(og0 + col) = v;
        }
        if (r1 < Sc) {
            float2 v = make_float2(round_tf32(o[dt][2] * invb), round_tf32(o[dt][3] * invb));
            *(float2*)(og1 + col) = v;
        }
    }
}

// ---------------------------------------------------------------------------
// Block reductions
// ---------------------------------------------------------------------------
__device__ __forceinline__ float blkReduceSum(float v) {
    __shared__ float sh[32];
    int lane = threadIdx.x & 31, w = threadIdx.x >> 5;
    #pragma unroll
    for (int o = 16; o; o >>= 1) v += __shfl_xor_sync(0xffffffffu, v, o);
    if (lane == 0) sh[w] = v;
    __syncthreads();
    int nw = blockDim.x >> 5;
    float r = (lane < nw) ? sh[lane] : 0.f;
    #pragma unroll
    for (int o = 16; o; o >>= 1) r += __shfl_xor_sync(0xffffffffu, r, o);
    __syncthreads();
    return r;
}

// ---------------------------------------------------------------------------
// Weight prep: ONE grid-stride kernel rounds every weight matrix (both layers)
// ---------------------------------------------------------------------------
constexpr int SEG0 = 2 * FF;                 // L0 Wiq|Wik -> wiR[0]
constexpr int SEG1 = SEG0 + FF;              // L0 Wiv -> wfqkv[0] + 2FF
constexpr int SEG2 = SEG1 + 2 * FF;          // L1 Wiq|Wik -> wiR + 2FF
constexpr int SEG3 = SEG2 + FF;              // L1 Wiv -> wfqkv[1] + 2FF
constexpr int SEG4 = SEG3 + 2 * FF;          // out_w both -> owR
constexpr int SEG5 = SEG4 + 2 * DFFc * Fc;   // l1w both -> l1R
constexpr int SEG6 = SEG5 + 2 * Fc * DFFc;   // l2w both -> l2R
constexpr int SEG7 = SEG6 + 3 * FF;          // embw -> embR
__global__ void round_weights_kernel(const float* __restrict__ in_w,
                                     const float* __restrict__ out_w,
                                     const float* __restrict__ l1w,
                                     const float* __restrict__ l2w,
                                     const float* __restrict__ embw,
                                     float* __restrict__ wiR,
                                     float* __restrict__ wfqkv,
                                     float* __restrict__ owR,
                                     float* __restrict__ l1R,
                                     float* __restrict__ l2R,
                                     float* __restrict__ embR)
{
    for (int i = blockIdx.x * 256 + threadIdx.x; i < SEG7; i += gridDim.x * 256) {
        if (i < SEG0)      wiR[i]                      = round_tf32(in_w[i]);
        else if (i < SEG1) wfqkv[2 * FF + (i - SEG0)]  = round_tf32(in_w[i]);
        else if (i < SEG2) wiR[2 * FF + (i - SEG1)]    = round_tf32(in_w[3 * FF + (i - SEG1)]);
        else if (i < SEG3) wfqkv[(ll)F3 * Fc + 2 * FF + (i - SEG2)]
                                                       = round_tf32(in_w[5 * FF + (i - SEG2)]);
        else if (i < SEG4) owR[i - SEG3]               = round_tf32(out_w[i - SEG3]);
        else if (i < SEG5) l1R[i - SEG4]               = round_tf32(l1w[i - SEG4]);
        else if (i < SEG6) l2R[i - SEG5]               = round_tf32(l2w[i - SEG5]);
        else               embR[i - SEG6]              = round_tf32(embw[i - SEG6]);
    }
}

// transpose wq/wk for both layers in one launch; z = l*2 + (0=q,1=k).
// q slices scaled by scl before rounding (folds 1/sqrt(dh) into fused weights).
__global__ void transpose_qk_kernel(const float* __restrict__ wq,
                                    const float* __restrict__ wk,
                                    float* __restrict__ wt, float scl)
{
    __shared__ float tile[32][33];
    int z = blockIdx.z, l = z >> 1, isK = z & 1;
    const float* in = (isK ? wk : wq) + (ll)l * FF;
    float* outp = wt + (ll)z * FF;
    float mul = isK ? 1.f : scl;
    int r0 = blockIdx.x * 32, c0 = blockIdx.y * 32;
    int tx = threadIdx.x, ty = threadIdx.y;
    #pragma unroll
    for (int i = 0; i < 4; i++)
        tile[ty + i * 8][tx] = in[(ll)(r0 + ty + i * 8) * Fc + c0 + tx];
    __syncthreads();
    int r = r0 + tx;
    #pragma unroll
    for (int i = 0; i < 4; i++) {
        int c = c0 + ty + i * 8;
        outp[(ll)c * Fc + r] = round_tf32(tile[tx][ty + i * 8] * mul);
    }
}

// fused biases, one launch: grid (Fc, 6).
// y<4: l=y>>1, isK=y&1: bfqkv[l][isK*F + n] = scl*(in_b[..] + Wi row . bsmall)
// y>=4: l=y-4: V bias copy.
__global__ void fuse_bias_all_kernel(const float* __restrict__ in_w,
                                     const float* __restrict__ in_b,
                                     const float* __restrict__ bq,
                                     const float* __restrict__ bk,
                                     float* __restrict__ bfqkv, float scale)
{
    int n = blockIdx.x, y = blockIdx.y;
    if (y >= 4) {
        int l = y - 4;
        if (threadIdx.x == 0)
            bfqkv[l * F3 + 2 * Fc + n] = in_b[(ll)l * F3 + 2 * Fc + n];
        return;
    }
    int l = y >> 1, isK = y & 1;
    const float* Wi = in_w + (ll)l * 3 * FF + (ll)isK * FF;
    const float* bs = (isK ? bk : bq) + (ll)l * Fc;
    float s = 0.f;
    for (int t = threadIdx.x; t < Fc; t += 256) s += Wi[(size_t)n * Fc + t] * bs[t];
    s = blkReduceSum(s);
    if (threadIdx.x == 0) {
        float badd = in_b[(ll)l * F3 + isK * Fc + n];
        bfqkv[l * F3 + isK * Fc + n] = (s + badd) * (isK ? 1.f : scale);
    }
}

// ---------------------------------------------------------------------------
// Small kernels
// ---------------------------------------------------------------------------
__global__ void copy_x_kernel(const float* __restrict__ x, float* __restrict__ src,
                              float* __restrict__ srcR) {
    int idx = blockIdx.x * 256 + threadIdx.x;
    if (idx >= Bc * Tc * Fc) return;
    int b = idx / (Tc * Fc);
    int r = idx - b * (Tc * Fc);
    float v = x[idx];
    size_t o = (size_t)b * Sc * Fc + r;
    src[o] = v;
    srcR[o] = round_tf32(v);
}

__global__ void fill_proto_kernel(const float* __restrict__ proto, float* __restrict__ src,
                                  float* __restrict__ srcR) {
    int idx = blockIdx.x * 256 + threadIdx.x;
    if (idx >= Bc * Cc * Fc) return;
    int b   = idx / (Cc * Fc);
    int rem = idx - b * (Cc * Fc);
    int c   = rem / Fc;
    int f   = rem - c * Fc;
    float v = proto[(size_t)f * Cc + c];
    size_t o = (size_t)b * Sc * Fc + (size_t)(Tc + c) * Fc + f;
    src[o] = v;
    srcR[o] = round_tf32(v);
}

// src = LN(src + delta); also writes tf32-rounded copy to srcR
__global__ void ln_add_kernel(float* __restrict__ src, float* __restrict__ srcR,
                              const float* __restrict__ delta,
                              const float* __restrict__ g, const float* __restrict__ b) {
    size_t row = blockIdx.x;
    float* sp = src + row * Fc;
    float* rp = srcR + row * Fc;
    const float* dp = delta + row * Fc;
    float x[4];
    float s = 0.f;
    #pragma unroll
    for (int j = 0; j < 4; j++) {
        int i = threadIdx.x + j * 256;
        x[j] = sp[i] + dp[i];
        s += x[j];
    }
    float mean = blkReduceSum(s) * (1.f / Fc);
    float s2 = 0.f;
    #pragma unroll
    for (int j = 0; j < 4; j++) { float d = x[j] - mean; s2 += d * d; }
    float var = blkReduceSum(s2) * (1.f / Fc);
    float rstd = rsqrtf(var + 1e-5f);
    #pragma unroll
    for (int j = 0; j < 4; j++) {
        int i = threadIdx.x + j * 256;
        float o = (x[j] - mean) * rstd * g[i] + b[i];
        sp[i] = o;
        rp[i] = round_tf32(o);
    }
}

__global__ void im2col_kernel(const float* __restrict__ srcR, float* __restrict__ col) {
    int idx = blockIdx.x * 256 + threadIdx.x;
    if (idx >= Bc * Tc * 3 * Fc) return;
    int c3 = idx % (3 * Fc);
    int bt = idx / (3 * Fc);
    int t = bt % Tc, b = bt / Tc;
    int fi = c3 / 3, kk = c3 - fi * 3;
    int tt = t + kk - 1;
    float v = 0.f;
    if (tt >= 0 && tt < Tc) v = srcR[(size_t)b * Sc * Fc + (size_t)tt * Fc + fi];
    col[idx] = v;
}

// generic transpose with tf32 rounding of outputs (vt build)
__global__ void transpose_kernel(const float* __restrict__ in, float* __restrict__ outp,
                                 int R, int ldin, int ldout, ll sIn, ll sOut) {
    __shared__ float tile[32][33];
    int b = blockIdx.z;
    in += b * sIn; outp += b * sOut;
    int r0 = blockIdx.x * 32, c0 = blockIdx.y * 32;
    int tx = threadIdx.x, ty = threadIdx.y;
    #pragma unroll
    for (int i = 0; i < 4; i++) {
        int r = r0 + ty + i * 8;
        if (r < R) tile[ty + i * 8][tx] = in[(ll)r * ldin + c0 + tx];
    }
    __syncthreads();
    int r = r0 + tx;
    if (r < R) {
        #pragma unroll
        for (int i = 0; i < 4; i++) {
            int c = c0 + ty + i * 8;
            outp[(ll)c * ldout + r] = round_tf32(tile[tx][ty + i * 8]);
        }
    }
}

__global__ void transpose_relu_kernel(const float* __restrict__ in, float* __restrict__ outp) {
    __shared__ float tile[32][33];
    int b = blockIdx.z;
    int t0 = blockIdx.x * 32, f0 = blockIdx.y * 32;
    int tx = threadIdx.x, ty = threadIdx.y;
    #pragma unroll
    for (int i = 0; i < 4; i++) {
        int tt = t0 + ty + i * 8;
        tile[ty + i * 8][tx] = in[(size_t)b * Tc * Fc + (size_t)tt * Fc + f0 + tx];
    }
    __syncthreads();
    #pragma unroll
    for (int i = 0; i < 4; i++) {
        int f = f0 + ty + i * 8;
        float v = tile[tx][ty + i * 8];
        outp[(size_t)b * Fc * Tc + (size_t)f * Tc + t0 + tx] = fmaxf(v, 0.f);
    }
}

// ---------------------------------------------------------------------------
// Host dispatch
// ---------------------------------------------------------------------------
static void launch_tmma(bool hasbias, bool dorelu, bool doround,
                        int M, int N, int K,
                        const float* A, int lda, const float* B, int ldb,
                        float* C, int ldc, const float* bias, float alpha,
                        int nz = 1, int batchH = 1,
                        ll sAb = 0, ll sAh = 0, ll sBb = 0, ll sBh = 0,
                        ll sCb = 0, ll sCh = 0)
{
    dim3 grid((N + 127) / 128, (M + 127) / 128, nz);
    #define TM_ARGS M, N, K, A, lda, B, ldb, C, ldc, bias, alpha, batchH, sAb, sAh, sBb, sBh, sCb, sCh
    if (!hasbias && !dorelu && doround)
        tmma_kernel<false, false, true ><<<grid, 256, TMMA_SMEM>>>(TM_ARGS);
    else if (!hasbias && !dorelu && !doround)
        tmma_kernel<false, false, false><<<grid, 256, TMMA_SMEM>>>(TM_ARGS);
    else if (hasbias && !dorelu && doround)
        tmma_kernel<true,  false, true ><<<grid, 256, TMMA_SMEM>>>(TM_ARGS);
    else if (hasbias && !dorelu && !doround)
        tmma_kernel<true,  false, false><<<grid, 256, TMMA_SMEM>>>(TM_ARGS);
    else
        tmma_kernel<true,  true,  true ><<<grid, 256, TMMA_SMEM>>>(TM_ARGS);
    #undef TM_ARGS
}

extern "C" void kernel_launch(void* const* d_in, const int* in_sizes, int n_in,
                              void* d_out, int out_size)
{
    const float* x      = (const float*)d_in[0];
    const float* proto  = (const float*)d_in[1];
    const float* wq     = (const float*)d_in[2];
    const float* bq     = (const float*)d_in[3];
    const float* wk     = (const float*)d_in[4];
    const float* bk     = (const float*)d_in[5];
    const float* in_w   = (const float*)d_in[6];
    const float* in_b   = (const float*)d_in[7];
    const float* out_w  = (const float*)d_in[8];
    const float* out_b  = (const float*)d_in[9];
    const float* l1w    = (const float*)d_in[10];
    const float* l1b    = (const float*)d_in[11];
    const float* l2w    = (const float*)d_in[12];
    const float* l2b    = (const float*)d_in[13];
    const float* ln1g   = (const float*)d_in[14];
    const float* ln1b   = (const float*)d_in[15];
    const float* ln2g   = (const float*)d_in[16];
    const float* ln2b   = (const float*)d_in[17];
    const float* embw   = (const float*)d_in[18];
    const float* embb   = (const float*)d_in[19];
    float* out = (float*)d_out;

    cudaFuncSetAttribute(tmma_kernel<false, false, true >,
                         cudaFuncAttributeMaxDynamicSharedMemorySize, (int)TMMA_SMEM);
    cudaFuncSetAttribute(tmma_kernel<false, false, false>,
                         cudaFuncAttributeMaxDynamicSharedMemorySize, (int)TMMA_SMEM);
    cudaFuncSetAttribute(tmma_kernel<true,  false, true >,
                         cudaFuncAttributeMaxDynamicSharedMemorySize, (int)TMMA_SMEM);
    cudaFuncSetAttribute(tmma_kernel<true,  false, false>,
                         cudaFuncAttributeMaxDynamicSharedMemorySize, (int)TMMA_SMEM);
    cudaFuncSetAttribute(tmma_kernel<true,  true,  true >,
                         cudaFuncAttributeMaxDynamicSharedMemorySize, (int)TMMA_SMEM);
    cudaFuncSetAttribute(flash_kernel,
                         cudaFuncAttributeMaxDynamicSharedMemorySize, (int)FLASH_SMEM);

    float *src, *srcR, *qkv, *att, *tmp, *ffh, *vt, *wt;
    float *wfqkv, *bfqkv, *icol, *ct, *wiR, *owR, *l1R, *l2R, *embR;
    cudaGetSymbolAddress((void**)&src,  d_src);
    cudaGetSymbolAddress((void**)&srcR, d_srcR);
    cudaGetSymbolAddress((void**)&qkv,  d_qkv);
    cudaGetSymbolAddress((void**)&att,  d_att);
    cudaGetSymbolAddress((void**)&tmp,  d_tmp);
    cudaGetSymbolAddress((void**)&ffh,  d_ffh);
    cudaGetSymbolAddress((void**)&vt,   d_vt);
    cudaGetSymbolAddress((void**)&wt,   d_wt);
    cudaGetSymbolAddress((void**)&wfqkv, d_wfqkv);
    cudaGetSymbolAddress((void**)&bfqkv, d_bfqkv);
    cudaGetSymbolAddress((void**)&icol, d_icol);
    cudaGetSymbolAddress((void**)&ct,   d_ct);
    cudaGetSymbolAddress((void**)&wiR,  d_wiR);
    cudaGetSymbolAddress((void**)&owR,  d_owR);
    cudaGetSymbolAddress((void**)&l1R,  d_l1R);
    cudaGetSymbolAddress((void**)&l2R,  d_l2R);
    cudaGetSymbolAddress((void**)&embR, d_embR);

    const float scale = 0.08838834764831845f;  // 1/sqrt(128)

    // ---- input staging + ALL weight prep up front (4 launches) ----
    copy_x_kernel<<<(Bc * Tc * Fc + 255) / 256, 256>>>(x, src, srcR);
    fill_proto_kernel<<<(Bc * Cc * Fc + 255) / 256, 256>>>(proto, src, srcR);

    round_weights_kernel<<<4096, 256>>>(in_w, out_w, l1w, l2w, embw,
                                        wiR, wfqkv, owR, l1R, l2R, embR);
    transpose_qk_kernel<<<dim3(32, 32, 4), dim3(32, 8)>>>(wq, wk, wt, scale);
    // fused QKV weights, batched over (layer, q/k): wfqkv[l] rows [0,F)=Q, [F,2F)=K
    launch_tmma(false, false, true, Fc, Fc, Fc,
                wiR, Fc, wt, Fc, wfqkv, Fc, nullptr, 1.f,
                4, 2,
                (ll)2 * FF, (ll)FF, (ll)2 * FF, (ll)FF, (ll)F3 * Fc, (ll)FF);
    fuse_bias_all_kernel<<<dim3(Fc, 6), 256>>>(in_w, in_b, bq, bk, bfqkv, scale);

    for (int l = 0; l < Lc; l++) {
        const float* wfl = wfqkv + (ll)l * F3 * Fc;
        const float* bfl = bfqkv + (ll)l * F3;

        // packed QKV: (BS, 3F), Q pre-scaled; rounded outputs
        launch_tmma(true, false, true, BSc, F3, Fc, srcR, Fc, wfl, Fc,
                    qkv, F3, bfl, 1.f);

        // V^T per batch: (Sc,F slice of qkv) -> (F, SP); pad cols stay zero
        transpose_kernel<<<dim3((Sc + 31) / 32, Fc / 32, Bc), dim3(32, 8)>>>(
            qkv + 2 * Fc, vt, Sc, F3, SP, (ll)Sc * F3, (ll)Fc * SP);

        // fused attention: att = softmax(Q K^T) V
        flash_kernel<<<dim3((Sc + 127) / 128, Bc * Hc), 256, FLASH_SMEM>>>(
            qkv, qkv + Fc, vt, att, F3);

        // out-proj (residual delta: NOT rounded) + residual LN
        launch_tmma(true, false, false, BSc, Fc, Fc,
                    att, Fc, owR + (ll)l * FF, Fc, tmp, Fc, out_b + (ll)l * Fc, 1.f);
        ln_add_kernel<<<BSc, 256>>>(src, srcR, tmp, ln1g + (ll)l * Fc, ln1b + (ll)l * Fc);

        // FFN + residual LN
        launch_tmma(true, true, true, BSc, DFFc, Fc,
                    srcR, Fc, l1R + (ll)l * DFFc * Fc, Fc, ffh, DFFc,
                    l1b + (ll)l * DFFc, 1.f);
        launch_tmma(true, false, false, BSc, Fc, DFFc,
                    ffh, DFFc, l2R + (ll)l * Fc * DFFc, DFFc, tmp, Fc,
                    l2b + (ll)l * Fc, 1.f);
        ln_add_kernel<<<BSc, 256>>>(src, srcR, tmp, ln2g + (ll)l * Fc, ln2b + (ll)l * Fc);
    }

    // Conv1d(F->F, k=3, pad=1) as im2col GEMM (operands pre-rounded)
    im2col_kernel<<<(Bc * Tc * 3 * Fc + 255) / 256, 256>>>(srcR, icol);
    launch_tmma(true, false, false, Bc * Tc, Fc, 3 * Fc,
                icol, 3 * Fc, embR, 3 * Fc, ct, Fc, embb, 1.f);

    transpose_relu_kernel<<<dim3(Tc / 32, Fc / 32, Bc), dim3(32, 8)>>>(ct, out);
}

// round 12
// speedup vs baseline: 1.7230x; 1.0129x over previous
#include <cuda_runtime.h>
#include <math_constants.h>
#include <cstdint>

typedef long long ll;

// Problem constants
constexpr int Lc   = 2;
constexpr int Bc   = 4;
constexpr int Tc   = 2048;
constexpr int Fc   = 1024;
constexpr int Cc   = 200;
constexpr int Hc   = 8;
constexpr int DFFc = 128;
constexpr int Sc   = Tc + Cc;   // 2248
constexpr int BSc  = Bc * Sc;   // 8992
constexpr int DHc  = Fc / Hc;   // 128
constexpr int SP   = 2304;      // padded S (36*64) for KV iteration
constexpr int F3   = 3 * Fc;    // packed QKV width
constexpr int FF   = Fc * Fc;

// ---------------------------------------------------------------------------
// Scratch (device globals; no allocations allowed)
// ---------------------------------------------------------------------------
__device__ float d_srcR[(size_t)BSc * Fc];                 // tf32-rounded residual
__device__ float d_qkv [(size_t)BSc * F3];                 // packed Q|K|V
__device__ float d_att [(size_t)BSc * Fc];
__device__ float d_tmp [(size_t)BSc * Fc];
__device__ float d_ffh [(size_t)BSc * DFFc];
__device__ float d_vt  [(size_t)Bc * Fc * SP];             // V transposed, padded
__device__ float d_wt  [4 * FF];                           // transposed wq/wk (2 layers)
__device__ float d_wfqkv[(size_t)2 * F3 * Fc];             // fused+rounded QKV weights
__device__ float d_bfqkv[2 * F3];
__device__ float d_ct  [(size_t)Bc * Tc * Fc];
// tf32-rounded weight copies (both layers)
__device__ float d_wiR [2 * 2 * FF];                       // Wiq|Wik per layer
__device__ float d_owR [2 * FF];
__device__ float d_l1R [2 * DFFc * Fc];
__device__ float d_l2R [2 * Fc * DFFc];
__device__ float d_embR[3 * FF];                           // repacked [kk][o][i] K-major

// ---------------------------------------------------------------------------
// PTX helpers (sm_80-compatible only — harness compiles for plain sm_100)
// ---------------------------------------------------------------------------
__device__ __forceinline__ uint32_t smem_u32(const void* p) {
    uint32_t a;
    asm("{ .reg .u64 t; cvta.to.shared.u64 t, %1; cvt.u32.u64 %0, t; }" : "=r"(a) : "l"(p));
    return a;
}

__device__ __forceinline__ void cp_async16(uint32_t dst, const float* src, int pred_bytes) {
    asm volatile("cp.async.cg.shared.global [%0], [%1], 16, %2;"
                 :: "r"(dst), "l"(src), "r"(pred_bytes) : "memory");
}
#define CP_COMMIT() asm volatile("cp.async.commit_group;" ::: "memory")
#define CP_WAIT2()  asm volatile("cp.async.wait_group 2;" ::: "memory")
#define CP_WAIT1()  asm volatile("cp.async.wait_group 1;" ::: "memory")

__device__ __forceinline__ uint32_t cvt_tf32(float f) {
    uint32_t u;
    asm("cvt.rna.tf32.f32 %0, %1;" : "=r"(u) : "f"(f));
    return u;
}
__device__ __forceinline__ float round_tf32(float f) {
    return __uint_as_float(cvt_tf32(f));
}

__device__ __forceinline__ void mma_tf32(float* c, const uint32_t* a,
                                         uint32_t b0, uint32_t b1) {
    asm volatile(
        "mma.sync.aligned.m16n8k8.row.col.f32.tf32.tf32.f32 "
        "{%0,%1,%2,%3}, {%4,%5,%6,%7}, {%8,%9}, {%0,%1,%2,%3};"
        : "+f"(c[0]), "+f"(c[1]), "+f"(c[2]), "+f"(c[3])
        : "r"(a[0]), "r"(a[1]), "r"(a[2]), "r"(a[3]), "r"(b0), "r"(b1));
}

// ---------------------------------------------------------------------------
// Tensor-core tf32 GEMM:  C (=|+=) alpha*A*B^T (+bias) (+relu) (+round)
// Operands pre-rounded to tf32 (RNA). k-slot permutation -> ld.shared.v2 frags.
// 4-stage pipeline, K-chunk 16, ONE __syncthreads per chunk, 96KB smem ->
// 2 CTAs/SM. KPAD=24 conflict-free. K % 16 == 0, K >= 48.
// A rows are read at (gm + rowOff), zero-predicated outside [0, rowLimA) —
// gives shifted/padded reads for conv. ACCUM: C += result (RMW epilogue).
// ---------------------------------------------------------------------------
constexpr int KPAD = 24;
constexpr int STAGE_FLOATS = 2 * 128 * KPAD;                   // 6144
constexpr size_t TMMA_SMEM = (size_t)4 * STAGE_FLOATS * 4;     // 98304 B

template<bool HASBIAS, bool DORELU, bool ROUND, bool ACCUM>
__global__ void __launch_bounds__(256, 2)
tmma_kernel(int M, int N, int K,
            const float* __restrict__ A, int lda,
            const float* __restrict__ B, int ldb,
            float* __restrict__ C, int ldc,
            const float* __restrict__ bias, float alpha,
            int batchH,
            ll sAb, ll sAh, ll sBb, ll sBh, ll sCb, ll sCh,
            int rowOff, int rowLimA)
{
    extern __shared__ float sm[];

    const int t = threadIdx.x;
    const int wid = t >> 5, lane = t & 31;
    const int warp_m = wid & 3, warp_n = wid >> 2;

    {
        int z = blockIdx.z;
        int zb = z / batchH, zh = z - zb * batchH;
        A += zb * sAb + zh * sAh;
        B += zb * sBb + zh * sBh;
        C += zb * sCb + zh * sCh;
    }
    const int m0 = blockIdx.y * 128, n0 = blockIdx.x * 128;

    const uint32_t smb = smem_u32(sm);
    const int KT = K >> 4;

    auto load_stage = [&](int stage, int kc) {
        const int k0 = kc << 4;
        uint32_t aB = smb + (uint32_t)(stage * STAGE_FLOATS) * 4;
        uint32_t bB = aB + 128 * KPAD * 4;
        #pragma unroll
        for (int i = 0; i < 2; i++) {
            int idx = t + i * 256;          // 0..511
            int row = idx >> 2, sub = idx & 3;
            int gn = n0 + row;
            int ar = m0 + row + rowOff;
            cp_async16(aB + (uint32_t)(row * KPAD + sub * 4) * 4,
                       A + (ll)ar * lda + k0 + sub * 4,
                       ((unsigned)ar < (unsigned)rowLimA) ? 16 : 0);
            cp_async16(bB + (uint32_t)(row * KPAD + sub * 4) * 4,
                       B + (ll)gn * ldb + k0 + sub * 4, (gn < N) ? 16 : 0);
        }
    };

    float c[2][8][4] = {};
    const int aRowBase = warp_m * 32 + (lane >> 2);
    const int bRowBase = warp_n * 64 + (lane >> 2);
    const int kLane2 = (lane & 3) << 1;

    load_stage(0, 0); CP_COMMIT();
    load_stage(1, 1); CP_COMMIT();
    load_stage(2, 2); CP_COMMIT();

    for (int kt = 0; kt < KT; kt++) {
        CP_WAIT2();
        __syncthreads();
        if (kt + 3 < KT) load_stage((kt + 3) & 3, kt + 3);
        CP_COMMIT();

        const float* As = sm + (kt & 3) * STAGE_FLOATS;
        const float* Bs = As + 128 * KPAD;

        #pragma unroll
        for (int kk = 0; kk < 2; kk++) {
            const int kb = kk * 8 + kLane2;
            uint32_t a[2][4];
            #pragma unroll
            for (int mt = 0; mt < 2; mt++) {
                int r = aRowBase + mt * 16;
                uint2 lo = *(const uint2*)&As[r * KPAD + kb];
                uint2 hi = *(const uint2*)&As[(r + 8) * KPAD + kb];
                a[mt][0] = lo.x; a[mt][1] = hi.x;
                a[mt][2] = lo.y; a[mt][3] = hi.y;
            }
            #pragma unroll
            for (int nt = 0; nt < 8; nt++) {
                uint2 b = *(const uint2*)&Bs[(bRowBase + nt * 8) * KPAD + kb];
                mma_tf32(c[0][nt], a[0], b.x, b.y);
                mma_tf32(c[1][nt], a[1], b.x, b.y);
            }
        }
    }

    #pragma unroll
    for (int mt = 0; mt < 2; mt++) {
        const int r0 = m0 + warp_m * 32 + mt * 16 + (lane >> 2);
        const int r1 = r0 + 8;
        #pragma unroll
        for (int nt = 0; nt < 8; nt++) {
            const int cb = n0 + warp_n * 64 + nt * 8;
            if (cb < N) {
                const int col = cb + 2 * (lane & 3);
                float2 v0 = make_float2(c[mt][nt][0] * alpha, c[mt][nt][1] * alpha);
                float2 v1 = make_float2(c[mt][nt][2] * alpha, c[mt][nt][3] * alpha);
                if (HASBIAS) {
                    float bx = bias[col], by = bias[col + 1];
                    v0.x += bx; v0.y += by; v1.x += bx; v1.y += by;
                }
                if (DORELU) {
                    v0.x = fmaxf(v0.x, 0.f); v0.y = fmaxf(v0.y, 0.f);
                    v1.x = fmaxf(v1.x, 0.f); v1.y = fmaxf(v1.y, 0.f);
                }
                if (ROUND) {
                    v0.x = round_tf32(v0.x); v0.y = round_tf32(v0.y);
                    v1.x = round_tf32(v1.x); v1.y = round_tf32(v1.y);
                }
                if (r0 < M) {
                    float* p = C + (ll)r0 * ldc + col;
                    if (ACCUM) { float2 o = *(float2*)p; v0.x += o.x; v0.y += o.y; }
                    *(float2*)p = v0;
                }
                if (r1 < M) {
                    float* p = C + (ll)r1 * ldc + col;
                    if (ACCUM) { float2 o = *(float2*)p; v1.x += o.x; v1.y += o.y; }
                    *(float2*)p = v1;
                }
            }
        }
    }
}

// ---------------------------------------------------------------------------
// Flash attention (as R11): att = softmax(Q K^T) V, per (b,h).
// ---------------------------------------------------------------------------
constexpr int FBN   = 64;
constexpr int NITER = SP / FBN;        // 36
constexpr int QLD = 132, KLD = 132, VLD = 72;
constexpr int KVSTG = 64 * KLD + 128 * VLD;
constexpr size_t FLASH_SMEM = (size_t)(128 * QLD + 2 * KVSTG) * 4;  // 208896 B

__global__ void __launch_bounds__(256, 1)
flash_kernel(const float* __restrict__ q, const float* __restrict__ k,
             const float* __restrict__ vt, float* __restrict__ att, int qld)
{
    extern __shared__ float sm[];
    const int t = threadIdx.x, wid = t >> 5, lane = t & 31;
    const int b = blockIdx.y >> 3, h = blockIdx.y & 7;
    const int q0 = blockIdx.x * 128;

    const float* qg = q  + ((ll)b * Sc) * qld + (ll)h * DHc;
    const float* kg = k  + ((ll)b * Sc) * qld + (ll)h * DHc;
    const float* vg = vt + (ll)b * Fc * SP + (ll)h * DHc * SP;

    const uint32_t smb = smem_u32(sm);

    #pragma unroll
    for (int i = 0; i < 16; i++) {
        int idx = t + i * 256;
        int row = idx >> 5, c4 = idx & 31;
        int gr = q0 + row;
        cp_async16(smb + (uint32_t)(row * QLD + c4 * 4) * 4,
                   qg + (ll)gr * qld + c4 * 4, gr < Sc ? 16 : 0);
    }
    CP_COMMIT();

    auto load_kv = [&](int stage, int it) {
        uint32_t ks = smb + (uint32_t)(128 * QLD + stage * KVSTG) * 4;
        uint32_t vs = ks + (uint32_t)(64 * KLD) * 4;
        int kv0 = it * FBN;
        #pragma unroll
        for (int i = 0; i < 8; i++) {
            int idx = t + i * 256;
            int row = idx >> 5, c4 = idx & 31;
            int gr = kv0 + row;
            cp_async16(ks + (uint32_t)(row * KLD + c4 * 4) * 4,
                       kg + (ll)gr * qld + c4 * 4, gr < Sc ? 16 : 0);
        }
        #pragma unroll
        for (int i = 0; i < 8; i++) {
            int idx = t + i * 256;
            int row = idx >> 4, c4 = idx & 15;
            cp_async16(vs + (uint32_t)(row * VLD + c4 * 4) * 4,
                       vg + (ll)row * SP + kv0 + c4 * 4, 16);
        }
        CP_COMMIT();
    };

    load_kv(0, 0);
    load_kv(1, 1);

    const int aRow = wid * 16 + (lane >> 2);
    const int cb = 2 * (lane & 3);

    float o[16][4];
    #pragma unroll
    for (int i = 0; i < 16; i++) { o[i][0] = o[i][1] = o[i][2] = o[i][3] = 0.f; }
    float m_a = -CUDART_INF_F, m_b = -CUDART_INF_F;
    float l_a = 0.f, l_b = 0.f;

    for (int it = 0; it < NITER; it++) {
        CP_WAIT1();
        __syncthreads();
        const float* Ks  = sm + 128 * QLD + (it & 1) * KVSTG;
        const float* Vts = Ks + 64 * KLD;

        float s[8][4];
        #pragma unroll
        for (int i = 0; i < 8; i++) { s[i][0] = s[i][1] = s[i][2] = s[i][3] = 0.f; }
        #pragma unroll
        for (int kk = 0; kk < 16; kk++) {
            const int kb = kk * 8 + cb;
            uint2 lo = *(const uint2*)&sm[aRow * QLD + kb];
            uint2 hi = *(const uint2*)&sm[(aRow + 8) * QLD + kb];
            uint32_t a[4] = {lo.x, hi.x, lo.y, hi.y};
            #pragma unroll
            for (int nt = 0; nt < 8; nt++) {
                uint2 bf = *(const uint2*)&Ks[(nt * 8 + (lane >> 2)) * KLD + kb];
                mma_tf32(s[nt], a, bf.x, bf.y);
            }
        }

        const int kv0 = it * FBN;
        if (kv0 + FBN > Sc) {
            #pragma unroll
            for (int nt = 0; nt < 8; nt++) {
                int c0 = kv0 + nt * 8 + cb;
                if (c0 >= Sc)     { s[nt][0] = -CUDART_INF_F; s[nt][2] = -CUDART_INF_F; }
                if (c0 + 1 >= Sc) { s[nt][1] = -CUDART_INF_F; s[nt][3] = -CUDART_INF_F; }
            }
        }

        float mx_a = -CUDART_INF_F, mx_b = -CUDART_INF_F;
        #pragma unroll
        for (int nt = 0; nt < 8; nt++) {
            mx_a = fmaxf(mx_a, fmaxf(s[nt][0], s[nt][1]));
            mx_b = fmaxf(mx_b, fmaxf(s[nt][2], s[nt][3]));
        }
        mx_a = fmaxf(mx_a, __shfl_xor_sync(0xffffffffu, mx_a, 1));
        mx_a = fmaxf(mx_a, __shfl_xor_sync(0xffffffffu, mx_a, 2));
        mx_b = fmaxf(mx_b, __shfl_xor_sync(0xffffffffu, mx_b, 1));
        mx_b = fmaxf(mx_b, __shfl_xor_sync(0xffffffffu, mx_b, 2));
        float mn_a = fmaxf(m_a, mx_a), mn_b = fmaxf(m_b, mx_b);
        float ca = __expf(m_a - mn_a), cbv = __expf(m_b - mn_b);
        m_a = mn_a; m_b = mn_b;

        float ra = 0.f, rb = 0.f;
        #pragma unroll
        for (int nt = 0; nt < 8; nt++) {
            s[nt][0] = round_tf32(__expf(s[nt][0] - mn_a));
            s[nt][1] = round_tf32(__expf(s[nt][1] - mn_a));
            s[nt][2] = round_tf32(__expf(s[nt][2] - mn_b));
            s[nt][3] = round_tf32(__expf(s[nt][3] - mn_b));
            ra += s[nt][0] + s[nt][1];
            rb += s[nt][2] + s[nt][3];
        }
        ra += __shfl_xor_sync(0xffffffffu, ra, 1);
        ra += __shfl_xor_sync(0xffffffffu, ra, 2);
        rb += __shfl_xor_sync(0xffffffffu, rb, 1);
        rb += __shfl_xor_sync(0xffffffffu, rb, 2);
        l_a = l_a * ca + ra;
        l_b = l_b * cbv + rb;

        #pragma unroll
        for (int dt = 0; dt < 16; dt++) {
            o[dt][0] *= ca;  o[dt][1] *= ca;
            o[dt][2] *= cbv; o[dt][3] *= cbv;
        }

        #pragma unroll
        for (int nt = 0; nt < 8; nt++) {
            uint32_t a[4] = { __float_as_uint(s[nt][0]), __float_as_uint(s[nt][2]),
                              __float_as_uint(s[nt][1]), __float_as_uint(s[nt][3]) };
            #pragma unroll
            for (int dt = 0; dt < 16; dt++) {
                uint2 bf = *(const uint2*)&Vts[(dt * 8 + (lane >> 2)) * VLD + nt * 8 + cb];
                mma_tf32(o[dt], a, bf.x, bf.y);
            }
        }

        __syncthreads();
        if (it + 2 < NITER) load_kv(it & 1, it + 2);
    }

    float inva = 1.f / l_a, invb = 1.f / l_b;
    int r0 = q0 + aRow, r1 = r0 + 8;
    float* og0 = att + ((ll)b * Sc + r0) * Fc + h * DHc;
    float* og1 = att + ((ll)b * Sc + r1) * Fc + h * DHc;
    #pragma unroll
    for (int dt = 0; dt < 16; dt++) {
        int col = dt * 8 + cb;
        if (r0 < Sc) {
            float2 v = make_float2(round_tf32(o[dt][0] * inva), round_tf32(o[dt][1] * inva));
            *(float2*)(og0 + col) = v;
        }
        if (r1 < Sc) {
            float2 v = make_float2(round_tf32(o[dt][2] * invb), round_tf32(o[dt][3] * invb));
            *(float2*)(og1 + col) = v;
        }
    }
}

// ---------------------------------------------------------------------------
// Block reductions
// ---------------------------------------------------------------------------
__device__ __forceinline__ float blkReduceSum(float v) {
    __shared__ float sh[32];
    int lane = threadIdx.x & 31, w = threadIdx.x >> 5;
    #pragma unroll
    for (int o = 16; o; o >>= 1) v += __shfl_xor_sync(0xffffffffu, v, o);
    if (lane == 0) sh[w] = v;
    __syncthreads();
    int nw = blockDim.x >> 5;
    float r = (lane < nw) ? sh[lane] : 0.f;
    #pragma unroll
    for (int o = 16; o; o >>= 1) r += __shfl_xor_sync(0xffffffffu, r, o);
    __syncthreads();
    return r;
}

// ---------------------------------------------------------------------------
// Weight prep: ONE grid-stride kernel rounds every weight matrix (both layers)
// emb segment repacks to [kk][o][i] K-major.
// ---------------------------------------------------------------------------
constexpr int SEG0 = 2 * FF;                 // L0 Wiq|Wik -> wiR[0]
constexpr int SEG1 = SEG0 + FF;              // L0 Wiv -> wfqkv[0] + 2FF
constexpr int SEG2 = SEG1 + 2 * FF;          // L1 Wiq|Wik -> wiR + 2FF
constexpr int SEG3 = SEG2 + FF;              // L1 Wiv -> wfqkv[1] + 2FF
constexpr int SEG4 = SEG3 + 2 * FF;          // out_w both -> owR
constexpr int SEG5 = SEG4 + 2 * DFFc * Fc;   // l1w both -> l1R
constexpr int SEG6 = SEG5 + 2 * Fc * DFFc;   // l2w both -> l2R
constexpr int SEG7 = SEG6 + 3 * FF;          // embw (repack) -> embR
__global__ void round_weights_kernel(const float* __restrict__ in_w,
                                     const float* __restrict__ out_w,
                                     const float* __restrict__ l1w,
                                     const float* __restrict__ l2w,
                                     const float* __restrict__ embw,
                                     float* __restrict__ wiR,
                                     float* __restrict__ wfqkv,
                                     float* __restrict__ owR,
                                     float* __restrict__ l1R,
                                     float* __restrict__ l2R,
                                     float* __restrict__ embR)
{
    for (int i = blockIdx.x * 256 + threadIdx.x; i < SEG7; i += gridDim.x * 256) {
        if (i < SEG0)      wiR[i]                      = round_tf32(in_w[i]);
        else if (i < SEG1) wfqkv[2 * FF + (i - SEG0)]  = round_tf32(in_w[i]);
        else if (i < SEG2) wiR[2 * FF + (i - SEG1)]    = round_tf32(in_w[3 * FF + (i - SEG1)]);
        else if (i < SEG3) wfqkv[(ll)F3 * Fc + 2 * FF + (i - SEG2)]
                                                       = round_tf32(in_w[5 * FF + (i - SEG2)]);
        else if (i < SEG4) owR[i - SEG3]               = round_tf32(out_w[i - SEG3]);
        else if (i < SEG5) l1R[i - SEG4]               = round_tf32(l1w[i - SEG4]);
        else if (i < SEG6) l2R[i - SEG5]               = round_tf32(l2w[i - SEG5]);
        else {
            int j = i - SEG6;
            int kk = j / FF, r = j - kk * FF;        // r = o*Fc + iin
            embR[j] = round_tf32(embw[(ll)r * 3 + kk]);
        }
    }
}

// transpose wq/wk for both layers in one launch; z = l*2 + (0=q,1=k).
__global__ void transpose_qk_kernel(const float* __restrict__ wq,
                                    const float* __restrict__ wk,
                                    float* __restrict__ wt, float scl)
{
    __shared__ float tile[32][33];
    int z = blockIdx.z, l = z >> 1, isK = z & 1;
    const float* in = (isK ? wk : wq) + (ll)l * FF;
    float* outp = wt + (ll)z * FF;
    float mul = isK ? 1.f : scl;
    int r0 = blockIdx.x * 32, c0 = blockIdx.y * 32;
    int tx = threadIdx.x, ty = threadIdx.y;
    #pragma unroll
    for (int i = 0; i < 4; i++)
        tile[ty + i * 8][tx] = in[(ll)(r0 + ty + i * 8) * Fc + c0 + tx];
    __syncthreads();
    int r = r0 + tx;
    #pragma unroll
    for (int i = 0; i < 4; i++) {
        int c = c0 + ty + i * 8;
        outp[(ll)c * Fc + r] = round_tf32(tile[tx][ty + i * 8] * mul);
    }
}

// fused biases, one launch: grid (Fc, 6).
__global__ void fuse_bias_all_kernel(const float* __restrict__ in_w,
                                     const float* __restrict__ in_b,
                                     const float* __restrict__ bq,
                                     const float* __restrict__ bk,
                                     float* __restrict__ bfqkv, float scale)
{
    int n = blockIdx.x, y = blockIdx.y;
    if (y >= 4) {
        int l = y - 4;
        if (threadIdx.x == 0)
            bfqkv[l * F3 + 2 * Fc + n] = in_b[(ll)l * F3 + 2 * Fc + n];
        return;
    }
    int l = y >> 1, isK = y & 1;
    const float* Wi = in_w + (ll)l * 3 * FF + (ll)isK * FF;
    const float* bs = (isK ? bk : bq) + (ll)l * Fc;
    float s = 0.f;
    for (int t = threadIdx.x; t < Fc; t += 256) s += Wi[(size_t)n * Fc + t] * bs[t];
    s = blkReduceSum(s);
    if (threadIdx.x == 0) {
        float badd = in_b[(ll)l * F3 + isK * Fc + n];
        bfqkv[l * F3 + isK * Fc + n] = (s + badd) * (isK ? 1.f : scale);
    }
}

// ---------------------------------------------------------------------------
// Small kernels
// ---------------------------------------------------------------------------
__global__ void copy_x_kernel(const float* __restrict__ x, float* __restrict__ srcR) {
    int idx = blockIdx.x * 256 + threadIdx.x;
    if (idx >= Bc * Tc * Fc) return;
    int b = idx / (Tc * Fc);
    int r = idx - b * (Tc * Fc);
    srcR[(size_t)b * Sc * Fc + r] = round_tf32(x[idx]);
}

__global__ void fill_proto_kernel(const float* __restrict__ proto, float* __restrict__ srcR) {
    int idx = blockIdx.x * 256 + threadIdx.x;
    if (idx >= Bc * Cc * Fc) return;
    int b   = idx / (Cc * Fc);
    int rem = idx - b * (Cc * Fc);
    int c   = rem / Fc;
    int f   = rem - c * Fc;
    srcR[(size_t)b * Sc * Fc + (size_t)(Tc + c) * Fc + f] = round_tf32(proto[(size_t)f * Cc + c]);
}

// srcR = round_tf32(LN(srcR + delta)); float4 path, one row per block
__global__ void ln_add_kernel(float* __restrict__ srcR, const float* __restrict__ delta,
                              const float* __restrict__ g, const float* __restrict__ b) {
    size_t row = blockIdx.x;
    float4* sp = (float4*)(srcR + row * Fc);
    const float4* dp = (const float4*)(delta + row * Fc);
    int i = threadIdx.x;      // 256 threads x float4 = 1024
    float4 xs = sp[i], ds = dp[i];
    xs.x += ds.x; xs.y += ds.y; xs.z += ds.z; xs.w += ds.w;
    float s = xs.x + xs.y + xs.z + xs.w;
    float mean = blkReduceSum(s) * (1.f / Fc);
    float dx = xs.x - mean, dy = xs.y - mean, dz = xs.z - mean, dw = xs.w - mean;
    float s2 = dx * dx + dy * dy + dz * dz + dw * dw;
    float var = blkReduceSum(s2) * (1.f / Fc);
    float rstd = rsqrtf(var + 1e-5f);
    const float4 gv = ((const float4*)g)[i];
    const float4 bv = ((const float4*)b)[i];
    float4 o;
    o.x = round_tf32(dx * rstd * gv.x + bv.x);
    o.y = round_tf32(dy * rstd * gv.y + bv.y);
    o.z = round_tf32(dz * rstd * gv.z + bv.z);
    o.w = round_tf32(dw * rstd * gv.w + bv.w);
    sp[i] = o;
}

// generic transpose with tf32 rounding of outputs (vt build)
__global__ void transpose_kernel(const float* __restrict__ in, float* __restrict__ outp,
                                 int R, int ldin, int ldout, ll sIn, ll sOut) {
    __shared__ float tile[32][33];
    int b = blockIdx.z;
    in += b * sIn; outp += b * sOut;
    int r0 = blockIdx.x * 32, c0 = blockIdx.y * 32;
    int tx = threadIdx.x, ty = threadIdx.y;
    #pragma unroll
    for (int i = 0; i < 4; i++) {
        int r = r0 + ty + i * 8;
        if (r < R) tile[ty + i * 8][tx] = in[(ll)r * ldin + c0 + tx];
    }
    __syncthreads();
    int r = r0 + tx;
    if (r < R) {
        #pragma unroll
        for (int i = 0; i < 4; i++) {
            int c = c0 + ty + i * 8;
            outp[(ll)c * ldout + r] = round_tf32(tile[tx][ty + i * 8]);
        }
    }
}

__global__ void transpose_relu_kernel(const float* __restrict__ in, float* __restrict__ outp) {
    __shared__ float tile[32][33];
    int b = blockIdx.z;
    int t0 = blockIdx.x * 32, f0 = blockIdx.y * 32;
    int tx = threadIdx.x, ty = threadIdx.y;
    #pragma unroll
    for (int i = 0; i < 4; i++) {
        int tt = t0 + ty + i * 8;
        tile[ty + i * 8][tx] = in[(size_t)b * Tc * Fc + (size_t)tt * Fc + f0 + tx];
    }
    __syncthreads();
    #pragma unroll
    for (int i = 0; i < 4; i++) {
        int f = f0 + ty + i * 8;
        float v = tile[tx][ty + i * 8];
        outp[(size_t)b * Fc * Tc + (size_t)f * Tc + t0 + tx] = fmaxf(v, 0.f);
    }
}

// ---------------------------------------------------------------------------
// Host dispatch
// ---------------------------------------------------------------------------
static void launch_tmma(bool hasbias, bool dorelu, bool doround, bool accum,
                        int M, int N, int K,
                        const float* A, int lda, const float* B, int ldb,
                        float* C, int ldc, const float* bias, float alpha,
                        int nz = 1, int batchH = 1,
                        ll sAb = 0, ll sAh = 0, ll sBb = 0, ll sBh = 0,
                        ll sCb = 0, ll sCh = 0,
                        int rowOff = 0, int rowLim = 0)
{
    if (rowLim == 0) rowLim = M;
    dim3 grid((N + 127) / 128, (M + 127) / 128, nz);
    #define TM_ARGS M, N, K, A, lda, B, ldb, C, ldc, bias, alpha, batchH, \
                    sAb, sAh, sBb, sBh, sCb, sCh, rowOff, rowLim
    if (accum)
        tmma_kernel<false, false, false, true ><<<grid, 256, TMMA_SMEM>>>(TM_ARGS);
    else if (!hasbias && !dorelu && doround)
        tmma_kernel<false, false, true,  false><<<grid, 256, TMMA_SMEM>>>(TM_ARGS);
    else if (hasbias && !dorelu && doround)
        tmma_kernel<true,  false, true,  false><<<grid, 256, TMMA_SMEM>>>(TM_ARGS);
    else if (hasbias && !dorelu && !doround)
        tmma_kernel<true,  false, false, false><<<grid, 256, TMMA_SMEM>>>(TM_ARGS);
    else
        tmma_kernel<true,  true,  true,  false><<<grid, 256, TMMA_SMEM>>>(TM_ARGS);
    #undef TM_ARGS
}

extern "C" void kernel_launch(void* const* d_in, const int* in_sizes, int n_in,
                              void* d_out, int out_size)
{
    const float* x      = (const float*)d_in[0];
    const float* proto  = (const float*)d_in[1];
    const float* wq     = (const float*)d_in[2];
    const float* bq     = (const float*)d_in[3];
    const float* wk     = (const float*)d_in[4];
    const float* bk     = (const float*)d_in[5];
    const float* in_w   = (const float*)d_in[6];
    const float* in_b   = (const float*)d_in[7];
    const float* out_w  = (const float*)d_in[8];
    const float* out_b  = (const float*)d_in[9];
    const float* l1w    = (const float*)d_in[10];
    const float* l1b    = (const float*)d_in[11];
    const float* l2w    = (const float*)d_in[12];
    const float* l2b    = (const float*)d_in[13];
    const float* ln1g   = (const float*)d_in[14];
    const float* ln1b   = (const float*)d_in[15];
    const float* ln2g   = (const float*)d_in[16];
    const float* ln2b   = (const float*)d_in[17];
    const float* embw   = (const float*)d_in[18];
    const float* embb   = (const float*)d_in[19];
    float* out = (float*)d_out;

    cudaFuncSetAttribute(tmma_kernel<false, false, false, true >,
                         cudaFuncAttributeMaxDynamicSharedMemorySize, (int)TMMA_SMEM);
    cudaFuncSetAttribute(tmma_kernel<false, false, true,  false>,
                         cudaFuncAttributeMaxDynamicSharedMemorySize, (int)TMMA_SMEM);
    cudaFuncSetAttribute(tmma_kernel<true,  false, true,  false>,
                         cudaFuncAttributeMaxDynamicSharedMemorySize, (int)TMMA_SMEM);
    cudaFuncSetAttribute(tmma_kernel<true,  false, false, false>,
                         cudaFuncAttributeMaxDynamicSharedMemorySize, (int)TMMA_SMEM);
    cudaFuncSetAttribute(tmma_kernel<true,  true,  true,  false>,
                         cudaFuncAttributeMaxDynamicSharedMemorySize, (int)TMMA_SMEM);
    cudaFuncSetAttribute(flash_kernel,
                         cudaFuncAttributeMaxDynamicSharedMemorySize, (int)FLASH_SMEM);

    float *srcR, *qkv, *att, *tmp, *ffh, *vt, *wt;
    float *wfqkv, *bfqkv, *ct, *wiR, *owR, *l1R, *l2R, *embR;
    cudaGetSymbolAddress((void**)&srcR, d_srcR);
    cudaGetSymbolAddress((void**)&qkv,  d_qkv);
    cudaGetSymbolAddress((void**)&att,  d_att);
    cudaGetSymbolAddress((void**)&tmp,  d_tmp);
    cudaGetSymbolAddress((void**)&ffh,  d_ffh);
    cudaGetSymbolAddress((void**)&vt,   d_vt);
    cudaGetSymbolAddress((void**)&wt,   d_wt);
    cudaGetSymbolAddress((void**)&wfqkv, d_wfqkv);
    cudaGetSymbolAddress((void**)&bfqkv, d_bfqkv);
    cudaGetSymbolAddress((void**)&ct,   d_ct);
    cudaGetSymbolAddress((void**)&wiR,  d_wiR);
    cudaGetSymbolAddress((void**)&owR,  d_owR);
    cudaGetSymbolAddress((void**)&l1R,  d_l1R);
    cudaGetSymbolAddress((void**)&l2R,  d_l2R);
    cudaGetSymbolAddress((void**)&embR, d_embR);

    const float scale = 0.08838834764831845f;  // 1/sqrt(128)

    // ---- input staging + ALL weight prep up front ----
    copy_x_kernel<<<(Bc * Tc * Fc + 255) / 256, 256>>>(x, srcR);
    fill_proto_kernel<<<(Bc * Cc * Fc + 255) / 256, 256>>>(proto, srcR);

    round_weights_kernel<<<4096, 256>>>(in_w, out_w, l1w, l2w, embw,
                                        wiR, wfqkv, owR, l1R, l2R, embR);
    transpose_qk_kernel<<<dim3(32, 32, 4), dim3(32, 8)>>>(wq, wk, wt, scale);
    launch_tmma(false, false, true, false, Fc, Fc, Fc,
                wiR, Fc, wt, Fc, wfqkv, Fc, nullptr, 1.f,
                4, 2,
                (ll)2 * FF, (ll)FF, (ll)2 * FF, (ll)FF, (ll)F3 * Fc, (ll)FF);
    fuse_bias_all_kernel<<<dim3(Fc, 6), 256>>>(in_w, in_b, bq, bk, bfqkv, scale);

    for (int l = 0; l < Lc; l++) {
        const float* wfl = wfqkv + (ll)l * F3 * Fc;
        const float* bfl = bfqkv + (ll)l * F3;

        // packed QKV: (BS, 3F), Q pre-scaled; rounded outputs
        launch_tmma(true, false, true, false, BSc, F3, Fc, srcR, Fc, wfl, Fc,
                    qkv, F3, bfl, 1.f);

        // V^T per batch: (Sc,F slice of qkv) -> (F, SP); pad cols stay zero
        transpose_kernel<<<dim3((Sc + 31) / 32, Fc / 32, Bc), dim3(32, 8)>>>(
            qkv + 2 * Fc, vt, Sc, F3, SP, (ll)Sc * F3, (ll)Fc * SP);

        // fused attention: att = softmax(Q K^T) V
        flash_kernel<<<dim3((Sc + 127) / 128, Bc * Hc), 256, FLASH_SMEM>>>(
            qkv, qkv + Fc, vt, att, F3);

        // out-proj (residual delta) + residual LN
        launch_tmma(true, false, false, false, BSc, Fc, Fc,
                    att, Fc, owR + (ll)l * FF, Fc, tmp, Fc, out_b + (ll)l * Fc, 1.f);
        ln_add_kernel<<<BSc, 256>>>(srcR, tmp, ln1g + (ll)l * Fc, ln1b + (ll)l * Fc);

        // FFN + residual LN
        launch_tmma(true, true, true, false, BSc, DFFc, Fc,
                    srcR, Fc, l1R + (ll)l * DFFc * Fc, Fc, ffh, DFFc,
                    l1b + (ll)l * DFFc, 1.f);
        launch_tmma(true, false, false, false, BSc, Fc, DFFc,
                    ffh, DFFc, l2R + (ll)l * Fc * DFFc, DFFc, tmp, Fc,
                    l2b + (ll)l * Fc, 1.f);
        ln_add_kernel<<<BSc, 256>>>(srcR, tmp, ln2g + (ll)l * Fc, ln2b + (ll)l * Fc);
    }

    // Conv1d(F->F, k=3, pad=1): 3 shifted, row-masked, accumulating GEMMs.
    // tap kk reads srcR row (t + kk - 1), zero outside [0, Tc) — this also
    // masks the prototype rows that live at t >= Tc in srcR.
    for (int kk = 0; kk < 3; kk++) {
        launch_tmma(kk == 0, false, false, kk > 0,
                    Tc, Fc, Fc,
                    srcR, Fc, embR + (ll)kk * FF, Fc, ct, Fc, embb, 1.f,
                    Bc, 1,
                    (ll)Sc * Fc, 0, 0, 0, (ll)Tc * Fc, 0,
                    kk - 1, Tc);
    }

    transpose_relu_kernel<<<dim3(Tc / 32, Fc / 32, Bc), dim3(32, 8)>>>(ct, out);
}

// round 13
// speedup vs baseline: 1.7540x; 1.0180x over previous
#include <cuda_runtime.h>
#include <math_constants.h>
#include <cstdint>

typedef long long ll;

// Problem constants
constexpr int Lc   = 2;
constexpr int Bc   = 4;
constexpr int Tc   = 2048;
constexpr int Fc   = 1024;
constexpr int Cc   = 200;
constexpr int Hc   = 8;
constexpr int DFFc = 128;
constexpr int Sc   = Tc + Cc;   // 2248
constexpr int BSc  = Bc * Sc;   // 8992
constexpr int DHc  = Fc / Hc;   // 128
constexpr int SP   = 2304;      // padded S (36*64) for KV iteration
constexpr int F3   = 3 * Fc;    // packed QKV width
constexpr int FF   = Fc * Fc;

// ---------------------------------------------------------------------------
// Scratch (device globals; no allocations allowed)
// ---------------------------------------------------------------------------
__device__ float d_srcR[(size_t)BSc * Fc];                 // tf32-rounded residual
__device__ float d_qkv [(size_t)BSc * F3];                 // packed Q|K|V
__device__ float d_att [(size_t)BSc * Fc];
__device__ float d_tmp [(size_t)BSc * Fc];
__device__ float d_ffh [(size_t)BSc * DFFc];
__device__ float d_vt  [(size_t)Bc * Fc * SP];             // V transposed, padded
__device__ float d_wt  [4 * FF];                           // transposed wq/wk (2 layers)
__device__ float d_wfqkv[(size_t)2 * F3 * Fc];             // fused+rounded QKV weights
__device__ float d_bfqkv[2 * F3];
__device__ float d_ct  [(size_t)Bc * Tc * Fc];
// tf32-rounded weight copies (both layers)
__device__ float d_wiR [2 * 2 * FF];                       // Wiq|Wik per layer
__device__ float d_owR [2 * FF];
__device__ float d_l1R [2 * DFFc * Fc];
__device__ float d_l2R [2 * Fc * DFFc];
__device__ float d_embR[3 * FF];                           // repacked [kk][o][i] K-major

// ---------------------------------------------------------------------------
// PTX helpers (sm_80-compatible only — harness compiles for plain sm_100)
// ---------------------------------------------------------------------------
__device__ __forceinline__ uint32_t smem_u32(const void* p) {
    uint32_t a;
    asm("{ .reg .u64 t; cvta.to.shared.u64 t, %1; cvt.u32.u64 %0, t; }" : "=r"(a) : "l"(p));
    return a;
}

__device__ __forceinline__ void cp_async16(uint32_t dst, const float* src, int pred_bytes) {
    asm volatile("cp.async.cg.shared.global [%0], [%1], 16, %2;"
                 :: "r"(dst), "l"(src), "r"(pred_bytes) : "memory");
}
#define CP_COMMIT() asm volatile("cp.async.commit_group;" ::: "memory")
#define CP_WAIT2()  asm volatile("cp.async.wait_group 2;" ::: "memory")
#define CP_WAIT1()  asm volatile("cp.async.wait_group 1;" ::: "memory")

__device__ __forceinline__ uint32_t cvt_tf32(float f) {
    uint32_t u;
    asm("cvt.rna.tf32.f32 %0, %1;" : "=r"(u) : "f"(f));
    return u;
}
__device__ __forceinline__ float round_tf32(float f) {
    return __uint_as_float(cvt_tf32(f));
}

__device__ __forceinline__ void mma_tf32(float* c, const uint32_t* a,
                                         uint32_t b0, uint32_t b1) {
    asm volatile(
        "mma.sync.aligned.m16n8k8.row.col.f32.tf32.tf32.f32 "
        "{%0,%1,%2,%3}, {%4,%5,%6,%7}, {%8,%9}, {%0,%1,%2,%3};"
        : "+f"(c[0]), "+f"(c[1]), "+f"(c[2]), "+f"(c[3])
        : "r"(a[0]), "r"(a[1]), "r"(a[2]), "r"(a[3]), "r"(b0), "r"(b1));
}

// ---------------------------------------------------------------------------
// Tensor-core tf32 GEMM:  C (=|+=) alpha*A*B^T (+bias) (+relu) (+round)
// Operands pre-rounded to tf32 (RNA).
// 4-contiguous k-permutation: within a 16-k chunk, thread-quad q owns actual
// k = {4q..4q+3}; mma step s uses (4q+2s, 4q+2s+1). A/B fragment loads are
// single ld.shared.v4 covering BOTH steps. KPAD=16 (no padding):
// LDS.128 8-lane phases hit banks {0-15},{16-31} -> conflict-free; cp.async
// store phase covers words 0..31 exactly.
// 4-stage pipeline, K-chunk 16, ONE __syncthreads per chunk, 64KB smem ->
// 2 CTAs/SM. K % 16 == 0, K >= 48.
// A rows read at (gm + rowOff), zero-predicated outside [0, rowLimA).
// ACCUM: C += result.
// ---------------------------------------------------------------------------
constexpr int KPAD = 16;
constexpr int STAGE_FLOATS = 2 * 128 * KPAD;                   // 4096
constexpr size_t TMMA_SMEM = (size_t)4 * STAGE_FLOATS * 4;     // 65536 B

template<bool HASBIAS, bool DORELU, bool ROUND, bool ACCUM>
__global__ void __launch_bounds__(256, 2)
tmma_kernel(int M, int N, int K,
            const float* __restrict__ A, int lda,
            const float* __restrict__ B, int ldb,
            float* __restrict__ C, int ldc,
            const float* __restrict__ bias, float alpha,
            int batchH,
            ll sAb, ll sAh, ll sBb, ll sBh, ll sCb, ll sCh,
            int rowOff, int rowLimA)
{
    extern __shared__ float sm[];

    const int t = threadIdx.x;
    const int wid = t >> 5, lane = t & 31;
    const int warp_m = wid & 3, warp_n = wid >> 2;

    {
        int z = blockIdx.z;
        int zb = z / batchH, zh = z - zb * batchH;
        A += zb * sAb + zh * sAh;
        B += zb * sBb + zh * sBh;
        C += zb * sCb + zh * sCh;
    }
    const int m0 = blockIdx.y * 128, n0 = blockIdx.x * 128;

    const uint32_t smb = smem_u32(sm);
    const int KT = K >> 4;

    auto load_stage = [&](int stage, int kc) {
        const int k0 = kc << 4;
        uint32_t aB = smb + (uint32_t)(stage * STAGE_FLOATS) * 4;
        uint32_t bB = aB + 128 * KPAD * 4;
        #pragma unroll
        for (int i = 0; i < 2; i++) {
            int idx = t + i * 256;          // 0..511
            int row = idx >> 2, sub = idx & 3;
            int gn = n0 + row;
            int ar = m0 + row + rowOff;
            cp_async16(aB + (uint32_t)(row * KPAD + sub * 4) * 4,
                       A + (ll)ar * lda + k0 + sub * 4,
                       ((unsigned)ar < (unsigned)rowLimA) ? 16 : 0);
            cp_async16(bB + (uint32_t)(row * KPAD + sub * 4) * 4,
                       B + (ll)gn * ldb + k0 + sub * 4, (gn < N) ? 16 : 0);
        }
    };

    float c[2][8][4] = {};
    const int aRowBase = warp_m * 32 + (lane >> 2);
    const int bRowBase = warp_n * 64 + (lane >> 2);
    const int k4 = (lane & 3) << 2;       // quad's 4 contiguous actual-k base

    load_stage(0, 0); CP_COMMIT();
    load_stage(1, 1); CP_COMMIT();
    load_stage(2, 2); CP_COMMIT();

    for (int kt = 0; kt < KT; kt++) {
        CP_WAIT2();
        __syncthreads();
        if (kt + 3 < KT) load_stage((kt + 3) & 3, kt + 3);
        CP_COMMIT();

        const float* As = sm + (kt & 3) * STAGE_FLOATS;
        const float* Bs = As + 128 * KPAD;

        // A fragments: one v4 per (row, row+8) per mt — covers both mma steps
        uint4 fa[2][2];
        #pragma unroll
        for (int mt = 0; mt < 2; mt++) {
            int r = aRowBase + mt * 16;
            fa[mt][0] = *(const uint4*)&As[r * KPAD + k4];
            fa[mt][1] = *(const uint4*)&As[(r + 8) * KPAD + k4];
        }
        uint32_t a0[2][4], a1[2][4];      // step0 / step1 fragments
        #pragma unroll
        for (int mt = 0; mt < 2; mt++) {
            a0[mt][0] = fa[mt][0].x; a0[mt][1] = fa[mt][1].x;
            a0[mt][2] = fa[mt][0].y; a0[mt][3] = fa[mt][1].y;
            a1[mt][0] = fa[mt][0].z; a1[mt][1] = fa[mt][1].z;
            a1[mt][2] = fa[mt][0].w; a1[mt][3] = fa[mt][1].w;
        }

        #pragma unroll
        for (int nt = 0; nt < 8; nt++) {
            uint4 fb = *(const uint4*)&Bs[(bRowBase + nt * 8) * KPAD + k4];
            mma_tf32(c[0][nt], a0[0], fb.x, fb.y);
            mma_tf32(c[1][nt], a0[1], fb.x, fb.y);
            mma_tf32(c[0][nt], a1[0], fb.z, fb.w);
            mma_tf32(c[1][nt], a1[1], fb.z, fb.w);
        }
    }

    #pragma unroll
    for (int mt = 0; mt < 2; mt++) {
        const int r0 = m0 + warp_m * 32 + mt * 16 + (lane >> 2);
        const int r1 = r0 + 8;
        #pragma unroll
        for (int nt = 0; nt < 8; nt++) {
            const int cb = n0 + warp_n * 64 + nt * 8;
            if (cb < N) {
                const int col = cb + 2 * (lane & 3);
                float2 v0 = make_float2(c[mt][nt][0] * alpha, c[mt][nt][1] * alpha);
                float2 v1 = make_float2(c[mt][nt][2] * alpha, c[mt][nt][3] * alpha);
                if (HASBIAS) {
                    float bx = bias[col], by = bias[col + 1];
                    v0.x += bx; v0.y += by; v1.x += bx; v1.y += by;
                }
                if (DORELU) {
                    v0.x = fmaxf(v0.x, 0.f); v0.y = fmaxf(v0.y, 0.f);
                    v1.x = fmaxf(v1.x, 0.f); v1.y = fmaxf(v1.y, 0.f);
                }
                if (ROUND) {
                    v0.x = round_tf32(v0.x); v0.y = round_tf32(v0.y);
                    v1.x = round_tf32(v1.x); v1.y = round_tf32(v1.y);
                }
                if (r0 < M) {
                    float* p = C + (ll)r0 * ldc + col;
                    if (ACCUM) { float2 o = *(float2*)p; v0.x += o.x; v0.y += o.y; }
                    *(float2*)p = v0;
                }
                if (r1 < M) {
                    float* p = C + (ll)r1 * ldc + col;
                    if (ACCUM) { float2 o = *(float2*)p; v1.x += o.x; v1.y += o.y; }
                    *(float2*)p = v1;
                }
            }
        }
    }
}

// ---------------------------------------------------------------------------
// Flash attention (as R12): att = softmax(Q K^T) V, per (b,h).
// ---------------------------------------------------------------------------
constexpr int FBN   = 64;
constexpr int NITER = SP / FBN;        // 36
constexpr int QLD = 132, KLD = 132, VLD = 72;
constexpr int KVSTG = 64 * KLD + 128 * VLD;
constexpr size_t FLASH_SMEM = (size_t)(128 * QLD + 2 * KVSTG) * 4;  // 208896 B

__global__ void __launch_bounds__(256, 1)
flash_kernel(const float* __restrict__ q, const float* __restrict__ k,
             const float* __restrict__ vt, float* __restrict__ att, int qld)
{
    extern __shared__ float sm[];
    const int t = threadIdx.x, wid = t >> 5, lane = t & 31;
    const int b = blockIdx.y >> 3, h = blockIdx.y & 7;
    const int q0 = blockIdx.x * 128;

    const float* qg = q  + ((ll)b * Sc) * qld + (ll)h * DHc;
    const float* kg = k  + ((ll)b * Sc) * qld + (ll)h * DHc;
    const float* vg = vt + (ll)b * Fc * SP + (ll)h * DHc * SP;

    const uint32_t smb = smem_u32(sm);

    #pragma unroll
    for (int i = 0; i < 16; i++) {
        int idx = t + i * 256;
        int row = idx >> 5, c4 = idx & 31;
        int gr = q0 + row;
        cp_async16(smb + (uint32_t)(row * QLD + c4 * 4) * 4,
                   qg + (ll)gr * qld + c4 * 4, gr < Sc ? 16 : 0);
    }
    CP_COMMIT();

    auto load_kv = [&](int stage, int it) {
        uint32_t ks = smb + (uint32_t)(128 * QLD + stage * KVSTG) * 4;
        uint32_t vs = ks + (uint32_t)(64 * KLD) * 4;
        int kv0 = it * FBN;
        #pragma unroll
        for (int i = 0; i < 8; i++) {
            int idx = t + i * 256;
            int row = idx >> 5, c4 = idx & 31;
            int gr = kv0 + row;
            cp_async16(ks + (uint32_t)(row * KLD + c4 * 4) * 4,
                       kg + (ll)gr * qld + c4 * 4, gr < Sc ? 16 : 0);
        }
        #pragma unroll
        for (int i = 0; i < 8; i++) {
            int idx = t + i * 256;
            int row = idx >> 4, c4 = idx & 15;
            cp_async16(vs + (uint32_t)(row * VLD + c4 * 4) * 4,
                       vg + (ll)row * SP + kv0 + c4 * 4, 16);
        }
        CP_COMMIT();
    };

    load_kv(0, 0);
    load_kv(1, 1);

    const int aRow = wid * 16 + (lane >> 2);
    const int cb = 2 * (lane & 3);

    float o[16][4];
    #pragma unroll
    for (int i = 0; i < 16; i++) { o[i][0] = o[i][1] = o[i][2] = o[i][3] = 0.f; }
    float m_a = -CUDART_INF_F, m_b = -CUDART_INF_F;
    float l_a = 0.f, l_b = 0.f;

    for (int it = 0; it < NITER; it++) {
        CP_WAIT1();
        __syncthreads();
        const float* Ks  = sm + 128 * QLD + (it & 1) * KVSTG;
        const float* Vts = Ks + 64 * KLD;

        float s[8][4];
        #pragma unroll
        for (int i = 0; i < 8; i++) { s[i][0] = s[i][1] = s[i][2] = s[i][3] = 0.f; }
        #pragma unroll
        for (int kk = 0; kk < 16; kk++) {
            const int kb = kk * 8 + cb;
            uint2 lo = *(const uint2*)&sm[aRow * QLD + kb];
            uint2 hi = *(const uint2*)&sm[(aRow + 8) * QLD + kb];
            uint32_t a[4] = {lo.x, hi.x, lo.y, hi.y};
            #pragma unroll
            for (int nt = 0; nt < 8; nt++) {
                uint2 bf = *(const uint2*)&Ks[(nt * 8 + (lane >> 2)) * KLD + kb];
                mma_tf32(s[nt], a, bf.x, bf.y);
            }
        }

        const int kv0 = it * FBN;
        if (kv0 + FBN > Sc) {
            #pragma unroll
            for (int nt = 0; nt < 8; nt++) {
                int c0 = kv0 + nt * 8 + cb;
                if (c0 >= Sc)     { s[nt][0] = -CUDART_INF_F; s[nt][2] = -CUDART_INF_F; }
                if (c0 + 1 >= Sc) { s[nt][1] = -CUDART_INF_F; s[nt][3] = -CUDART_INF_F; }
            }
        }

        float mx_a = -CUDART_INF_F, mx_b = -CUDART_INF_F;
        #pragma unroll
        for (int nt = 0; nt < 8; nt++) {
            mx_a = fmaxf(mx_a, fmaxf(s[nt][0], s[nt][1]));
            mx_b = fmaxf(mx_b, fmaxf(s[nt][2], s[nt][3]));
        }
        mx_a = fmaxf(mx_a, __shfl_xor_sync(0xffffffffu, mx_a, 1));
        mx_a = fmaxf(mx_a, __shfl_xor_sync(0xffffffffu, mx_a, 2));
        mx_b = fmaxf(mx_b, __shfl_xor_sync(0xffffffffu, mx_b, 1));
        mx_b = fmaxf(mx_b, __shfl_xor_sync(0xffffffffu, mx_b, 2));
        float mn_a = fmaxf(m_a, mx_a), mn_b = fmaxf(m_b, mx_b);
        float ca = __expf(m_a - mn_a), cbv = __expf(m_b - mn_b);
        m_a = mn_a; m_b = mn_b;

        float ra = 0.f, rb = 0.f;
        #pragma unroll
        for (int nt = 0; nt < 8; nt++) {
            s[nt][0] = round_tf32(__expf(s[nt][0] - mn_a));
            s[nt][1] = round_tf32(__expf(s[nt][1] - mn_a));
            s[nt][2] = round_tf32(__expf(s[nt][2] - mn_b));
            s[nt][3] = round_tf32(__expf(s[nt][3] - mn_b));
            ra += s[nt][0] + s[nt][1];
            rb += s[nt][2] + s[nt][3];
        }
        ra += __shfl_xor_sync(0xffffffffu, ra, 1);
        ra += __shfl_xor_sync(0xffffffffu, ra, 2);
        rb += __shfl_xor_sync(0xffffffffu, rb, 1);
        rb += __shfl_xor_sync(0xffffffffu, rb, 2);
        l_a = l_a * ca + ra;
        l_b = l_b * cbv + rb;

        #pragma unroll
        for (int dt = 0; dt < 16; dt++) {
            o[dt][0] *= ca;  o[dt][1] *= ca;
            o[dt][2] *= cbv; o[dt][3] *= cbv;
        }

        #pragma unroll
        for (int nt = 0; nt < 8; nt++) {
            uint32_t a[4] = { __float_as_uint(s[nt][0]), __float_as_uint(s[nt][2]),
                              __float_as_uint(s[nt][1]), __float_as_uint(s[nt][3]) };
            #pragma unroll
            for (int dt = 0; dt < 16; dt++) {
                uint2 bf = *(const uint2*)&Vts[(dt * 8 + (lane >> 2)) * VLD + nt * 8 + cb];
                mma_tf32(o[dt], a, bf.x, bf.y);
            }
        }

        __syncthreads();
        if (it + 2 < NITER) load_kv(it & 1, it + 2);
    }

    float inva = 1.f / l_a, invb = 1.f / l_b;
    int r0 = q0 + aRow, r1 = r0 + 8;
    float* og0 = att + ((ll)b * Sc + r0) * Fc + h * DHc;
    float* og1 = att + ((ll)b * Sc + r1) * Fc + h * DHc;
    #pragma unroll
    for (int dt = 0; dt < 16; dt++) {
        int col = dt * 8 + cb;
        if (r0 < Sc) {
            float2 v = make_float2(round_tf32(o[dt][0] * inva), round_tf32(o[dt][1] * inva));
            *(float2*)(og0 + col) = v;
        }
        if (r1 < Sc) {
            float2 v = make_float2(round_tf32(o[dt][2] * invb), round_tf32(o[dt][3] * invb));
            *(float2*)(og1 + col) = v;
        }
    }
}

// ---------------------------------------------------------------------------
// Block reductions
// ---------------------------------------------------------------------------
__device__ __forceinline__ float blkReduceSum(float v) {
    __shared__ float sh[32];
    int lane = threadIdx.x & 31, w = threadIdx.x >> 5;
    #pragma unroll
    for (int o = 16; o; o >>= 1) v += __shfl_xor_sync(0xffffffffu, v, o);
    if (lane == 0) sh[w] = v;
    __syncthreads();
    int nw = blockDim.x >> 5;
    float r = (lane < nw) ? sh[lane] : 0.f;
    #pragma unroll
    for (int o = 16; o; o >>= 1) r += __shfl_xor_sync(0xffffffffu, r, o);
    __syncthreads();
    return r;
}

// ---------------------------------------------------------------------------
// Weight prep: ONE grid-stride kernel rounds every weight matrix (both layers)
// emb segment repacks to [kk][o][i] K-major.
// ---------------------------------------------------------------------------
constexpr int SEG0 = 2 * FF;                 // L0 Wiq|Wik -> wiR[0]
constexpr int SEG1 = SEG0 + FF;              // L0 Wiv -> wfqkv[0] + 2FF
constexpr int SEG2 = SEG1 + 2 * FF;          // L1 Wiq|Wik -> wiR + 2FF
constexpr int SEG3 = SEG2 + FF;              // L1 Wiv -> wfqkv[1] + 2FF
constexpr int SEG4 = SEG3 + 2 * FF;          // out_w both -> owR
constexpr int SEG5 = SEG4 + 2 * DFFc * Fc;   // l1w both -> l1R
constexpr int SEG6 = SEG5 + 2 * Fc * DFFc;   // l2w both -> l2R
constexpr int SEG7 = SEG6 + 3 * FF;          // embw (repack) -> embR
__global__ void round_weights_kernel(const float* __restrict__ in_w,
                                     const float* __restrict__ out_w,
                                     const float* __restrict__ l1w,
                                     const float* __restrict__ l2w,
                                     const float* __restrict__ embw,
                                     float* __restrict__ wiR,
                                     float* __restrict__ wfqkv,
                                     float* __restrict__ owR,
                                     float* __restrict__ l1R,
                                     float* __restrict__ l2R,
                                     float* __restrict__ embR)
{
    for (int i = blockIdx.x * 256 + threadIdx.x; i < SEG7; i += gridDim.x * 256) {
        if (i < SEG0)      wiR[i]                      = round_tf32(in_w[i]);
        else if (i < SEG1) wfqkv[2 * FF + (i - SEG0)]  = round_tf32(in_w[i]);
        else if (i < SEG2) wiR[2 * FF + (i - SEG1)]    = round_tf32(in_w[3 * FF + (i - SEG1)]);
        else if (i < SEG3) wfqkv[(ll)F3 * Fc + 2 * FF + (i - SEG2)]
                                                       = round_tf32(in_w[5 * FF + (i - SEG2)]);
        else if (i < SEG4) owR[i - SEG3]               = round_tf32(out_w[i - SEG3]);
        else if (i < SEG5) l1R[i - SEG4]               = round_tf32(l1w[i - SEG4]);
        else if (i < SEG6) l2R[i - SEG5]               = round_tf32(l2w[i - SEG5]);
        else {
            int j = i - SEG6;
            int kk = j / FF, r = j - kk * FF;        // r = o*Fc + iin
            embR[j] = round_tf32(embw[(ll)r * 3 + kk]);
        }
    }
}

// transpose wq/wk for both layers in one launch; z = l*2 + (0=q,1=k).
__global__ void transpose_qk_kernel(const float* __restrict__ wq,
                                    const float* __restrict__ wk,
                                    float* __restrict__ wt, float scl)
{
    __shared__ float tile[32][33];
    int z = blockIdx.z, l = z >> 1, isK = z & 1;
    const float* in = (isK ? wk : wq) + (ll)l * FF;
    float* outp = wt + (ll)z * FF;
    float mul = isK ? 1.f : scl;
    int r0 = blockIdx.x * 32, c0 = blockIdx.y * 32;
    int tx = threadIdx.x, ty = threadIdx.y;
    #pragma unroll
    for (int i = 0; i < 4; i++)
        tile[ty + i * 8][tx] = in[(ll)(r0 + ty + i * 8) * Fc + c0 + tx];
    __syncthreads();
    int r = r0 + tx;
    #pragma unroll
    for (int i = 0; i < 4; i++) {
        int c = c0 + ty + i * 8;
        outp[(ll)c * Fc + r] = round_tf32(tile[tx][ty + i * 8] * mul);
    }
}

// fused biases, one launch: grid (Fc, 6).
__global__ void fuse_bias_all_kernel(const float* __restrict__ in_w,
                                     const float* __restrict__ in_b,
                                     const float* __restrict__ bq,
                                     const float* __restrict__ bk,
                                     float* __restrict__ bfqkv, float scale)
{
    int n = blockIdx.x, y = blockIdx.y;
    if (y >= 4) {
        int l = y - 4;
        if (threadIdx.x == 0)
            bfqkv[l * F3 + 2 * Fc + n] = in_b[(ll)l * F3 + 2 * Fc + n];
        return;
    }
    int l = y >> 1, isK = y & 1;
    const float* Wi = in_w + (ll)l * 3 * FF + (ll)isK * FF;
    const float* bs = (isK ? bk : bq) + (ll)l * Fc;
    float s = 0.f;
    for (int t = threadIdx.x; t < Fc; t += 256) s += Wi[(size_t)n * Fc + t] * bs[t];
    s = blkReduceSum(s);
    if (threadIdx.x == 0) {
        float badd = in_b[(ll)l * F3 + isK * Fc + n];
        bfqkv[l * F3 + isK * Fc + n] = (s + badd) * (isK ? 1.f : scale);
    }
}

// ---------------------------------------------------------------------------
// Small kernels
// ---------------------------------------------------------------------------
__global__ void copy_x_kernel(const float* __restrict__ x, float* __restrict__ srcR) {
    int idx = blockIdx.x * 256 + threadIdx.x;
    if (idx >= Bc * Tc * Fc) return;
    int b = idx / (Tc * Fc);
    int r = idx - b * (Tc * Fc);
    srcR[(size_t)b * Sc * Fc + r] = round_tf32(x[idx]);
}

__global__ void fill_proto_kernel(const float* __restrict__ proto, float* __restrict__ srcR) {
    int idx = blockIdx.x * 256 + threadIdx.x;
    if (idx >= Bc * Cc * Fc) return;
    int b   = idx / (Cc * Fc);
    int rem = idx - b * (Cc * Fc);
    int c   = rem / Fc;
    int f   = rem - c * Fc;
    srcR[(size_t)b * Sc * Fc + (size_t)(Tc + c) * Fc + f] = round_tf32(proto[(size_t)f * Cc + c]);
}

// srcR = round_tf32(LN(srcR + delta)); float4 path, one row per block
__global__ void ln_add_kernel(float* __restrict__ srcR, const float* __restrict__ delta,
                              const float* __restrict__ g, const float* __restrict__ b) {
    size_t row = blockIdx.x;
    float4* sp = (float4*)(srcR + row * Fc);
    const float4* dp = (const float4*)(delta + row * Fc);
    int i = threadIdx.x;      // 256 threads x float4 = 1024
    float4 xs = sp[i], ds = dp[i];
    xs.x += ds.x; xs.y += ds.y; xs.z += ds.z; xs.w += ds.w;
    float s = xs.x + xs.y + xs.z + xs.w;
    float mean = blkReduceSum(s) * (1.f / Fc);
    float dx = xs.x - mean, dy = xs.y - mean, dz = xs.z - mean, dw = xs.w - mean;
    float s2 = dx * dx + dy * dy + dz * dz + dw * dw;
    float var = blkReduceSum(s2) * (1.f / Fc);
    float rstd = rsqrtf(var + 1e-5f);
    const float4 gv = ((const float4*)g)[i];
    const float4 bv = ((const float4*)b)[i];
    float4 o;
    o.x = round_tf32(dx * rstd * gv.x + bv.x);
    o.y = round_tf32(dy * rstd * gv.y + bv.y);
    o.z = round_tf32(dz * rstd * gv.z + bv.z);
    o.w = round_tf32(dw * rstd * gv.w + bv.w);
    sp[i] = o;
}

// generic transpose with tf32 rounding of outputs (vt build)
__global__ void transpose_kernel(const float* __restrict__ in, float* __restrict__ outp,
                                 int R, int ldin, int ldout, ll sIn, ll sOut) {
    __shared__ float tile[32][33];
    int b = blockIdx.z;
    in += b * sIn; outp += b * sOut;
    int r0 = blockIdx.x * 32, c0 = blockIdx.y * 32;
    int tx = threadIdx.x, ty = threadIdx.y;
    #pragma unroll
    for (int i = 0; i < 4; i++) {
        int r = r0 + ty + i * 8;
        if (r < R) tile[ty + i * 8][tx] = in[(ll)r * ldin + c0 + tx];
    }
    __syncthreads();
    int r = r0 + tx;
    if (r < R) {
        #pragma unroll
        for (int i = 0; i < 4; i++) {
            int c = c0 + ty + i * 8;
            outp[(ll)c * ldout + r] = round_tf32(tile[tx][ty + i * 8]);
        }
    }
}

__global__ void transpose_relu_kernel(const float* __restrict__ in, float* __restrict__ outp) {
    __shared__ float tile[32][33];
    int b = blockIdx.z;
    int t0 = blockIdx.x * 32, f0 = blockIdx.y * 32;
    int tx = threadIdx.x, ty = threadIdx.y;
    #pragma unroll
    for (int i = 0; i < 4; i++) {
        int tt = t0 + ty + i * 8;
        tile[ty + i * 8][tx] = in[(size_t)b * Tc * Fc + (size_t)tt * Fc + f0 + tx];
    }
    __syncthreads();
    #pragma unroll
    for (int i = 0; i < 4; i++) {
        int f = f0 + ty + i * 8;
        float v = tile[tx][ty + i * 8];
        outp[(size_t)b * Fc * Tc + (size_t)f * Tc + t0 + tx] = fmaxf(v, 0.f);
    }
}

// ---------------------------------------------------------------------------
// Host dispatch
// ---------------------------------------------------------------------------
static void launch_tmma(bool hasbias, bool dorelu, bool doround, bool accum,
                        int M, int N, int K,
                        const float* A, int lda, const float* B, int ldb,
                        float* C, int ldc, const float* bias, float alpha,
                        int nz = 1, int batchH = 1,
                        ll sAb = 0, ll sAh = 0, ll sBb = 0, ll sBh = 0,
                        ll sCb = 0, ll sCh = 0,
                        int rowOff = 0, int rowLim = 0)
{
    if (rowLim == 0) rowLim = M;
    dim3 grid((N + 127) / 128, (M + 127) / 128, nz);
    #define TM_ARGS M, N, K, A, lda, B, ldb, C, ldc, bias, alpha, batchH, \
                    sAb, sAh, sBb, sBh, sCb, sCh, rowOff, rowLim
    if (accum)
        tmma_kernel<false, false, false, true ><<<grid, 256, TMMA_SMEM>>>(TM_ARGS);
    else if (!hasbias && !dorelu && doround)
        tmma_kernel<false, false, true,  false><<<grid, 256, TMMA_SMEM>>>(TM_ARGS);
    else if (hasbias && !dorelu && doround)
        tmma_kernel<true,  false, true,  false><<<grid, 256, TMMA_SMEM>>>(TM_ARGS);
    else if (hasbias && !dorelu && !doround)
        tmma_kernel<true,  false, false, false><<<grid, 256, TMMA_SMEM>>>(TM_ARGS);
    else
        tmma_kernel<true,  true,  true,  false><<<grid, 256, TMMA_SMEM>>>(TM_ARGS);
    #undef TM_ARGS
}

extern "C" void kernel_launch(void* const* d_in, const int* in_sizes, int n_in,
                              void* d_out, int out_size)
{
    const float* x      = (const float*)d_in[0];
    const float* proto  = (const float*)d_in[1];
    const float* wq     = (const float*)d_in[2];
    const float* bq     = (const float*)d_in[3];
    const float* wk     = (const float*)d_in[4];
    const float* bk     = (const float*)d_in[5];
    const float* in_w   = (const float*)d_in[6];
    const float* in_b   = (const float*)d_in[7];
    const float* out_w  = (const float*)d_in[8];
    const float* out_b  = (const float*)d_in[9];
    const float* l1w    = (const float*)d_in[10];
    const float* l1b    = (const float*)d_in[11];
    const float* l2w    = (const float*)d_in[12];
    const float* l2b    = (const float*)d_in[13];
    const float* ln1g   = (const float*)d_in[14];
    const float* ln1b   = (const float*)d_in[15];
    const float* ln2g   = (const float*)d_in[16];
    const float* ln2b   = (const float*)d_in[17];
    const float* embw   = (const float*)d_in[18];
    const float* embb   = (const float*)d_in[19];
    float* out = (float*)d_out;

    cudaFuncSetAttribute(tmma_kernel<false, false, false, true >,
                         cudaFuncAttributeMaxDynamicSharedMemorySize, (int)TMMA_SMEM);
    cudaFuncSetAttribute(tmma_kernel<false, false, true,  false>,
                         cudaFuncAttributeMaxDynamicSharedMemorySize, (int)TMMA_SMEM);
    cudaFuncSetAttribute(tmma_kernel<true,  false, true,  false>,
                         cudaFuncAttributeMaxDynamicSharedMemorySize, (int)TMMA_SMEM);
    cudaFuncSetAttribute(tmma_kernel<true,  false, false, false>,
                         cudaFuncAttributeMaxDynamicSharedMemorySize, (int)TMMA_SMEM);
    cudaFuncSetAttribute(tmma_kernel<true,  true,  true,  false>,
                         cudaFuncAttributeMaxDynamicSharedMemorySize, (int)TMMA_SMEM);
    cudaFuncSetAttribute(flash_kernel,
                         cudaFuncAttributeMaxDynamicSharedMemorySize, (int)FLASH_SMEM);

    float *srcR, *qkv, *att, *tmp, *ffh, *vt, *wt;
    float *wfqkv, *bfqkv, *ct, *wiR, *owR, *l1R, *l2R, *embR;
    cudaGetSymbolAddress((void**)&srcR, d_srcR);
    cudaGetSymbolAddress((void**)&qkv,  d_qkv);
    cudaGetSymbolAddress((void**)&att,  d_att);
    cudaGetSymbolAddress((void**)&tmp,  d_tmp);
    cudaGetSymbolAddress((void**)&ffh,  d_ffh);
    cudaGetSymbolAddress((void**)&vt,   d_vt);
    cudaGetSymbolAddress((void**)&wt,   d_wt);
    cudaGetSymbolAddress((void**)&wfqkv, d_wfqkv);
    cudaGetSymbolAddress((void**)&bfqkv, d_bfqkv);
    cudaGetSymbolAddress((void**)&ct,   d_ct);
    cudaGetSymbolAddress((void**)&wiR,  d_wiR);
    cudaGetSymbolAddress((void**)&owR,  d_owR);
    cudaGetSymbolAddress((void**)&l1R,  d_l1R);
    cudaGetSymbolAddress((void**)&l2R,  d_l2R);
    cudaGetSymbolAddress((void**)&embR, d_embR);

    const float scale = 0.08838834764831845f;  // 1/sqrt(128)

    // ---- input staging + ALL weight prep up front ----
    copy_x_kernel<<<(Bc * Tc * Fc + 255) / 256, 256>>>(x, srcR);
    fill_proto_kernel<<<(Bc * Cc * Fc + 255) / 256, 256>>>(proto, srcR);

    round_weights_kernel<<<4096, 256>>>(in_w, out_w, l1w, l2w, embw,
                                        wiR, wfqkv, owR, l1R, l2R, embR);
    transpose_qk_kernel<<<dim3(32, 32, 4), dim3(32, 8)>>>(wq, wk, wt, scale);
    launch_tmma(false, false, true, false, Fc, Fc, Fc,
                wiR, Fc, wt, Fc, wfqkv, Fc, nullptr, 1.f,
                4, 2,
                (ll)2 * FF, (ll)FF, (ll)2 * FF, (ll)FF, (ll)F3 * Fc, (ll)FF);
    fuse_bias_all_kernel<<<dim3(Fc, 6), 256>>>(in_w, in_b, bq, bk, bfqkv, scale);

    for (int l = 0; l < Lc; l++) {
        const float* wfl = wfqkv + (ll)l * F3 * Fc;
        const float* bfl = bfqkv + (ll)l * F3;

        // packed QKV: (BS, 3F), Q pre-scaled; rounded outputs
        launch_tmma(true, false, true, false, BSc, F3, Fc, srcR, Fc, wfl, Fc,
                    qkv, F3, bfl, 1.f);

        // V^T per batch: (Sc,F slice of qkv) -> (F, SP); pad cols stay zero
        transpose_kernel<<<dim3((Sc + 31) / 32, Fc / 32, Bc), dim3(32, 8)>>>(
            qkv + 2 * Fc, vt, Sc, F3, SP, (ll)Sc * F3, (ll)Fc * SP);

        // fused attention: att = softmax(Q K^T) V
        flash_kernel<<<dim3((Sc + 127) / 128, Bc * Hc), 256, FLASH_SMEM>>>(
            qkv, qkv + Fc, vt, att, F3);

        // out-proj (residual delta) + residual LN
        launch_tmma(true, false, false, false, BSc, Fc, Fc,
                    att, Fc, owR + (ll)l * FF, Fc, tmp, Fc, out_b + (ll)l * Fc, 1.f);
        ln_add_kernel<<<BSc, 256>>>(srcR, tmp, ln1g + (ll)l * Fc, ln1b + (ll)l * Fc);

        // FFN + residual LN
        launch_tmma(true, true, true, false, BSc, DFFc, Fc,
                    srcR, Fc, l1R + (ll)l * DFFc * Fc, Fc, ffh, DFFc,
                    l1b + (ll)l * DFFc, 1.f);
        launch_tmma(true, false, false, false, BSc, Fc, DFFc,
                    ffh, DFFc, l2R + (ll)l * Fc * DFFc, DFFc, tmp, Fc,
                    l2b + (ll)l * Fc, 1.f);
        ln_add_kernel<<<BSc, 256>>>(srcR, tmp, ln2g + (ll)l * Fc, ln2b + (ll)l * Fc);
    }

    // Conv1d(F->F, k=3, pad=1): 3 shifted, row-masked, accumulating GEMMs.
    for (int kk = 0; kk < 3; kk++) {
        launch_tmma(kk == 0, false, false, kk > 0,
                    Tc, Fc, Fc,
                    srcR, Fc, embR + (ll)kk * FF, Fc, ct, Fc, embb, 1.f,
                    Bc, 1,
                    (ll)Sc * Fc, 0, 0, 0, (ll)Tc * Fc, 0,
                    kk - 1, Tc);
    }

    transpose_relu_kernel<<<dim3(Tc / 32, Fc / 32, Bc), dim3(32, 8)>>>(ct, out);
}